// round 2
// baseline (speedup 1.0000x reference)
#include <cuda_runtime.h>
#include <math.h>

// Problem constants
#define SEQ      2048
#define DMODEL   4096
#define DGROUP   512
#define DH       64
#define NHEADS   64
#define GROUPS   8

// Scratch (allocation-free rule: __device__ globals)
__device__ float g_Q[SEQ * DMODEL];   // 32 MB
__device__ float g_K[SEQ * DGROUP];   //  4 MB
__device__ float g_V[SEQ * DGROUP];   //  4 MB
__device__ float g_O[SEQ * DMODEL];   // 32 MB (attention output, pre-Wo)

// ============================================================================
// SGEMM: C[M,N] = A[M,K] @ B[K,N] + bias[N]
// 128x128 block tile, BK=8, 256 threads, 8x8 register tile per thread.
// M, N multiples of 128; K multiple of 8 (true for all four calls here).
// ============================================================================
__global__ __launch_bounds__(256, 2)
void sgemm_bias(const float* __restrict__ A, const float* __restrict__ B,
                const float* __restrict__ bias, float* __restrict__ C,
                int M, int N, int K)
{
    __shared__ float As[8][128];   // transposed A tile: As[k][m]
    __shared__ float Bs[8][128];   // Bs[k][n]

    const int tid = threadIdx.x;
    const int tx  = tid & 15;      // 0..15 -> N direction
    const int ty  = tid >> 4;      // 0..15 -> M direction
    const int rowBase = blockIdx.y * 128;
    const int colBase = blockIdx.x * 128;

    // A tile load mapping: 128 rows x 8 cols = 256 float4
    const int arow = tid >> 1;
    const int acol = (tid & 1) * 4;
    // B tile load mapping: 8 rows x 128 cols = 256 float4
    const int brow = tid >> 5;
    const int bcol = (tid & 31) * 4;

    const float* Aptr = A + (size_t)(rowBase + arow) * K + acol;
    const float* Bptr = B + (size_t)brow * N + colBase + bcol;

    float acc[8][8];
    #pragma unroll
    for (int i = 0; i < 8; i++)
        #pragma unroll
        for (int j = 0; j < 8; j++)
            acc[i][j] = 0.0f;

    for (int kt = 0; kt < K; kt += 8) {
        float4 a4 = *(const float4*)(Aptr + kt);
        As[acol + 0][arow] = a4.x;
        As[acol + 1][arow] = a4.y;
        As[acol + 2][arow] = a4.z;
        As[acol + 3][arow] = a4.w;

        float4 b4 = *(const float4*)(Bptr + (size_t)kt * N);
        *(float4*)&Bs[brow][bcol] = b4;

        __syncthreads();

        #pragma unroll
        for (int kk = 0; kk < 8; kk++) {
            float ra[8], rb[8];
            #pragma unroll
            for (int i = 0; i < 8; i++) ra[i] = As[kk][ty * 8 + i];
            *(float4*)&rb[0] = *(const float4*)&Bs[kk][tx * 8];
            *(float4*)&rb[4] = *(const float4*)&Bs[kk][tx * 8 + 4];
            #pragma unroll
            for (int i = 0; i < 8; i++)
                #pragma unroll
                for (int j = 0; j < 8; j++)
                    acc[i][j] = fmaf(ra[i], rb[j], acc[i][j]);
        }
        __syncthreads();
    }

    // Epilogue: add bias, store
    float bj[8];
    #pragma unroll
    for (int j = 0; j < 8; j++) bj[j] = bias[colBase + tx * 8 + j];

    #pragma unroll
    for (int i = 0; i < 8; i++) {
        int row = rowBase + ty * 8 + i;
        float* Crow = C + (size_t)row * N + colBase + tx * 8;
        float4 o0, o1;
        o0.x = acc[i][0] + bj[0];  o0.y = acc[i][1] + bj[1];
        o0.z = acc[i][2] + bj[2];  o0.w = acc[i][3] + bj[3];
        o1.x = acc[i][4] + bj[4];  o1.y = acc[i][5] + bj[5];
        o1.z = acc[i][6] + bj[6];  o1.w = acc[i][7] + bj[7];
        *(float4*)(Crow)     = o0;
        *(float4*)(Crow + 4) = o1;
    }
}

// ============================================================================
// Flash attention: one (128-query tile, head) per CTA.
// Q: [SEQ, DMODEL], head h uses columns h*64 .. h*64+63
// K,V: [SEQ, DGROUP], group g = h/8 uses columns g*64 .. g*64+63
// O: [SEQ, DMODEL] (same column layout as Q)
// Streams 64-key tiles with online softmax. 256 threads.
// ============================================================================
#define FL_BM 128
#define FL_BN 64
// SMEM layout (floats):
//   Qs  [128][65]   (pad 65: row-indexed scalar reads conflict-free)
//   Kts [64][68]    (K transposed: Kts[d][key]; pad 68 keeps float4 alignment)
//   Vs  [64][68]
//   Ss  [128][65]   (scores -> probabilities)
//   mrow[128], lrow[128], cs[128], red[256]
#define QS_STRIDE 65
#define KV_STRIDE 68
#define OFF_QS   0
#define OFF_KTS  (OFF_QS  + 128 * QS_STRIDE)
#define OFF_VS   (OFF_KTS + 64 * KV_STRIDE)
#define OFF_SS   (OFF_VS  + 64 * KV_STRIDE)
#define OFF_M    (OFF_SS  + 128 * QS_STRIDE)
#define OFF_L    (OFF_M + 128)
#define OFF_CS   (OFF_L + 128)
#define OFF_RED  (OFF_CS + 128)
#define FLASH_SMEM_FLOATS (OFF_RED + 256)
#define FLASH_SMEM_BYTES  (FLASH_SMEM_FLOATS * 4)

__global__ __launch_bounds__(256, 1)
void flash_kernel(const float* __restrict__ Q, const float* __restrict__ Kg,
                  const float* __restrict__ Vg, float* __restrict__ O)
{
    extern __shared__ float sm[];
    float* Qs   = sm + OFF_QS;
    float* Kts  = sm + OFF_KTS;
    float* Vs   = sm + OFF_VS;
    float* Ss   = sm + OFF_SS;
    float* mrow = sm + OFF_M;
    float* lrow = sm + OFF_L;
    float* cs   = sm + OFF_CS;
    float* red  = sm + OFF_RED;

    const int tid   = threadIdx.x;
    const int head  = blockIdx.y;          // 0..63
    const int g     = head >> 3;           // KV group
    const int qcol0 = head * DH;
    const int kcol0 = g * DH;
    const int qrow0 = blockIdx.x * FL_BM;

    const int tx = tid & 15;   // 0..15 -> 4 cols each (of 64)
    const int ty = tid >> 4;   // 0..15 -> 8 rows each (of 128)

    // ---- Load Q tile: 128x64 floats = 2048 float4, 8 per thread
    #pragma unroll
    for (int i = 0; i < 8; i++) {
        int e   = tid + i * 256;
        int row = e >> 4;
        int c4  = (e & 15) * 4;
        float4 q4 = *(const float4*)&Q[(size_t)(qrow0 + row) * DMODEL + qcol0 + c4];
        float* dst = &Qs[row * QS_STRIDE + c4];
        dst[0] = q4.x; dst[1] = q4.y; dst[2] = q4.z; dst[3] = q4.w;
    }
    if (tid < 128) { mrow[tid] = -INFINITY; lrow[tid] = 0.0f; }

    float acc[8][4];
    #pragma unroll
    for (int i = 0; i < 8; i++)
        #pragma unroll
        for (int j = 0; j < 4; j++)
            acc[i][j] = 0.0f;

    const int row_s = tid & 127;   // softmax row for this thread
    const int half  = tid >> 7;    // which 32-col half

    for (int kt = 0; kt < SEQ / FL_BN; kt++) {
        __syncthreads();   // prior iteration done reading Kts/Vs/Ss

        // ---- Load K (transposed) and V tiles: 64x64 each, 4 float4/thread
        const int krow0 = kt * FL_BN;
        #pragma unroll
        for (int i = 0; i < 4; i++) {
            int e   = tid + i * 256;
            int key = e >> 4;
            int c4  = (e & 15) * 4;
            float4 k4 = *(const float4*)&Kg[(size_t)(krow0 + key) * DGROUP + kcol0 + c4];
            Kts[(c4 + 0) * KV_STRIDE + key] = k4.x;
            Kts[(c4 + 1) * KV_STRIDE + key] = k4.y;
            Kts[(c4 + 2) * KV_STRIDE + key] = k4.z;
            Kts[(c4 + 3) * KV_STRIDE + key] = k4.w;
            float4 v4 = *(const float4*)&Vg[(size_t)(krow0 + key) * DGROUP + kcol0 + c4];
            *(float4*)&Vs[key * KV_STRIDE + c4] = v4;
        }
        __syncthreads();

        // ---- S = (Q @ K^T) * scale : each thread 8 rows x 4 cols
        float s[8][4];
        #pragma unroll
        for (int i = 0; i < 8; i++)
            #pragma unroll
            for (int j = 0; j < 4; j++)
                s[i][j] = 0.0f;

        #pragma unroll 8
        for (int d = 0; d < DH; d++) {
            float4 kb = *(const float4*)&Kts[d * KV_STRIDE + tx * 4];
            float qa[8];
            #pragma unroll
            for (int i = 0; i < 8; i++) qa[i] = Qs[(ty * 8 + i) * QS_STRIDE + d];
            #pragma unroll
            for (int i = 0; i < 8; i++) {
                s[i][0] = fmaf(qa[i], kb.x, s[i][0]);
                s[i][1] = fmaf(qa[i], kb.y, s[i][1]);
                s[i][2] = fmaf(qa[i], kb.z, s[i][2]);
                s[i][3] = fmaf(qa[i], kb.w, s[i][3]);
            }
        }
        const float scale = 0.125f;   // 1/sqrt(64)
        #pragma unroll
        for (int i = 0; i < 8; i++)
            #pragma unroll
            for (int j = 0; j < 4; j++)
                Ss[(ty * 8 + i) * QS_STRIDE + tx * 4 + j] = s[i][j] * scale;
        __syncthreads();

        // ---- Online softmax over this 64-key tile
        // (a) per-half row max
        {
            float lm = -INFINITY;
            const float* srow = &Ss[row_s * QS_STRIDE + half * 32];
            #pragma unroll 8
            for (int c = 0; c < 32; c++) lm = fmaxf(lm, srow[c]);
            red[tid] = lm;
        }
        __syncthreads();
        // (b) combine + rescale factor
        if (tid < 128) {
            float tm = fmaxf(red[tid], red[tid + 128]);
            float mo = mrow[tid];
            float mn = fmaxf(mo, tm);
            mrow[tid] = mn;
            cs[tid]   = __expf(mo - mn);
        }
        __syncthreads();
        // (c) exponentiate + per-half row sum
        {
            float mn = mrow[row_s];
            float ls = 0.0f;
            float* srow = &Ss[row_s * QS_STRIDE + half * 32];
            #pragma unroll 8
            for (int c = 0; c < 32; c++) {
                float p = __expf(srow[c] - mn);
                srow[c] = p;
                ls += p;
            }
            red[tid] = ls;
        }
        __syncthreads();
        // (d) update l
        if (tid < 128)
            lrow[tid] = lrow[tid] * cs[tid] + red[tid] + red[tid + 128];
        __syncthreads();   // cs + probabilities visible to everyone

        // ---- Rescale accumulators, then O += P @ V
        #pragma unroll
        for (int i = 0; i < 8; i++) {
            float c_ = cs[ty * 8 + i];
            #pragma unroll
            for (int j = 0; j < 4; j++) acc[i][j] *= c_;
        }

        #pragma unroll 8
        for (int k = 0; k < FL_BN; k++) {
            float4 vb = *(const float4*)&Vs[k * KV_STRIDE + tx * 4];
            float pa[8];
            #pragma unroll
            for (int i = 0; i < 8; i++) pa[i] = Ss[(ty * 8 + i) * QS_STRIDE + k];
            #pragma unroll
            for (int i = 0; i < 8; i++) {
                acc[i][0] = fmaf(pa[i], vb.x, acc[i][0]);
                acc[i][1] = fmaf(pa[i], vb.y, acc[i][1]);
                acc[i][2] = fmaf(pa[i], vb.z, acc[i][2]);
                acc[i][3] = fmaf(pa[i], vb.w, acc[i][3]);
            }
        }
    }

    // lrow finalized before the last __syncthreads inside the loop
    #pragma unroll
    for (int i = 0; i < 8; i++) {
        int r = ty * 8 + i;
        float inv = 1.0f / lrow[r];
        float4 o;
        o.x = acc[i][0] * inv;
        o.y = acc[i][1] * inv;
        o.z = acc[i][2] * inv;
        o.w = acc[i][3] * inv;
        *(float4*)&O[(size_t)(qrow0 + r) * DMODEL + qcol0 + tx * 4] = o;
    }
}

// ============================================================================
// kernel_launch
// Inputs (metadata order): x, wq, bq, wk, bk, wv, bv, wo, bo, test
// ============================================================================
extern "C" void kernel_launch(void* const* d_in, const int* in_sizes, int n_in,
                              void* d_out, int out_size)
{
    const float* x  = (const float*)d_in[0];
    const float* wq = (const float*)d_in[1];
    const float* bq = (const float*)d_in[2];
    const float* wk = (const float*)d_in[3];
    const float* bk = (const float*)d_in[4];
    const float* wv = (const float*)d_in[5];
    const float* bv = (const float*)d_in[6];
    const float* wo = (const float*)d_in[7];
    const float* bo = (const float*)d_in[8];
    float* out = (float*)d_out;

    float *Qb, *Kb, *Vb, *Ob;
    cudaGetSymbolAddress((void**)&Qb, g_Q);
    cudaGetSymbolAddress((void**)&Kb, g_K);
    cudaGetSymbolAddress((void**)&Vb, g_V);
    cudaGetSymbolAddress((void**)&Ob, g_O);

    cudaFuncSetAttribute(flash_kernel,
                         cudaFuncAttributeMaxDynamicSharedMemorySize,
                         FLASH_SMEM_BYTES);

    dim3 blk(256);

    // Q = x @ wq + bq        [2048,4096] @ [4096,4096]
    sgemm_bias<<<dim3(DMODEL / 128, SEQ / 128), blk>>>(x, wq, bq, Qb, SEQ, DMODEL, DMODEL);
    // K = x @ wk + bk        [2048,4096] @ [4096,512]
    sgemm_bias<<<dim3(DGROUP / 128, SEQ / 128), blk>>>(x, wk, bk, Kb, SEQ, DGROUP, DMODEL);
    // V = x @ wv + bv
    sgemm_bias<<<dim3(DGROUP / 128, SEQ / 128), blk>>>(x, wv, bv, Vb, SEQ, DGROUP, DMODEL);
    // Attention: grid (16 q-tiles, 64 heads)
    flash_kernel<<<dim3(SEQ / FL_BM, NHEADS), blk, FLASH_SMEM_BYTES>>>(Qb, Kb, Vb, Ob);
    // out = O @ wo + bo
    sgemm_bias<<<dim3(DMODEL / 128, SEQ / 128), blk>>>(Ob, wo, bo, out, SEQ, DMODEL, DMODEL);
}

// round 4
// speedup vs baseline: 1.7959x; 1.7959x over previous
#include <cuda_runtime.h>
#include <cuda_bf16.h>
#include <math.h>
#include <stdint.h>

// ============================ problem constants =============================
#define SEQ      2048
#define DMODEL   4096
#define DGROUP   512
#define DH       64
#define NHEADS   64
#define KDIM     4096

// ============================ scratch (device globals) ======================
__device__ float g_Q[SEQ * DMODEL];
__device__ float g_K[SEQ * DGROUP];
__device__ float g_V[SEQ * DGROUP];
__device__ float g_O[SEQ * DMODEL];

__device__ __nv_bfloat16 g_xhi[SEQ * DMODEL];
__device__ __nv_bfloat16 g_xlo[SEQ * DMODEL];
__device__ __nv_bfloat16 g_Ohi[SEQ * DMODEL];
__device__ __nv_bfloat16 g_Olo[SEQ * DMODEL];
__device__ __nv_bfloat16 g_wqT_hi[DMODEL * DMODEL];
__device__ __nv_bfloat16 g_wqT_lo[DMODEL * DMODEL];
__device__ __nv_bfloat16 g_wkT_hi[DGROUP * DMODEL];
__device__ __nv_bfloat16 g_wkT_lo[DGROUP * DMODEL];
__device__ __nv_bfloat16 g_wvT_hi[DGROUP * DMODEL];
__device__ __nv_bfloat16 g_wvT_lo[DGROUP * DMODEL];
__device__ __nv_bfloat16 g_woT_hi[DMODEL * DMODEL];
__device__ __nv_bfloat16 g_woT_lo[DMODEL * DMODEL];

// ============================ PTX helpers (sm_80-era only) ==================
__device__ __forceinline__ uint32_t smem_u32(const void* p) {
    uint32_t a;
    asm("{ .reg .u64 t; cvta.to.shared.u64 t, %1; cvt.u32.u64 %0, t; }" : "=r"(a) : "l"(p));
    return a;
}
#define CP_ASYNC16(dst, src) \
    asm volatile("cp.async.cg.shared.global [%0], [%1], 16;" :: "r"(dst), "l"(src) : "memory")
#define CP_COMMIT() asm volatile("cp.async.commit_group;" ::: "memory")
#define CP_WAIT0()  asm volatile("cp.async.wait_group 0;" ::: "memory")
#define CP_WAIT1()  asm volatile("cp.async.wait_group 1;" ::: "memory")

__device__ __forceinline__ void ldsm_x4(uint32_t* r, uint32_t addr) {
    asm volatile("ldmatrix.sync.aligned.m8n8.x4.shared.b16 {%0,%1,%2,%3}, [%4];"
                 : "=r"(r[0]), "=r"(r[1]), "=r"(r[2]), "=r"(r[3]) : "r"(addr));
}
__device__ __forceinline__ void mma16816(float* d, const uint32_t* a, const uint32_t* b) {
    asm volatile(
        "mma.sync.aligned.m16n8k16.row.col.f32.bf16.bf16.f32 "
        "{%0,%1,%2,%3}, {%4,%5,%6,%7}, {%8,%9}, {%0,%1,%2,%3};"
        : "+f"(d[0]), "+f"(d[1]), "+f"(d[2]), "+f"(d[3])
        : "r"(a[0]), "r"(a[1]), "r"(a[2]), "r"(a[3]), "r"(b[0]), "r"(b[1]));
}

// ============================ split-bf16 mma.sync GEMM ======================
// C[M, Nglob] = A[M,4096] @ B^T + bias ; B stored [Nglob, 4096] K-major.
// A, B pre-split into bf16 hi/lo. 3 products: hi*hi + hi*lo + lo*hi.
// CTA tile 128x128, BK=32, 8 warps (warp tile 32x64), cp.async double buffer.
#define BM 128
#define BN 128
#define BK 32
#define NIT (KDIM / BK)          // 128
#define RS 40                    // smem row stride in bf16 (80B = 5 x 16B -> LDSM conflict-free)
#define MAT_BYTES (128 * RS * 2) // 10240
#define STAGE_BYTES (4 * MAT_BYTES)      // Ahi, Alo, Bhi, Blo
#define GEMM_SMEM (2 * STAGE_BYTES)      // 81920
#define OFF_AHI 0
#define OFF_ALO (1 * MAT_BYTES)
#define OFF_BHI (2 * MAT_BYTES)
#define OFF_BLO (3 * MAT_BYTES)

__device__ __forceinline__ void gemm_load_stage(
    uint32_t st, int tid,
    const __nv_bfloat16* __restrict__ Ahi, const __nv_bfloat16* __restrict__ Alo,
    const __nv_bfloat16* __restrict__ Bhi, const __nv_bfloat16* __restrict__ Blo,
    int mBase, int nBase, int kt)
{
    const size_t k0 = (size_t)kt * BK;
    // each matrix: 128 rows x 4 chunks of 16B = 512 cp.async, 2 per thread
    #pragma unroll
    for (int i = 0; i < 2; i++) {
        int e = tid + i * 256, r = e >> 2, c = e & 3;
        CP_ASYNC16(st + OFF_AHI + r * 80 + c * 16,
                   Ahi + (size_t)(mBase + r) * KDIM + k0 + c * 8);
    }
    #pragma unroll
    for (int i = 0; i < 2; i++) {
        int e = tid + i * 256, r = e >> 2, c = e & 3;
        CP_ASYNC16(st + OFF_ALO + r * 80 + c * 16,
                   Alo + (size_t)(mBase + r) * KDIM + k0 + c * 8);
    }
    #pragma unroll
    for (int i = 0; i < 2; i++) {
        int e = tid + i * 256, r = e >> 2, c = e & 3;
        CP_ASYNC16(st + OFF_BHI + r * 80 + c * 16,
                   Bhi + (size_t)(nBase + r) * KDIM + k0 + c * 8);
    }
    #pragma unroll
    for (int i = 0; i < 2; i++) {
        int e = tid + i * 256, r = e >> 2, c = e & 3;
        CP_ASYNC16(st + OFF_BLO + r * 80 + c * 16,
                   Blo + (size_t)(nBase + r) * KDIM + k0 + c * 8);
    }
    CP_COMMIT();
}

__global__ __launch_bounds__(256, 1)
void gemm_mma(const __nv_bfloat16* __restrict__ Ahi, const __nv_bfloat16* __restrict__ Alo,
              const __nv_bfloat16* __restrict__ Bhi, const __nv_bfloat16* __restrict__ Blo,
              const float* __restrict__ bias, float* __restrict__ C, int Nglob)
{
    extern __shared__ char smc[];
    const uint32_t sbase = smem_u32(smc);
    const int tid  = threadIdx.x;
    const int wid  = tid >> 5, lane = tid & 31;
    const int wm   = wid & 3;           // 0..3 -> M
    const int wn   = wid >> 2;          // 0..1 -> N
    const int mBase = blockIdx.y * BM, nBase = blockIdx.x * BN;

    // ldmatrix lane byte-offsets within a 128xRS tile
    // A (row-major m16k16 frag): lane -> row (lane&15), k-half (lane>>4)*8
    const uint32_t a_lane =
        (uint32_t)(((wm * 32 + (lane & 15)) * RS + ((lane >> 4) << 3)) * 2);
    // B ([n][k] rows; x4 -> two n8 blocks x two k8 halves)
    const uint32_t b_lane =
        (uint32_t)(((wn * 64 + ((lane >> 4) << 3) + (lane & 7)) * RS + (((lane >> 3) & 1) << 3)) * 2);

    float acc[2][8][4];
    #pragma unroll
    for (int i = 0; i < 2; i++)
        #pragma unroll
        for (int j = 0; j < 8; j++)
            #pragma unroll
            for (int c = 0; c < 4; c++)
                acc[i][j][c] = 0.0f;

    gemm_load_stage(sbase, tid, Ahi, Alo, Bhi, Blo, mBase, nBase, 0);
    gemm_load_stage(sbase + STAGE_BYTES, tid, Ahi, Alo, Bhi, Blo, mBase, nBase, 1);

    for (int it = 0; it < NIT; it++) {
        if (it + 2 < NIT) { CP_WAIT1(); } else { CP_WAIT0(); }
        __syncthreads();
        const uint32_t st = sbase + (it & 1) * STAGE_BYTES;

        #pragma unroll
        for (int kk = 0; kk < 2; kk++) {
            const uint32_t koff = kk * 32;   // 16 bf16 = 32B along k
            uint32_t bh[4][4], bl[4][4];
            #pragma unroll
            for (int j = 0; j < 4; j++) {
                ldsm_x4(bh[j], st + OFF_BHI + b_lane + j * (16 * RS * 2) + koff);
                ldsm_x4(bl[j], st + OFF_BLO + b_lane + j * (16 * RS * 2) + koff);
            }
            #pragma unroll
            for (int i = 0; i < 2; i++) {
                uint32_t ah[4], al[4];
                ldsm_x4(ah, st + OFF_AHI + a_lane + i * (16 * RS * 2) + koff);
                ldsm_x4(al, st + OFF_ALO + a_lane + i * (16 * RS * 2) + koff);
                #pragma unroll
                for (int jj = 0; jj < 8; jj++) {
                    const uint32_t* bhp = &bh[jj >> 1][(jj & 1) * 2];
                    const uint32_t* blp = &bl[jj >> 1][(jj & 1) * 2];
                    mma16816(acc[i][jj], ah, bhp);
                    mma16816(acc[i][jj], ah, blp);
                    mma16816(acc[i][jj], al, bhp);
                }
            }
        }
        __syncthreads();
        if (it + 2 < NIT)
            gemm_load_stage(sbase + (it & 1) * STAGE_BYTES, tid,
                            Ahi, Alo, Bhi, Blo, mBase, nBase, it + 2);
    }

    // epilogue: accum layout m16n8 f32: thread holds (row lane>>2 [+8], col (lane&3)*2 [+1])
    const int r0 = mBase + wm * 32 + (lane >> 2);
    const int c0 = nBase + wn * 64 + (lane & 3) * 2;
    #pragma unroll
    for (int i = 0; i < 2; i++) {
        #pragma unroll
        for (int jj = 0; jj < 8; jj++) {
            const int col = c0 + jj * 8;
            const float b0 = __ldg(&bias[col]), b1 = __ldg(&bias[col + 1]);
            const int row = r0 + i * 16;
            float2 v0 = make_float2(acc[i][jj][0] + b0, acc[i][jj][1] + b1);
            float2 v1 = make_float2(acc[i][jj][2] + b0, acc[i][jj][3] + b1);
            *(float2*)&C[(size_t)row * Nglob + col]       = v0;
            *(float2*)&C[(size_t)(row + 8) * Nglob + col] = v1;
        }
    }
}

// ============================ conversion kernels ============================
__global__ void split_kernel(const float* __restrict__ in,
                             __nv_bfloat16* __restrict__ hi,
                             __nv_bfloat16* __restrict__ lo, int n)
{
    int idx = (blockIdx.x * blockDim.x + threadIdx.x) * 4;
    if (idx >= n) return;
    float4 v = *(const float4*)(in + idx);
    __nv_bfloat16 h0 = __float2bfloat16(v.x), h1 = __float2bfloat16(v.y);
    __nv_bfloat16 h2 = __float2bfloat16(v.z), h3 = __float2bfloat16(v.w);
    __nv_bfloat16 l0 = __float2bfloat16(v.x - __bfloat162float(h0));
    __nv_bfloat16 l1 = __float2bfloat16(v.y - __bfloat162float(h1));
    __nv_bfloat16 l2 = __float2bfloat16(v.z - __bfloat162float(h2));
    __nv_bfloat16 l3 = __float2bfloat16(v.w - __bfloat162float(h3));
    __nv_bfloat162* H = (__nv_bfloat162*)(hi + idx);
    __nv_bfloat162* L = (__nv_bfloat162*)(lo + idx);
    H[0] = {h0, h1}; H[1] = {h2, h3};
    L[0] = {l0, l1}; L[1] = {l2, l3};
}

// w[K, N] (N contiguous) -> t[N, K] (K contiguous), split into hi/lo bf16
__global__ void transpose_split(const float* __restrict__ w,
                                __nv_bfloat16* __restrict__ thi,
                                __nv_bfloat16* __restrict__ tlo, int K, int N)
{
    __shared__ float tile[32][33];
    const int kb = blockIdx.y * 32, nb = blockIdx.x * 32;
    const int tx = threadIdx.x, ty = threadIdx.y;
    #pragma unroll
    for (int j = 0; j < 4; j++) {
        int r = ty + 8 * j;
        tile[r][tx] = w[(size_t)(kb + r) * N + nb + tx];
    }
    __syncthreads();
    #pragma unroll
    for (int j = 0; j < 4; j++) {
        int r = ty + 8 * j;
        float v = tile[tx][r];
        __nv_bfloat16 h = __float2bfloat16(v);
        __nv_bfloat16 l = __float2bfloat16(v - __bfloat162float(h));
        size_t o = (size_t)(nb + r) * K + kb + tx;
        thi[o] = h; tlo[o] = l;
    }
}

// ============================ flash attention (fp32) ========================
#define FL_BM 128
#define FL_BN 64
#define QS_STRIDE 65
#define KV_STRIDE 68
#define OFF_QS   0
#define OFF_KTS  (OFF_QS  + 128 * QS_STRIDE)
#define OFF_VS   (OFF_KTS + 64 * KV_STRIDE)
#define OFF_SS   (OFF_VS  + 64 * KV_STRIDE)
#define OFF_M    (OFF_SS  + 128 * QS_STRIDE)
#define OFF_L    (OFF_M + 128)
#define OFF_CS   (OFF_L + 128)
#define OFF_RED  (OFF_CS + 128)
#define FLASH_SMEM_FLOATS (OFF_RED + 256)
#define FLASH_SMEM_BYTES  (FLASH_SMEM_FLOATS * 4)

__global__ __launch_bounds__(256, 1)
void flash_kernel(const float* __restrict__ Q, const float* __restrict__ Kg,
                  const float* __restrict__ Vg, float* __restrict__ O)
{
    extern __shared__ float smf[];
    float* Qs   = smf + OFF_QS;
    float* Kts  = smf + OFF_KTS;
    float* Vs   = smf + OFF_VS;
    float* Ss   = smf + OFF_SS;
    float* mrow = smf + OFF_M;
    float* lrow = smf + OFF_L;
    float* cs   = smf + OFF_CS;
    float* red  = smf + OFF_RED;

    const int tid   = threadIdx.x;
    const int head  = blockIdx.y;
    const int g     = head >> 3;
    const int qcol0 = head * DH;
    const int kcol0 = g * DH;
    const int qrow0 = blockIdx.x * FL_BM;

    const int tx = tid & 15;
    const int ty = tid >> 4;

    #pragma unroll
    for (int i = 0; i < 8; i++) {
        int e = tid + i * 256;
        int row = e >> 4;
        int c4  = (e & 15) * 4;
        float4 q4 = *(const float4*)&Q[(size_t)(qrow0 + row) * DMODEL + qcol0 + c4];
        float* dst = &Qs[row * QS_STRIDE + c4];
        dst[0] = q4.x; dst[1] = q4.y; dst[2] = q4.z; dst[3] = q4.w;
    }
    if (tid < 128) { mrow[tid] = -INFINITY; lrow[tid] = 0.0f; }

    float acc[8][4];
    #pragma unroll
    for (int i = 0; i < 8; i++)
        #pragma unroll
        for (int j = 0; j < 4; j++) acc[i][j] = 0.0f;

    const int row_s = tid & 127;
    const int half  = tid >> 7;

    for (int kt = 0; kt < SEQ / FL_BN; kt++) {
        __syncthreads();
        const int krow0 = kt * FL_BN;
        #pragma unroll
        for (int i = 0; i < 4; i++) {
            int e = tid + i * 256;
            int key = e >> 4;
            int c4  = (e & 15) * 4;
            float4 k4 = *(const float4*)&Kg[(size_t)(krow0 + key) * DGROUP + kcol0 + c4];
            Kts[(c4 + 0) * KV_STRIDE + key] = k4.x;
            Kts[(c4 + 1) * KV_STRIDE + key] = k4.y;
            Kts[(c4 + 2) * KV_STRIDE + key] = k4.z;
            Kts[(c4 + 3) * KV_STRIDE + key] = k4.w;
            float4 v4 = *(const float4*)&Vg[(size_t)(krow0 + key) * DGROUP + kcol0 + c4];
            *(float4*)&Vs[key * KV_STRIDE + c4] = v4;
        }
        __syncthreads();

        float s[8][4];
        #pragma unroll
        for (int i = 0; i < 8; i++)
            #pragma unroll
            for (int j = 0; j < 4; j++) s[i][j] = 0.0f;

        #pragma unroll 8
        for (int d = 0; d < DH; d++) {
            float4 kb = *(const float4*)&Kts[d * KV_STRIDE + tx * 4];
            float qa[8];
            #pragma unroll
            for (int i = 0; i < 8; i++) qa[i] = Qs[(ty * 8 + i) * QS_STRIDE + d];
            #pragma unroll
            for (int i = 0; i < 8; i++) {
                s[i][0] = fmaf(qa[i], kb.x, s[i][0]);
                s[i][1] = fmaf(qa[i], kb.y, s[i][1]);
                s[i][2] = fmaf(qa[i], kb.z, s[i][2]);
                s[i][3] = fmaf(qa[i], kb.w, s[i][3]);
            }
        }
        const float scale = 0.125f;
        #pragma unroll
        for (int i = 0; i < 8; i++)
            #pragma unroll
            for (int j = 0; j < 4; j++)
                Ss[(ty * 8 + i) * QS_STRIDE + tx * 4 + j] = s[i][j] * scale;
        __syncthreads();

        {
            float lm = -INFINITY;
            const float* srow = &Ss[row_s * QS_STRIDE + half * 32];
            #pragma unroll 8
            for (int c = 0; c < 32; c++) lm = fmaxf(lm, srow[c]);
            red[tid] = lm;
        }
        __syncthreads();
        if (tid < 128) {
            float tm = fmaxf(red[tid], red[tid + 128]);
            float mo = mrow[tid];
            float mn = fmaxf(mo, tm);
            mrow[tid] = mn;
            cs[tid]   = __expf(mo - mn);
        }
        __syncthreads();
        {
            float mn = mrow[row_s];
            float ls = 0.0f;
            float* srow = &Ss[row_s * QS_STRIDE + half * 32];
            #pragma unroll 8
            for (int c = 0; c < 32; c++) {
                float p = __expf(srow[c] - mn);
                srow[c] = p;
                ls += p;
            }
            red[tid] = ls;
        }
        __syncthreads();
        if (tid < 128)
            lrow[tid] = lrow[tid] * cs[tid] + red[tid] + red[tid + 128];
        __syncthreads();

        #pragma unroll
        for (int i = 0; i < 8; i++) {
            float c_ = cs[ty * 8 + i];
            #pragma unroll
            for (int j = 0; j < 4; j++) acc[i][j] *= c_;
        }

        #pragma unroll 8
        for (int k = 0; k < FL_BN; k++) {
            float4 vb = *(const float4*)&Vs[k * KV_STRIDE + tx * 4];
            float pa[8];
            #pragma unroll
            for (int i = 0; i < 8; i++) pa[i] = Ss[(ty * 8 + i) * QS_STRIDE + k];
            #pragma unroll
            for (int i = 0; i < 8; i++) {
                acc[i][0] = fmaf(pa[i], vb.x, acc[i][0]);
                acc[i][1] = fmaf(pa[i], vb.y, acc[i][1]);
                acc[i][2] = fmaf(pa[i], vb.z, acc[i][2]);
                acc[i][3] = fmaf(pa[i], vb.w, acc[i][3]);
            }
        }
    }

    #pragma unroll
    for (int i = 0; i < 8; i++) {
        int r = ty * 8 + i;
        float inv = 1.0f / lrow[r];
        float4 o;
        o.x = acc[i][0] * inv;
        o.y = acc[i][1] * inv;
        o.z = acc[i][2] * inv;
        o.w = acc[i][3] * inv;
        *(float4*)&O[(size_t)(qrow0 + r) * DMODEL + qcol0 + tx * 4] = o;
    }
}

// ============================ kernel_launch =================================
extern "C" void kernel_launch(void* const* d_in, const int* in_sizes, int n_in,
                              void* d_out, int out_size)
{
    const float* x  = (const float*)d_in[0];
    const float* wq = (const float*)d_in[1];
    const float* bq = (const float*)d_in[2];
    const float* wk = (const float*)d_in[3];
    const float* bk = (const float*)d_in[4];
    const float* wv = (const float*)d_in[5];
    const float* bv = (const float*)d_in[6];
    const float* wo = (const float*)d_in[7];
    const float* bo = (const float*)d_in[8];
    float* out = (float*)d_out;

    float *Qb, *Kb, *Vb, *Ob;
    cudaGetSymbolAddress((void**)&Qb, g_Q);
    cudaGetSymbolAddress((void**)&Kb, g_K);
    cudaGetSymbolAddress((void**)&Vb, g_V);
    cudaGetSymbolAddress((void**)&Ob, g_O);
    __nv_bfloat16 *xhi, *xlo, *Ohi, *Olo;
    __nv_bfloat16 *wqh, *wql, *wkh, *wkl, *wvh, *wvl, *woh, *wol;
    cudaGetSymbolAddress((void**)&xhi, g_xhi);
    cudaGetSymbolAddress((void**)&xlo, g_xlo);
    cudaGetSymbolAddress((void**)&Ohi, g_Ohi);
    cudaGetSymbolAddress((void**)&Olo, g_Olo);
    cudaGetSymbolAddress((void**)&wqh, g_wqT_hi);
    cudaGetSymbolAddress((void**)&wql, g_wqT_lo);
    cudaGetSymbolAddress((void**)&wkh, g_wkT_hi);
    cudaGetSymbolAddress((void**)&wkl, g_wkT_lo);
    cudaGetSymbolAddress((void**)&wvh, g_wvT_hi);
    cudaGetSymbolAddress((void**)&wvl, g_wvT_lo);
    cudaGetSymbolAddress((void**)&woh, g_woT_hi);
    cudaGetSymbolAddress((void**)&wol, g_woT_lo);

    cudaFuncSetAttribute(gemm_mma, cudaFuncAttributeMaxDynamicSharedMemorySize, GEMM_SMEM);
    cudaFuncSetAttribute(flash_kernel, cudaFuncAttributeMaxDynamicSharedMemorySize, FLASH_SMEM_BYTES);

    const int nX = SEQ * DMODEL;

    // 1) split x into bf16 hi/lo
    split_kernel<<<nX / (256 * 4), 256>>>(x, xhi, xlo, nX);
    // 2) transpose+split weights: w[4096, N] -> [N, 4096]
    transpose_split<<<dim3(DMODEL / 32, DMODEL / 32), dim3(32, 8)>>>(wq, wqh, wql, DMODEL, DMODEL);
    transpose_split<<<dim3(DGROUP / 32, DMODEL / 32), dim3(32, 8)>>>(wk, wkh, wkl, DMODEL, DGROUP);
    transpose_split<<<dim3(DGROUP / 32, DMODEL / 32), dim3(32, 8)>>>(wv, wvh, wvl, DMODEL, DGROUP);
    transpose_split<<<dim3(DMODEL / 32, DMODEL / 32), dim3(32, 8)>>>(wo, woh, wol, DMODEL, DMODEL);

    // 3) projections on tensor pipe (mma.sync)
    gemm_mma<<<dim3(DMODEL / BN, SEQ / BM), 256, GEMM_SMEM>>>(xhi, xlo, wqh, wql, bq, Qb, DMODEL);
    gemm_mma<<<dim3(DGROUP / BN, SEQ / BM), 256, GEMM_SMEM>>>(xhi, xlo, wkh, wkl, bk, Kb, DGROUP);
    gemm_mma<<<dim3(DGROUP / BN, SEQ / BM), 256, GEMM_SMEM>>>(xhi, xlo, wvh, wvl, bv, Vb, DGROUP);

    // 4) attention (fp32)
    flash_kernel<<<dim3(SEQ / FL_BM, NHEADS), 256, FLASH_SMEM_BYTES>>>(Qb, Kb, Vb, Ob);

    // 5) output projection
    split_kernel<<<nX / (256 * 4), 256>>>(Ob, Ohi, Olo, nX);
    gemm_mma<<<dim3(DMODEL / BN, SEQ / BM), 256, GEMM_SMEM>>>(Ohi, Olo, woh, wol, bo, out, DMODEL);
}

// round 5
// speedup vs baseline: 2.6198x; 1.4588x over previous
#include <cuda_runtime.h>
#include <cuda_bf16.h>
#include <math.h>
#include <stdint.h>

// ============================ problem constants =============================
#define SEQ      2048
#define DMODEL   4096
#define DGROUP   512
#define DH       64
#define NHEADS   64
#define KDIM     4096

// ============================ scratch (device globals) ======================
__device__ __nv_bfloat16 g_xhi[SEQ * DMODEL];
__device__ __nv_bfloat16 g_xlo[SEQ * DMODEL];
__device__ __nv_bfloat16 g_Qhi[SEQ * DMODEL];
__device__ __nv_bfloat16 g_Qlo[SEQ * DMODEL];
__device__ __nv_bfloat16 g_Khi[SEQ * DGROUP];
__device__ __nv_bfloat16 g_Klo[SEQ * DGROUP];
__device__ __nv_bfloat16 g_Vhi[SEQ * DGROUP];
__device__ __nv_bfloat16 g_Vlo[SEQ * DGROUP];
__device__ __nv_bfloat16 g_Ohi[SEQ * DMODEL];
__device__ __nv_bfloat16 g_Olo[SEQ * DMODEL];
__device__ __nv_bfloat16 g_wqT_hi[DMODEL * DMODEL];
__device__ __nv_bfloat16 g_wqT_lo[DMODEL * DMODEL];
__device__ __nv_bfloat16 g_wkT_hi[DGROUP * DMODEL];
__device__ __nv_bfloat16 g_wkT_lo[DGROUP * DMODEL];
__device__ __nv_bfloat16 g_wvT_hi[DGROUP * DMODEL];
__device__ __nv_bfloat16 g_wvT_lo[DGROUP * DMODEL];
__device__ __nv_bfloat16 g_woT_hi[DMODEL * DMODEL];
__device__ __nv_bfloat16 g_woT_lo[DMODEL * DMODEL];

// ============================ PTX helpers ===================================
__device__ __forceinline__ uint32_t smem_u32(const void* p) {
    uint32_t a;
    asm("{ .reg .u64 t; cvta.to.shared.u64 t, %1; cvt.u32.u64 %0, t; }" : "=r"(a) : "l"(p));
    return a;
}
#define CP_ASYNC16(dst, src) \
    asm volatile("cp.async.cg.shared.global [%0], [%1], 16;" :: "r"(dst), "l"(src) : "memory")
#define CP_COMMIT() asm volatile("cp.async.commit_group;" ::: "memory")
#define CP_WAIT0()  asm volatile("cp.async.wait_group 0;" ::: "memory")
#define CP_WAIT1()  asm volatile("cp.async.wait_group 1;" ::: "memory")

__device__ __forceinline__ void ldsm_x4(uint32_t* r, uint32_t addr) {
    asm volatile("ldmatrix.sync.aligned.m8n8.x4.shared.b16 {%0,%1,%2,%3}, [%4];"
                 : "=r"(r[0]), "=r"(r[1]), "=r"(r[2]), "=r"(r[3]) : "r"(addr));
}
__device__ __forceinline__ void ldsm_x4_t(uint32_t* r, uint32_t addr) {
    asm volatile("ldmatrix.sync.aligned.m8n8.x4.trans.shared.b16 {%0,%1,%2,%3}, [%4];"
                 : "=r"(r[0]), "=r"(r[1]), "=r"(r[2]), "=r"(r[3]) : "r"(addr));
}
__device__ __forceinline__ void mma16816(float* d, const uint32_t* a, const uint32_t* b) {
    asm volatile(
        "mma.sync.aligned.m16n8k16.row.col.f32.bf16.bf16.f32 "
        "{%0,%1,%2,%3}, {%4,%5,%6,%7}, {%8,%9}, {%0,%1,%2,%3};"
        : "+f"(d[0]), "+f"(d[1]), "+f"(d[2]), "+f"(d[3])
        : "r"(a[0]), "r"(a[1]), "r"(a[2]), "r"(a[3]), "r"(b[0]), "r"(b[1]));
}
// pack two f32 -> bf16x2 (lo in low half, hi_arg in high half)
__device__ __forceinline__ uint32_t packbf2(float lo, float hi) {
    uint32_t r;
    asm("cvt.rn.satfinite.bf16x2.f32 %0, %1, %2;" : "=r"(r) : "f"(hi), "f"(lo));
    return r;
}
__device__ __forceinline__ void unpackbf2(uint32_t v, float& lo, float& hi) {
    __nv_bfloat162 b = *reinterpret_cast<__nv_bfloat162*>(&v);
    lo = __bfloat162float(b.x); hi = __bfloat162float(b.y);
}

// ============================ split-bf16 mma.sync GEMM ======================
#define BM 128
#define BN 128
#define BK 32
#define NIT (KDIM / BK)          // 128
#define RS 40
#define MAT_BYTES (128 * RS * 2)
#define STAGE_BYTES (4 * MAT_BYTES)
#define GEMM_SMEM (2 * STAGE_BYTES)
#define OFF_AHI 0
#define OFF_ALO (1 * MAT_BYTES)
#define OFF_BHI (2 * MAT_BYTES)
#define OFF_BLO (3 * MAT_BYTES)

__device__ __forceinline__ void gemm_load_stage(
    uint32_t st, int tid,
    const __nv_bfloat16* __restrict__ Ahi, const __nv_bfloat16* __restrict__ Alo,
    const __nv_bfloat16* __restrict__ Bhi, const __nv_bfloat16* __restrict__ Blo,
    int mBase, int nBase, int kt)
{
    const size_t k0 = (size_t)kt * BK;
    #pragma unroll
    for (int i = 0; i < 2; i++) {
        int e = tid + i * 256, r = e >> 2, c = e & 3;
        CP_ASYNC16(st + OFF_AHI + r * 80 + c * 16, Ahi + (size_t)(mBase + r) * KDIM + k0 + c * 8);
    }
    #pragma unroll
    for (int i = 0; i < 2; i++) {
        int e = tid + i * 256, r = e >> 2, c = e & 3;
        CP_ASYNC16(st + OFF_ALO + r * 80 + c * 16, Alo + (size_t)(mBase + r) * KDIM + k0 + c * 8);
    }
    #pragma unroll
    for (int i = 0; i < 2; i++) {
        int e = tid + i * 256, r = e >> 2, c = e & 3;
        CP_ASYNC16(st + OFF_BHI + r * 80 + c * 16, Bhi + (size_t)(nBase + r) * KDIM + k0 + c * 8);
    }
    #pragma unroll
    for (int i = 0; i < 2; i++) {
        int e = tid + i * 256, r = e >> 2, c = e & 3;
        CP_ASYNC16(st + OFF_BLO + r * 80 + c * 16, Blo + (size_t)(nBase + r) * KDIM + k0 + c * 8);
    }
    CP_COMMIT();
}

// mode 0: write fp32 Cf. mode 1: write split bf16 Chi/Clo.
__global__ __launch_bounds__(256, 1)
void gemm_mma(const __nv_bfloat16* __restrict__ Ahi, const __nv_bfloat16* __restrict__ Alo,
              const __nv_bfloat16* __restrict__ Bhi, const __nv_bfloat16* __restrict__ Blo,
              const float* __restrict__ bias, float* __restrict__ Cf,
              __nv_bfloat16* __restrict__ Chi, __nv_bfloat16* __restrict__ Clo,
              int Nglob, int mode)
{
    extern __shared__ char smc[];
    const uint32_t sbase = smem_u32(smc);
    const int tid  = threadIdx.x;
    const int wid  = tid >> 5, lane = tid & 31;
    const int wm   = wid & 3;
    const int wn   = wid >> 2;
    const int mBase = blockIdx.y * BM, nBase = blockIdx.x * BN;

    const uint32_t a_lane =
        (uint32_t)(((wm * 32 + (lane & 15)) * RS + ((lane >> 4) << 3)) * 2);
    const uint32_t b_lane =
        (uint32_t)(((wn * 64 + ((lane >> 4) << 3) + (lane & 7)) * RS + (((lane >> 3) & 1) << 3)) * 2);

    float acc[2][8][4];
    #pragma unroll
    for (int i = 0; i < 2; i++)
        #pragma unroll
        for (int j = 0; j < 8; j++)
            #pragma unroll
            for (int c = 0; c < 4; c++)
                acc[i][j][c] = 0.0f;

    gemm_load_stage(sbase, tid, Ahi, Alo, Bhi, Blo, mBase, nBase, 0);
    gemm_load_stage(sbase + STAGE_BYTES, tid, Ahi, Alo, Bhi, Blo, mBase, nBase, 1);

    for (int it = 0; it < NIT; it++) {
        if (it + 2 < NIT) { CP_WAIT1(); } else { CP_WAIT0(); }
        __syncthreads();
        const uint32_t st = sbase + (it & 1) * STAGE_BYTES;

        #pragma unroll
        for (int kk = 0; kk < 2; kk++) {
            const uint32_t koff = kk * 32;
            uint32_t bh[4][4], bl[4][4];
            #pragma unroll
            for (int j = 0; j < 4; j++) {
                ldsm_x4(bh[j], st + OFF_BHI + b_lane + j * (16 * RS * 2) + koff);
                ldsm_x4(bl[j], st + OFF_BLO + b_lane + j * (16 * RS * 2) + koff);
            }
            #pragma unroll
            for (int i = 0; i < 2; i++) {
                uint32_t ah[4], al[4];
                ldsm_x4(ah, st + OFF_AHI + a_lane + i * (16 * RS * 2) + koff);
                ldsm_x4(al, st + OFF_ALO + a_lane + i * (16 * RS * 2) + koff);
                #pragma unroll
                for (int jj = 0; jj < 8; jj++) {
                    const uint32_t* bhp = &bh[jj >> 1][(jj & 1) * 2];
                    const uint32_t* blp = &bl[jj >> 1][(jj & 1) * 2];
                    mma16816(acc[i][jj], ah, bhp);
                    mma16816(acc[i][jj], ah, blp);
                    mma16816(acc[i][jj], al, bhp);
                }
            }
        }
        __syncthreads();
        if (it + 2 < NIT)
            gemm_load_stage(sbase + (it & 1) * STAGE_BYTES, tid,
                            Ahi, Alo, Bhi, Blo, mBase, nBase, it + 2);
    }

    const int r0 = mBase + wm * 32 + (lane >> 2);
    const int c0 = nBase + wn * 64 + (lane & 3) * 2;
    #pragma unroll
    for (int i = 0; i < 2; i++) {
        #pragma unroll
        for (int jj = 0; jj < 8; jj++) {
            const int col = c0 + jj * 8;
            const float b0 = __ldg(&bias[col]), b1 = __ldg(&bias[col + 1]);
            const int row = r0 + i * 16;
            float u0 = acc[i][jj][0] + b0, u1 = acc[i][jj][1] + b1;
            float u2 = acc[i][jj][2] + b0, u3 = acc[i][jj][3] + b1;
            if (mode == 0) {
                *(float2*)&Cf[(size_t)row * Nglob + col]       = make_float2(u0, u1);
                *(float2*)&Cf[(size_t)(row + 8) * Nglob + col] = make_float2(u2, u3);
            } else {
                uint32_t h0 = packbf2(u0, u1), h1 = packbf2(u2, u3);
                float f0, f1, f2, f3;
                unpackbf2(h0, f0, f1); unpackbf2(h1, f2, f3);
                uint32_t l0 = packbf2(u0 - f0, u1 - f1), l1 = packbf2(u2 - f2, u3 - f3);
                *(uint32_t*)&Chi[(size_t)row * Nglob + col]       = h0;
                *(uint32_t*)&Chi[(size_t)(row + 8) * Nglob + col] = h1;
                *(uint32_t*)&Clo[(size_t)row * Nglob + col]       = l0;
                *(uint32_t*)&Clo[(size_t)(row + 8) * Nglob + col] = l1;
            }
        }
    }
}

// ============================ conversion kernels ============================
__global__ void split_kernel(const float* __restrict__ in,
                             __nv_bfloat16* __restrict__ hi,
                             __nv_bfloat16* __restrict__ lo, int n)
{
    int idx = (blockIdx.x * blockDim.x + threadIdx.x) * 4;
    if (idx >= n) return;
    float4 v = *(const float4*)(in + idx);
    __nv_bfloat16 h0 = __float2bfloat16(v.x), h1 = __float2bfloat16(v.y);
    __nv_bfloat16 h2 = __float2bfloat16(v.z), h3 = __float2bfloat16(v.w);
    __nv_bfloat16 l0 = __float2bfloat16(v.x - __bfloat162float(h0));
    __nv_bfloat16 l1 = __float2bfloat16(v.y - __bfloat162float(h1));
    __nv_bfloat16 l2 = __float2bfloat16(v.z - __bfloat162float(h2));
    __nv_bfloat16 l3 = __float2bfloat16(v.w - __bfloat162float(h3));
    __nv_bfloat162* H = (__nv_bfloat162*)(hi + idx);
    __nv_bfloat162* L = (__nv_bfloat162*)(lo + idx);
    H[0] = {h0, h1}; H[1] = {h2, h3};
    L[0] = {l0, l1}; L[1] = {l2, l3};
}

__global__ void transpose_split(const float* __restrict__ w,
                                __nv_bfloat16* __restrict__ thi,
                                __nv_bfloat16* __restrict__ tlo, int K, int N)
{
    __shared__ float tile[32][33];
    const int kb = blockIdx.y * 32, nb = blockIdx.x * 32;
    const int tx = threadIdx.x, ty = threadIdx.y;
    #pragma unroll
    for (int j = 0; j < 4; j++) {
        int r = ty + 8 * j;
        tile[r][tx] = w[(size_t)(kb + r) * N + nb + tx];
    }
    __syncthreads();
    #pragma unroll
    for (int j = 0; j < 4; j++) {
        int r = ty + 8 * j;
        float v = tile[tx][r];
        __nv_bfloat16 h = __float2bfloat16(v);
        __nv_bfloat16 l = __float2bfloat16(v - __bfloat162float(h));
        size_t o = (size_t)(nb + r) * K + kb + tx;
        thi[o] = h; tlo[o] = l;
    }
}

// ============================ flash attention (mma.sync, split bf16) ========
// CTA: 256 thr = 8 warps; warp w owns q-rows [w*16, w*16+16). 128 q-rows/CTA.
// grid (16 q-tiles, 64 heads). K-tile = 64 keys/iter, 32 iters.
// SMEM (bf16 stride 72): Qhi, Qlo [128x64]; 2 stages x {Khi,Klo,Vhi,Vlo}[64x64].
#define FRS 72
#define FQ_BYTES  (128 * FRS * 2)       // 18432
#define FKV_BYTES (64 * FRS * 2)        // 9216
#define FSTG_BYTES (4 * FKV_BYTES)      // 36864
#define FQLO_OFF  FQ_BYTES
#define FSTG_OFF  (2 * FQ_BYTES)
#define FLASH_SMEM (FSTG_OFF + 2 * FSTG_BYTES)  // 110592
#define FNIT (SEQ / 64)                 // 32

__device__ __forceinline__ void flash_load_kv(
    uint32_t st, int tid,
    const __nv_bfloat16* __restrict__ Khi, const __nv_bfloat16* __restrict__ Klo,
    const __nv_bfloat16* __restrict__ Vhi, const __nv_bfloat16* __restrict__ Vlo,
    int krow0, int kcol0)
{
    #pragma unroll
    for (int i = 0; i < 2; i++) {
        int e = tid + i * 256, r = e >> 3, c = e & 7;
        CP_ASYNC16(st + r * (FRS * 2) + c * 16, Khi + (size_t)(krow0 + r) * DGROUP + kcol0 + c * 8);
    }
    #pragma unroll
    for (int i = 0; i < 2; i++) {
        int e = tid + i * 256, r = e >> 3, c = e & 7;
        CP_ASYNC16(st + FKV_BYTES + r * (FRS * 2) + c * 16, Klo + (size_t)(krow0 + r) * DGROUP + kcol0 + c * 8);
    }
    #pragma unroll
    for (int i = 0; i < 2; i++) {
        int e = tid + i * 256, r = e >> 3, c = e & 7;
        CP_ASYNC16(st + 2 * FKV_BYTES + r * (FRS * 2) + c * 16, Vhi + (size_t)(krow0 + r) * DGROUP + kcol0 + c * 8);
    }
    #pragma unroll
    for (int i = 0; i < 2; i++) {
        int e = tid + i * 256, r = e >> 3, c = e & 7;
        CP_ASYNC16(st + 3 * FKV_BYTES + r * (FRS * 2) + c * 16, Vlo + (size_t)(krow0 + r) * DGROUP + kcol0 + c * 8);
    }
    CP_COMMIT();
}

__global__ __launch_bounds__(256, 1)
void flash_mma(const __nv_bfloat16* __restrict__ Qhi, const __nv_bfloat16* __restrict__ Qlo,
               const __nv_bfloat16* __restrict__ Khi, const __nv_bfloat16* __restrict__ Klo,
               const __nv_bfloat16* __restrict__ Vhi, const __nv_bfloat16* __restrict__ Vlo,
               __nv_bfloat16* __restrict__ Ohi, __nv_bfloat16* __restrict__ Olo)
{
    extern __shared__ char smc[];
    const uint32_t sbase = smem_u32(smc);
    const int tid  = threadIdx.x;
    const int wid  = tid >> 5, lane = tid & 31;
    const int head = blockIdx.y, g = head >> 3;
    const int qrow0 = blockIdx.x * 128;
    const int qcol0 = head * DH, kcol0 = g * DH;

    // load Q (hi+lo) + stage0, one group; then stage1, second group
    #pragma unroll
    for (int i = 0; i < 4; i++) {
        int e = tid + i * 256, r = e >> 3, c = e & 7;
        CP_ASYNC16(sbase + r * (FRS * 2) + c * 16, Qhi + (size_t)(qrow0 + r) * DMODEL + qcol0 + c * 8);
    }
    #pragma unroll
    for (int i = 0; i < 4; i++) {
        int e = tid + i * 256, r = e >> 3, c = e & 7;
        CP_ASYNC16(sbase + FQLO_OFF + r * (FRS * 2) + c * 16, Qlo + (size_t)(qrow0 + r) * DMODEL + qcol0 + c * 8);
    }
    flash_load_kv(sbase + FSTG_OFF, tid, Khi, Klo, Vhi, Vlo, 0, kcol0);          // group 0 (Q + stage0)
    flash_load_kv(sbase + FSTG_OFF + FSTG_BYTES, tid, Khi, Klo, Vhi, Vlo, 64, kcol0); // group 1

    // ldmatrix lane offsets
    const uint32_t a_lane =  // Q / A-frag: rows wid*16.., 16 k per step
        (uint32_t)(((wid * 16 + (lane & 15)) * FRS + ((lane >> 4) << 3)) * 2);
    const uint32_t b_lane =  // K / B-frag non-trans: [key][d]
        (uint32_t)(((((lane >> 4) << 3) + (lane & 7)) * FRS + (((lane >> 3) & 1) << 3)) * 2);
    const uint32_t v_lane =  // V / B-frag trans: [key][d] -> (n=d, k=key)
        (uint32_t)(((((lane >> 3) & 1) * 8 + (lane & 7)) * FRS + ((lane >> 4) << 3)) * 2);

    float oacc[8][4];
    #pragma unroll
    for (int t = 0; t < 8; t++)
        #pragma unroll
        for (int c = 0; c < 4; c++) oacc[t][c] = 0.0f;
    float m0 = -INFINITY, m1 = -INFINITY, l0 = 0.0f, l1 = 0.0f;

    for (int it = 0; it < FNIT; it++) {
        if (it < FNIT - 1) { CP_WAIT1(); } else { CP_WAIT0(); }
        __syncthreads();
        const uint32_t st = sbase + FSTG_OFF + (it & 1) * FSTG_BYTES;

        // ---- S = Q K^T (split: QhKh + QhKl + QlKh), warp tile m16 x n64, k64
        float sacc[8][4];
        #pragma unroll
        for (int t = 0; t < 8; t++)
            #pragma unroll
            for (int c = 0; c < 4; c++) sacc[t][c] = 0.0f;

        #pragma unroll
        for (int kk = 0; kk < 4; kk++) {
            const uint32_t koff = kk * 32;
            uint32_t ah[4], al[4];
            ldsm_x4(ah, sbase + a_lane + koff);
            ldsm_x4(al, sbase + FQLO_OFF + a_lane + koff);
            uint32_t bh[4][4], bl[4][4];
            #pragma unroll
            for (int j = 0; j < 4; j++) {
                ldsm_x4(bh[j], st + b_lane + j * (16 * FRS * 2) + koff);
                ldsm_x4(bl[j], st + FKV_BYTES + b_lane + j * (16 * FRS * 2) + koff);
            }
            #pragma unroll
            for (int t = 0; t < 8; t++) {
                const uint32_t* bhp = &bh[t >> 1][(t & 1) * 2];
                const uint32_t* blp = &bl[t >> 1][(t & 1) * 2];
                mma16816(sacc[t], ah, bhp);
                mma16816(sacc[t], ah, blp);
                mma16816(sacc[t], al, bhp);
            }
        }

        // ---- online softmax (rows owned by quad: lanes sharing lane>>2)
        const float scale = 0.125f;
        float mx0 = -INFINITY, mx1 = -INFINITY;
        #pragma unroll
        for (int t = 0; t < 8; t++) {
            #pragma unroll
            for (int c = 0; c < 4; c++) sacc[t][c] *= scale;
            mx0 = fmaxf(mx0, fmaxf(sacc[t][0], sacc[t][1]));
            mx1 = fmaxf(mx1, fmaxf(sacc[t][2], sacc[t][3]));
        }
        mx0 = fmaxf(mx0, __shfl_xor_sync(0xffffffffu, mx0, 1));
        mx0 = fmaxf(mx0, __shfl_xor_sync(0xffffffffu, mx0, 2));
        mx1 = fmaxf(mx1, __shfl_xor_sync(0xffffffffu, mx1, 1));
        mx1 = fmaxf(mx1, __shfl_xor_sync(0xffffffffu, mx1, 2));
        const float mn0 = fmaxf(m0, mx0), mn1 = fmaxf(m1, mx1);
        const float corr0 = __expf(m0 - mn0), corr1 = __expf(m1 - mn1);
        m0 = mn0; m1 = mn1;

        float sum0 = 0.0f, sum1 = 0.0f;
        uint32_t ph[8][2], pl[8][2];
        #pragma unroll
        for (int t = 0; t < 8; t++) {
            float p0 = __expf(sacc[t][0] - mn0), p1 = __expf(sacc[t][1] - mn0);
            float p2 = __expf(sacc[t][2] - mn1), p3 = __expf(sacc[t][3] - mn1);
            sum0 += p0 + p1; sum1 += p2 + p3;
            uint32_t h0 = packbf2(p0, p1), h1 = packbf2(p2, p3);
            float f0, f1, f2, f3;
            unpackbf2(h0, f0, f1); unpackbf2(h1, f2, f3);
            ph[t][0] = h0; ph[t][1] = h1;
            pl[t][0] = packbf2(p0 - f0, p1 - f1);
            pl[t][1] = packbf2(p2 - f2, p3 - f3);
        }
        sum0 += __shfl_xor_sync(0xffffffffu, sum0, 1);
        sum0 += __shfl_xor_sync(0xffffffffu, sum0, 2);
        sum1 += __shfl_xor_sync(0xffffffffu, sum1, 1);
        sum1 += __shfl_xor_sync(0xffffffffu, sum1, 2);
        l0 = l0 * corr0 + sum0;
        l1 = l1 * corr1 + sum1;
        #pragma unroll
        for (int t = 0; t < 8; t++) {
            oacc[t][0] *= corr0; oacc[t][1] *= corr0;
            oacc[t][2] *= corr1; oacc[t][3] *= corr1;
        }

        // ---- O += P V (split: PhVh + PhVl + PlVh); k = keys (4 x16 steps)
        #pragma unroll
        for (int j = 0; j < 4; j++) {
            uint32_t ahh[4] = { ph[2 * j][0], ph[2 * j][1], ph[2 * j + 1][0], ph[2 * j + 1][1] };
            uint32_t alo[4] = { pl[2 * j][0], pl[2 * j][1], pl[2 * j + 1][0], pl[2 * j + 1][1] };
            #pragma unroll
            for (int nb = 0; nb < 4; nb++) {
                uint32_t vaddr = st + 2 * FKV_BYTES + v_lane + j * (16 * FRS * 2) + nb * 32;
                uint32_t vh[4], vl[4];
                ldsm_x4_t(vh, vaddr);
                ldsm_x4_t(vl, vaddr + FKV_BYTES);
                mma16816(oacc[2 * nb],     ahh, &vh[0]);
                mma16816(oacc[2 * nb],     ahh, &vl[0]);
                mma16816(oacc[2 * nb],     alo, &vh[0]);
                mma16816(oacc[2 * nb + 1], ahh, &vh[2]);
                mma16816(oacc[2 * nb + 1], ahh, &vl[2]);
                mma16816(oacc[2 * nb + 1], alo, &vh[2]);
            }
        }

        __syncthreads();
        if (it + 2 < FNIT)
            flash_load_kv(st, tid, Khi, Klo, Vhi, Vlo, (it + 2) * 64, kcol0);
    }

    // ---- epilogue: normalize, split to bf16 hi/lo, store
    const float inv0 = 1.0f / l0, inv1 = 1.0f / l1;
    const int row0 = qrow0 + wid * 16 + (lane >> 2);
    const int row1 = row0 + 8;
    #pragma unroll
    for (int t = 0; t < 8; t++) {
        const int col = qcol0 + t * 8 + (lane & 3) * 2;
        float u0 = oacc[t][0] * inv0, u1 = oacc[t][1] * inv0;
        float u2 = oacc[t][2] * inv1, u3 = oacc[t][3] * inv1;
        uint32_t h0 = packbf2(u0, u1), h1 = packbf2(u2, u3);
        float f0, f1, f2, f3;
        unpackbf2(h0, f0, f1); unpackbf2(h1, f2, f3);
        *(uint32_t*)&Ohi[(size_t)row0 * DMODEL + col] = h0;
        *(uint32_t*)&Ohi[(size_t)row1 * DMODEL + col] = h1;
        *(uint32_t*)&Olo[(size_t)row0 * DMODEL + col] = packbf2(u0 - f0, u1 - f1);
        *(uint32_t*)&Olo[(size_t)row1 * DMODEL + col] = packbf2(u2 - f2, u3 - f3);
    }
}

// ============================ kernel_launch =================================
extern "C" void kernel_launch(void* const* d_in, const int* in_sizes, int n_in,
                              void* d_out, int out_size)
{
    const float* x  = (const float*)d_in[0];
    const float* wq = (const float*)d_in[1];
    const float* bq = (const float*)d_in[2];
    const float* wk = (const float*)d_in[3];
    const float* bk = (const float*)d_in[4];
    const float* wv = (const float*)d_in[5];
    const float* bv = (const float*)d_in[6];
    const float* wo = (const float*)d_in[7];
    const float* bo = (const float*)d_in[8];
    float* out = (float*)d_out;

    __nv_bfloat16 *xhi, *xlo, *Qhi, *Qlo, *Khi, *Klo, *Vhi, *Vlo, *Ohi, *Olo;
    __nv_bfloat16 *wqh, *wql, *wkh, *wkl, *wvh, *wvl, *woh, *wol;
    cudaGetSymbolAddress((void**)&xhi, g_xhi);
    cudaGetSymbolAddress((void**)&xlo, g_xlo);
    cudaGetSymbolAddress((void**)&Qhi, g_Qhi);
    cudaGetSymbolAddress((void**)&Qlo, g_Qlo);
    cudaGetSymbolAddress((void**)&Khi, g_Khi);
    cudaGetSymbolAddress((void**)&Klo, g_Klo);
    cudaGetSymbolAddress((void**)&Vhi, g_Vhi);
    cudaGetSymbolAddress((void**)&Vlo, g_Vlo);
    cudaGetSymbolAddress((void**)&Ohi, g_Ohi);
    cudaGetSymbolAddress((void**)&Olo, g_Olo);
    cudaGetSymbolAddress((void**)&wqh, g_wqT_hi);
    cudaGetSymbolAddress((void**)&wql, g_wqT_lo);
    cudaGetSymbolAddress((void**)&wkh, g_wkT_hi);
    cudaGetSymbolAddress((void**)&wkl, g_wkT_lo);
    cudaGetSymbolAddress((void**)&wvh, g_wvT_hi);
    cudaGetSymbolAddress((void**)&wvl, g_wvT_lo);
    cudaGetSymbolAddress((void**)&woh, g_woT_hi);
    cudaGetSymbolAddress((void**)&wol, g_woT_lo);

    cudaFuncSetAttribute(gemm_mma, cudaFuncAttributeMaxDynamicSharedMemorySize, GEMM_SMEM);
    cudaFuncSetAttribute(flash_mma, cudaFuncAttributeMaxDynamicSharedMemorySize, FLASH_SMEM);

    const int nX = SEQ * DMODEL;

    split_kernel<<<nX / (256 * 4), 256>>>(x, xhi, xlo, nX);
    transpose_split<<<dim3(DMODEL / 32, DMODEL / 32), dim3(32, 8)>>>(wq, wqh, wql, DMODEL, DMODEL);
    transpose_split<<<dim3(DGROUP / 32, DMODEL / 32), dim3(32, 8)>>>(wk, wkh, wkl, DMODEL, DGROUP);
    transpose_split<<<dim3(DGROUP / 32, DMODEL / 32), dim3(32, 8)>>>(wv, wvh, wvl, DMODEL, DGROUP);
    transpose_split<<<dim3(DMODEL / 32, DMODEL / 32), dim3(32, 8)>>>(wo, woh, wol, DMODEL, DMODEL);

    gemm_mma<<<dim3(DMODEL / BN, SEQ / BM), 256, GEMM_SMEM>>>(xhi, xlo, wqh, wql, bq, nullptr, Qhi, Qlo, DMODEL, 1);
    gemm_mma<<<dim3(DGROUP / BN, SEQ / BM), 256, GEMM_SMEM>>>(xhi, xlo, wkh, wkl, bk, nullptr, Khi, Klo, DGROUP, 1);
    gemm_mma<<<dim3(DGROUP / BN, SEQ / BM), 256, GEMM_SMEM>>>(xhi, xlo, wvh, wvl, bv, nullptr, Vhi, Vlo, DGROUP, 1);

    flash_mma<<<dim3(SEQ / 128, NHEADS), 256, FLASH_SMEM>>>(Qhi, Qlo, Khi, Klo, Vhi, Vlo, Ohi, Olo);

    gemm_mma<<<dim3(DMODEL / BN, SEQ / BM), 256, GEMM_SMEM>>>(Ohi, Olo, woh, wol, bo, out, nullptr, nullptr, DMODEL, 0);
}

// round 6
// speedup vs baseline: 3.2195x; 1.2289x over previous
#include <cuda_runtime.h>
#include <cuda_bf16.h>
#include <math.h>
#include <stdint.h>

// ============================ problem constants =============================
#define SEQ      2048
#define DMODEL   4096
#define DGROUP   512
#define DH       64
#define NHEADS   64
#define KDIM     4096
#define QKV_N    (DMODEL + 2 * DGROUP)   // 5120
#define KOFF     DMODEL                  // K cols start
#define VOFF     (DMODEL + DGROUP)       // V cols start

// ============================ scratch (device globals) ======================
__device__ __nv_bfloat16 g_xhi[SEQ * DMODEL];
__device__ __nv_bfloat16 g_xlo[SEQ * DMODEL];
__device__ __nv_bfloat16 g_QKVhi[SEQ * QKV_N];
__device__ __nv_bfloat16 g_QKVlo[SEQ * QKV_N];
__device__ __nv_bfloat16 g_Ohi[SEQ * DMODEL];
__device__ __nv_bfloat16 g_Olo[SEQ * DMODEL];
__device__ __nv_bfloat16 g_wqkvT_hi[QKV_N * KDIM];
__device__ __nv_bfloat16 g_wqkvT_lo[QKV_N * KDIM];
__device__ __nv_bfloat16 g_woT_hi[DMODEL * DMODEL];
__device__ __nv_bfloat16 g_woT_lo[DMODEL * DMODEL];
__device__ float g_bqkv[QKV_N];

// ============================ PTX helpers ===================================
__device__ __forceinline__ uint32_t smem_u32(const void* p) {
    uint32_t a;
    asm("{ .reg .u64 t; cvta.to.shared.u64 t, %1; cvt.u32.u64 %0, t; }" : "=r"(a) : "l"(p));
    return a;
}
#define CP_ASYNC16(dst, src) \
    asm volatile("cp.async.cg.shared.global [%0], [%1], 16;" :: "r"(dst), "l"(src) : "memory")
#define CP_COMMIT() asm volatile("cp.async.commit_group;" ::: "memory")
#define CP_WAIT0()  asm volatile("cp.async.wait_group 0;" ::: "memory")
#define CP_WAIT1()  asm volatile("cp.async.wait_group 1;" ::: "memory")

__device__ __forceinline__ void ldsm_x4(uint32_t* r, uint32_t addr) {
    asm volatile("ldmatrix.sync.aligned.m8n8.x4.shared.b16 {%0,%1,%2,%3}, [%4];"
                 : "=r"(r[0]), "=r"(r[1]), "=r"(r[2]), "=r"(r[3]) : "r"(addr));
}
__device__ __forceinline__ void ldsm_x4_t(uint32_t* r, uint32_t addr) {
    asm volatile("ldmatrix.sync.aligned.m8n8.x4.trans.shared.b16 {%0,%1,%2,%3}, [%4];"
                 : "=r"(r[0]), "=r"(r[1]), "=r"(r[2]), "=r"(r[3]) : "r"(addr));
}
__device__ __forceinline__ void mma16816(float* d, const uint32_t* a, const uint32_t* b) {
    asm volatile(
        "mma.sync.aligned.m16n8k16.row.col.f32.bf16.bf16.f32 "
        "{%0,%1,%2,%3}, {%4,%5,%6,%7}, {%8,%9}, {%0,%1,%2,%3};"
        : "+f"(d[0]), "+f"(d[1]), "+f"(d[2]), "+f"(d[3])
        : "r"(a[0]), "r"(a[1]), "r"(a[2]), "r"(a[3]), "r"(b[0]), "r"(b[1]));
}
__device__ __forceinline__ uint32_t packbf2(float lo, float hi) {
    uint32_t r;
    asm("cvt.rn.satfinite.bf16x2.f32 %0, %1, %2;" : "=r"(r) : "f"(hi), "f"(lo));
    return r;
}
__device__ __forceinline__ void unpackbf2(uint32_t v, float& lo, float& hi) {
    __nv_bfloat162 b = *reinterpret_cast<__nv_bfloat162*>(&v);
    lo = __bfloat162float(b.x); hi = __bfloat162float(b.y);
}

// ============================ split-bf16 mma.sync GEMM ======================
#define BM 128
#define BN 128
#define BK 32
#define NIT (KDIM / BK)          // 128
#define RS 40
#define MAT_BYTES (128 * RS * 2)
#define STAGE_BYTES (4 * MAT_BYTES)
#define GEMM_SMEM (2 * STAGE_BYTES)      // 81920 -> 2 CTAs/SM fit in 227KB
#define OFF_AHI 0
#define OFF_ALO (1 * MAT_BYTES)
#define OFF_BHI (2 * MAT_BYTES)
#define OFF_BLO (3 * MAT_BYTES)

__device__ __forceinline__ void gemm_load_stage(
    uint32_t st, int tid,
    const __nv_bfloat16* __restrict__ Ahi, const __nv_bfloat16* __restrict__ Alo,
    const __nv_bfloat16* __restrict__ Bhi, const __nv_bfloat16* __restrict__ Blo,
    int mBase, int nBase, int kt)
{
    const size_t k0 = (size_t)kt * BK;
    #pragma unroll
    for (int i = 0; i < 2; i++) {
        int e = tid + i * 256, r = e >> 2, c = e & 3;
        CP_ASYNC16(st + OFF_AHI + r * 80 + c * 16, Ahi + (size_t)(mBase + r) * KDIM + k0 + c * 8);
    }
    #pragma unroll
    for (int i = 0; i < 2; i++) {
        int e = tid + i * 256, r = e >> 2, c = e & 3;
        CP_ASYNC16(st + OFF_ALO + r * 80 + c * 16, Alo + (size_t)(mBase + r) * KDIM + k0 + c * 8);
    }
    #pragma unroll
    for (int i = 0; i < 2; i++) {
        int e = tid + i * 256, r = e >> 2, c = e & 3;
        CP_ASYNC16(st + OFF_BHI + r * 80 + c * 16, Bhi + (size_t)(nBase + r) * KDIM + k0 + c * 8);
    }
    #pragma unroll
    for (int i = 0; i < 2; i++) {
        int e = tid + i * 256, r = e >> 2, c = e & 3;
        CP_ASYNC16(st + OFF_BLO + r * 80 + c * 16, Blo + (size_t)(nBase + r) * KDIM + k0 + c * 8);
    }
    CP_COMMIT();
}

// mode 0: write fp32 Cf. mode 1: write split bf16 Chi/Clo.
__global__ __launch_bounds__(256, 2)
void gemm_mma(const __nv_bfloat16* __restrict__ Ahi, const __nv_bfloat16* __restrict__ Alo,
              const __nv_bfloat16* __restrict__ Bhi, const __nv_bfloat16* __restrict__ Blo,
              const float* __restrict__ bias, float* __restrict__ Cf,
              __nv_bfloat16* __restrict__ Chi, __nv_bfloat16* __restrict__ Clo,
              int Nglob, int mode)
{
    extern __shared__ char smc[];
    const uint32_t sbase = smem_u32(smc);
    const int tid  = threadIdx.x;
    const int wid  = tid >> 5, lane = tid & 31;
    const int wm   = wid & 3;
    const int wn   = wid >> 2;
    const int mBase = blockIdx.y * BM, nBase = blockIdx.x * BN;

    const uint32_t a_lane =
        (uint32_t)(((wm * 32 + (lane & 15)) * RS + ((lane >> 4) << 3)) * 2);
    const uint32_t b_lane =
        (uint32_t)(((wn * 64 + ((lane >> 4) << 3) + (lane & 7)) * RS + (((lane >> 3) & 1) << 3)) * 2);

    float acc[2][8][4];
    #pragma unroll
    for (int i = 0; i < 2; i++)
        #pragma unroll
        for (int j = 0; j < 8; j++)
            #pragma unroll
            for (int c = 0; c < 4; c++)
                acc[i][j][c] = 0.0f;

    gemm_load_stage(sbase, tid, Ahi, Alo, Bhi, Blo, mBase, nBase, 0);
    gemm_load_stage(sbase + STAGE_BYTES, tid, Ahi, Alo, Bhi, Blo, mBase, nBase, 1);

    for (int it = 0; it < NIT; it++) {
        if (it + 2 < NIT) { CP_WAIT1(); } else { CP_WAIT0(); }
        __syncthreads();
        const uint32_t st = sbase + (it & 1) * STAGE_BYTES;

        #pragma unroll
        for (int kk = 0; kk < 2; kk++) {
            const uint32_t koff = kk * 32;
            uint32_t bh[4][4], bl[4][4];
            #pragma unroll
            for (int j = 0; j < 4; j++) {
                ldsm_x4(bh[j], st + OFF_BHI + b_lane + j * (16 * RS * 2) + koff);
                ldsm_x4(bl[j], st + OFF_BLO + b_lane + j * (16 * RS * 2) + koff);
            }
            #pragma unroll
            for (int i = 0; i < 2; i++) {
                uint32_t ah[4], al[4];
                ldsm_x4(ah, st + OFF_AHI + a_lane + i * (16 * RS * 2) + koff);
                ldsm_x4(al, st + OFF_ALO + a_lane + i * (16 * RS * 2) + koff);
                #pragma unroll
                for (int jj = 0; jj < 8; jj++) {
                    const uint32_t* bhp = &bh[jj >> 1][(jj & 1) * 2];
                    const uint32_t* blp = &bl[jj >> 1][(jj & 1) * 2];
                    mma16816(acc[i][jj], ah, bhp);
                    mma16816(acc[i][jj], ah, blp);
                    mma16816(acc[i][jj], al, bhp);
                }
            }
        }
        __syncthreads();
        if (it + 2 < NIT)
            gemm_load_stage(sbase + (it & 1) * STAGE_BYTES, tid,
                            Ahi, Alo, Bhi, Blo, mBase, nBase, it + 2);
    }

    const int r0 = mBase + wm * 32 + (lane >> 2);
    const int c0 = nBase + wn * 64 + (lane & 3) * 2;
    #pragma unroll
    for (int i = 0; i < 2; i++) {
        #pragma unroll
        for (int jj = 0; jj < 8; jj++) {
            const int col = c0 + jj * 8;
            const float b0 = __ldg(&bias[col]), b1 = __ldg(&bias[col + 1]);
            const int row = r0 + i * 16;
            float u0 = acc[i][jj][0] + b0, u1 = acc[i][jj][1] + b1;
            float u2 = acc[i][jj][2] + b0, u3 = acc[i][jj][3] + b1;
            if (mode == 0) {
                *(float2*)&Cf[(size_t)row * Nglob + col]       = make_float2(u0, u1);
                *(float2*)&Cf[(size_t)(row + 8) * Nglob + col] = make_float2(u2, u3);
            } else {
                uint32_t h0 = packbf2(u0, u1), h1 = packbf2(u2, u3);
                float f0, f1, f2, f3;
                unpackbf2(h0, f0, f1); unpackbf2(h1, f2, f3);
                uint32_t l0 = packbf2(u0 - f0, u1 - f1), l1 = packbf2(u2 - f2, u3 - f3);
                *(uint32_t*)&Chi[(size_t)row * Nglob + col]       = h0;
                *(uint32_t*)&Chi[(size_t)(row + 8) * Nglob + col] = h1;
                *(uint32_t*)&Clo[(size_t)row * Nglob + col]       = l0;
                *(uint32_t*)&Clo[(size_t)(row + 8) * Nglob + col] = l1;
            }
        }
    }
}

// ============================ conversion kernels ============================
__global__ void split_kernel(const float* __restrict__ in,
                             __nv_bfloat16* __restrict__ hi,
                             __nv_bfloat16* __restrict__ lo, int n)
{
    int idx = (blockIdx.x * blockDim.x + threadIdx.x) * 4;
    if (idx >= n) return;
    float4 v = *(const float4*)(in + idx);
    __nv_bfloat16 h0 = __float2bfloat16(v.x), h1 = __float2bfloat16(v.y);
    __nv_bfloat16 h2 = __float2bfloat16(v.z), h3 = __float2bfloat16(v.w);
    __nv_bfloat16 l0 = __float2bfloat16(v.x - __bfloat162float(h0));
    __nv_bfloat16 l1 = __float2bfloat16(v.y - __bfloat162float(h1));
    __nv_bfloat16 l2 = __float2bfloat16(v.z - __bfloat162float(h2));
    __nv_bfloat16 l3 = __float2bfloat16(v.w - __bfloat162float(h3));
    __nv_bfloat162* H = (__nv_bfloat162*)(hi + idx);
    __nv_bfloat162* L = (__nv_bfloat162*)(lo + idx);
    H[0] = {h0, h1}; H[1] = {h2, h3};
    L[0] = {l0, l1}; L[1] = {l2, l3};
}

// w[K, N] (N contiguous) -> t[N, K] (K contiguous), split into hi/lo bf16
__global__ void transpose_split(const float* __restrict__ w,
                                __nv_bfloat16* __restrict__ thi,
                                __nv_bfloat16* __restrict__ tlo, int K, int N)
{
    __shared__ float tile[32][33];
    const int kb = blockIdx.y * 32, nb = blockIdx.x * 32;
    const int tx = threadIdx.x, ty = threadIdx.y;
    #pragma unroll
    for (int j = 0; j < 4; j++) {
        int r = ty + 8 * j;
        tile[r][tx] = w[(size_t)(kb + r) * N + nb + tx];
    }
    __syncthreads();
    #pragma unroll
    for (int j = 0; j < 4; j++) {
        int r = ty + 8 * j;
        float v = tile[tx][r];
        __nv_bfloat16 h = __float2bfloat16(v);
        __nv_bfloat16 l = __float2bfloat16(v - __bfloat162float(h));
        size_t o = (size_t)(nb + r) * K + kb + tx;
        thi[o] = h; tlo[o] = l;
    }
}

// ============================ flash attention (mma.sync, split bf16) ========
// Reads Q/K/V from the fused QKV buffer [SEQ, 5120].
#define FRS 72
#define FQ_BYTES  (128 * FRS * 2)
#define FKV_BYTES (64 * FRS * 2)
#define FSTG_BYTES (4 * FKV_BYTES)
#define FQLO_OFF  FQ_BYTES
#define FSTG_OFF  (2 * FQ_BYTES)
#define FLASH_SMEM (FSTG_OFF + 2 * FSTG_BYTES)
#define FNIT (SEQ / 64)

__device__ __forceinline__ void flash_load_kv(
    uint32_t st, int tid,
    const __nv_bfloat16* __restrict__ QKVhi, const __nv_bfloat16* __restrict__ QKVlo,
    int krow0, int kcol0, int vcol0)
{
    #pragma unroll
    for (int i = 0; i < 2; i++) {
        int e = tid + i * 256, r = e >> 3, c = e & 7;
        CP_ASYNC16(st + r * (FRS * 2) + c * 16, QKVhi + (size_t)(krow0 + r) * QKV_N + kcol0 + c * 8);
    }
    #pragma unroll
    for (int i = 0; i < 2; i++) {
        int e = tid + i * 256, r = e >> 3, c = e & 7;
        CP_ASYNC16(st + FKV_BYTES + r * (FRS * 2) + c * 16, QKVlo + (size_t)(krow0 + r) * QKV_N + kcol0 + c * 8);
    }
    #pragma unroll
    for (int i = 0; i < 2; i++) {
        int e = tid + i * 256, r = e >> 3, c = e & 7;
        CP_ASYNC16(st + 2 * FKV_BYTES + r * (FRS * 2) + c * 16, QKVhi + (size_t)(krow0 + r) * QKV_N + vcol0 + c * 8);
    }
    #pragma unroll
    for (int i = 0; i < 2; i++) {
        int e = tid + i * 256, r = e >> 3, c = e & 7;
        CP_ASYNC16(st + 3 * FKV_BYTES + r * (FRS * 2) + c * 16, QKVlo + (size_t)(krow0 + r) * QKV_N + vcol0 + c * 8);
    }
    CP_COMMIT();
}

__global__ __launch_bounds__(256, 1)
void flash_mma(const __nv_bfloat16* __restrict__ QKVhi, const __nv_bfloat16* __restrict__ QKVlo,
               __nv_bfloat16* __restrict__ Ohi, __nv_bfloat16* __restrict__ Olo)
{
    extern __shared__ char smc[];
    const uint32_t sbase = smem_u32(smc);
    const int tid  = threadIdx.x;
    const int wid  = tid >> 5, lane = tid & 31;
    const int head = blockIdx.y, g = head >> 3;
    const int qrow0 = blockIdx.x * 128;
    const int qcol0 = head * DH;
    const int kcol0 = KOFF + g * DH;
    const int vcol0 = VOFF + g * DH;

    #pragma unroll
    for (int i = 0; i < 4; i++) {
        int e = tid + i * 256, r = e >> 3, c = e & 7;
        CP_ASYNC16(sbase + r * (FRS * 2) + c * 16, QKVhi + (size_t)(qrow0 + r) * QKV_N + qcol0 + c * 8);
    }
    #pragma unroll
    for (int i = 0; i < 4; i++) {
        int e = tid + i * 256, r = e >> 3, c = e & 7;
        CP_ASYNC16(sbase + FQLO_OFF + r * (FRS * 2) + c * 16, QKVlo + (size_t)(qrow0 + r) * QKV_N + qcol0 + c * 8);
    }
    flash_load_kv(sbase + FSTG_OFF, tid, QKVhi, QKVlo, 0, kcol0, vcol0);
    flash_load_kv(sbase + FSTG_OFF + FSTG_BYTES, tid, QKVhi, QKVlo, 64, kcol0, vcol0);

    const uint32_t a_lane =
        (uint32_t)(((wid * 16 + (lane & 15)) * FRS + ((lane >> 4) << 3)) * 2);
    const uint32_t b_lane =
        (uint32_t)(((((lane >> 4) << 3) + (lane & 7)) * FRS + (((lane >> 3) & 1) << 3)) * 2);
    const uint32_t v_lane =
        (uint32_t)(((((lane >> 3) & 1) * 8 + (lane & 7)) * FRS + ((lane >> 4) << 3)) * 2);

    float oacc[8][4];
    #pragma unroll
    for (int t = 0; t < 8; t++)
        #pragma unroll
        for (int c = 0; c < 4; c++) oacc[t][c] = 0.0f;
    float m0 = -INFINITY, m1 = -INFINITY, l0 = 0.0f, l1 = 0.0f;

    for (int it = 0; it < FNIT; it++) {
        if (it < FNIT - 1) { CP_WAIT1(); } else { CP_WAIT0(); }
        __syncthreads();
        const uint32_t st = sbase + FSTG_OFF + (it & 1) * FSTG_BYTES;

        float sacc[8][4];
        #pragma unroll
        for (int t = 0; t < 8; t++)
            #pragma unroll
            for (int c = 0; c < 4; c++) sacc[t][c] = 0.0f;

        #pragma unroll
        for (int kk = 0; kk < 4; kk++) {
            const uint32_t koff = kk * 32;
            uint32_t ah[4], al[4];
            ldsm_x4(ah, sbase + a_lane + koff);
            ldsm_x4(al, sbase + FQLO_OFF + a_lane + koff);
            uint32_t bh[4][4], bl[4][4];
            #pragma unroll
            for (int j = 0; j < 4; j++) {
                ldsm_x4(bh[j], st + b_lane + j * (16 * FRS * 2) + koff);
                ldsm_x4(bl[j], st + FKV_BYTES + b_lane + j * (16 * FRS * 2) + koff);
            }
            #pragma unroll
            for (int t = 0; t < 8; t++) {
                const uint32_t* bhp = &bh[t >> 1][(t & 1) * 2];
                const uint32_t* blp = &bl[t >> 1][(t & 1) * 2];
                mma16816(sacc[t], ah, bhp);
                mma16816(sacc[t], ah, blp);
                mma16816(sacc[t], al, bhp);
            }
        }

        const float scale = 0.125f;
        float mx0 = -INFINITY, mx1 = -INFINITY;
        #pragma unroll
        for (int t = 0; t < 8; t++) {
            #pragma unroll
            for (int c = 0; c < 4; c++) sacc[t][c] *= scale;
            mx0 = fmaxf(mx0, fmaxf(sacc[t][0], sacc[t][1]));
            mx1 = fmaxf(mx1, fmaxf(sacc[t][2], sacc[t][3]));
        }
        mx0 = fmaxf(mx0, __shfl_xor_sync(0xffffffffu, mx0, 1));
        mx0 = fmaxf(mx0, __shfl_xor_sync(0xffffffffu, mx0, 2));
        mx1 = fmaxf(mx1, __shfl_xor_sync(0xffffffffu, mx1, 1));
        mx1 = fmaxf(mx1, __shfl_xor_sync(0xffffffffu, mx1, 2));
        const float mn0 = fmaxf(m0, mx0), mn1 = fmaxf(m1, mx1);
        const float corr0 = __expf(m0 - mn0), corr1 = __expf(m1 - mn1);
        m0 = mn0; m1 = mn1;

        float sum0 = 0.0f, sum1 = 0.0f;
        uint32_t ph[8][2], pl[8][2];
        #pragma unroll
        for (int t = 0; t < 8; t++) {
            float p0 = __expf(sacc[t][0] - mn0), p1 = __expf(sacc[t][1] - mn0);
            float p2 = __expf(sacc[t][2] - mn1), p3 = __expf(sacc[t][3] - mn1);
            sum0 += p0 + p1; sum1 += p2 + p3;
            uint32_t h0 = packbf2(p0, p1), h1 = packbf2(p2, p3);
            float f0, f1, f2, f3;
            unpackbf2(h0, f0, f1); unpackbf2(h1, f2, f3);
            ph[t][0] = h0; ph[t][1] = h1;
            pl[t][0] = packbf2(p0 - f0, p1 - f1);
            pl[t][1] = packbf2(p2 - f2, p3 - f3);
        }
        sum0 += __shfl_xor_sync(0xffffffffu, sum0, 1);
        sum0 += __shfl_xor_sync(0xffffffffu, sum0, 2);
        sum1 += __shfl_xor_sync(0xffffffffu, sum1, 1);
        sum1 += __shfl_xor_sync(0xffffffffu, sum1, 2);
        l0 = l0 * corr0 + sum0;
        l1 = l1 * corr1 + sum1;
        #pragma unroll
        for (int t = 0; t < 8; t++) {
            oacc[t][0] *= corr0; oacc[t][1] *= corr0;
            oacc[t][2] *= corr1; oacc[t][3] *= corr1;
        }

        #pragma unroll
        for (int j = 0; j < 4; j++) {
            uint32_t ahh[4] = { ph[2 * j][0], ph[2 * j][1], ph[2 * j + 1][0], ph[2 * j + 1][1] };
            uint32_t alo[4] = { pl[2 * j][0], pl[2 * j][1], pl[2 * j + 1][0], pl[2 * j + 1][1] };
            #pragma unroll
            for (int nb = 0; nb < 4; nb++) {
                uint32_t vaddr = st + 2 * FKV_BYTES + v_lane + j * (16 * FRS * 2) + nb * 32;
                uint32_t vh[4], vl[4];
                ldsm_x4_t(vh, vaddr);
                ldsm_x4_t(vl, vaddr + FKV_BYTES);
                mma16816(oacc[2 * nb],     ahh, &vh[0]);
                mma16816(oacc[2 * nb],     ahh, &vl[0]);
                mma16816(oacc[2 * nb],     alo, &vh[0]);
                mma16816(oacc[2 * nb + 1], ahh, &vh[2]);
                mma16816(oacc[2 * nb + 1], ahh, &vl[2]);
                mma16816(oacc[2 * nb + 1], alo, &vh[2]);
            }
        }

        __syncthreads();
        if (it + 2 < FNIT)
            flash_load_kv(st, tid, QKVhi, QKVlo, (it + 2) * 64, kcol0, vcol0);
    }

    const float inv0 = 1.0f / l0, inv1 = 1.0f / l1;
    const int row0 = qrow0 + wid * 16 + (lane >> 2);
    const int row1 = row0 + 8;
    #pragma unroll
    for (int t = 0; t < 8; t++) {
        const int col = qcol0 + t * 8 + (lane & 3) * 2;
        float u0 = oacc[t][0] * inv0, u1 = oacc[t][1] * inv0;
        float u2 = oacc[t][2] * inv1, u3 = oacc[t][3] * inv1;
        uint32_t h0 = packbf2(u0, u1), h1 = packbf2(u2, u3);
        float f0, f1, f2, f3;
        unpackbf2(h0, f0, f1); unpackbf2(h1, f2, f3);
        *(uint32_t*)&Ohi[(size_t)row0 * DMODEL + col] = h0;
        *(uint32_t*)&Ohi[(size_t)row1 * DMODEL + col] = h1;
        *(uint32_t*)&Olo[(size_t)row0 * DMODEL + col] = packbf2(u0 - f0, u1 - f1);
        *(uint32_t*)&Olo[(size_t)row1 * DMODEL + col] = packbf2(u2 - f2, u3 - f3);
    }
}

// ============================ kernel_launch =================================
extern "C" void kernel_launch(void* const* d_in, const int* in_sizes, int n_in,
                              void* d_out, int out_size)
{
    const float* x  = (const float*)d_in[0];
    const float* wq = (const float*)d_in[1];
    const float* bq = (const float*)d_in[2];
    const float* wk = (const float*)d_in[3];
    const float* bk = (const float*)d_in[4];
    const float* wv = (const float*)d_in[5];
    const float* bv = (const float*)d_in[6];
    const float* wo = (const float*)d_in[7];
    const float* bo = (const float*)d_in[8];
    float* out = (float*)d_out;

    __nv_bfloat16 *xhi, *xlo, *QKVhi, *QKVlo, *Ohi, *Olo;
    __nv_bfloat16 *wqkvh, *wqkvl, *woh, *wol;
    float* bqkv;
    cudaGetSymbolAddress((void**)&xhi, g_xhi);
    cudaGetSymbolAddress((void**)&xlo, g_xlo);
    cudaGetSymbolAddress((void**)&QKVhi, g_QKVhi);
    cudaGetSymbolAddress((void**)&QKVlo, g_QKVlo);
    cudaGetSymbolAddress((void**)&Ohi, g_Ohi);
    cudaGetSymbolAddress((void**)&Olo, g_Olo);
    cudaGetSymbolAddress((void**)&wqkvh, g_wqkvT_hi);
    cudaGetSymbolAddress((void**)&wqkvl, g_wqkvT_lo);
    cudaGetSymbolAddress((void**)&woh, g_woT_hi);
    cudaGetSymbolAddress((void**)&wol, g_woT_lo);
    cudaGetSymbolAddress((void**)&bqkv, g_bqkv);

    cudaFuncSetAttribute(gemm_mma, cudaFuncAttributeMaxDynamicSharedMemorySize, GEMM_SMEM);
    cudaFuncSetAttribute(flash_mma, cudaFuncAttributeMaxDynamicSharedMemorySize, FLASH_SMEM);

    const int nX = SEQ * DMODEL;

    // fused bias vector [5120] = bq | bk | bv  (async D2D copies, capturable)
    cudaMemcpyAsync(bqkv,        bq, DMODEL * sizeof(float), cudaMemcpyDeviceToDevice);
    cudaMemcpyAsync(bqkv + KOFF, bk, DGROUP * sizeof(float), cudaMemcpyDeviceToDevice);
    cudaMemcpyAsync(bqkv + VOFF, bv, DGROUP * sizeof(float), cudaMemcpyDeviceToDevice);

    split_kernel<<<nX / (256 * 4), 256>>>(x, xhi, xlo, nX);
    // fused transposed weights [5120, 4096]: rows 0..4095 = wq^T, then wk^T, wv^T
    transpose_split<<<dim3(DMODEL / 32, KDIM / 32), dim3(32, 8)>>>(wq, wqkvh, wqkvl, KDIM, DMODEL);
    transpose_split<<<dim3(DGROUP / 32, KDIM / 32), dim3(32, 8)>>>(
        wk, wqkvh + (size_t)KOFF * KDIM, wqkvl + (size_t)KOFF * KDIM, KDIM, DGROUP);
    transpose_split<<<dim3(DGROUP / 32, KDIM / 32), dim3(32, 8)>>>(
        wv, wqkvh + (size_t)VOFF * KDIM, wqkvl + (size_t)VOFF * KDIM, KDIM, DGROUP);
    transpose_split<<<dim3(DMODEL / 32, KDIM / 32), dim3(32, 8)>>>(wo, woh, wol, KDIM, DMODEL);

    // fused QKV projection: [2048, 4096] @ [4096, 5120] -> [2048, 5120]
    gemm_mma<<<dim3(QKV_N / BN, SEQ / BM), 256, GEMM_SMEM>>>(
        xhi, xlo, wqkvh, wqkvl, bqkv, nullptr, QKVhi, QKVlo, QKV_N, 1);

    flash_mma<<<dim3(SEQ / 128, NHEADS), 256, FLASH_SMEM>>>(QKVhi, QKVlo, Ohi, Olo);

    gemm_mma<<<dim3(DMODEL / BN, SEQ / BM), 256, GEMM_SMEM>>>(
        Ohi, Olo, woh, wol, bo, out, nullptr, nullptr, DMODEL, 0);
}

// round 7
// speedup vs baseline: 3.6672x; 1.1391x over previous
#include <cuda_runtime.h>
#include <cuda_fp16.h>
#include <math.h>
#include <stdint.h>

// ============================ problem constants =============================
#define SEQ      2048
#define DMODEL   4096
#define DGROUP   512
#define DH       64
#define NHEADS   64
#define KDIM     4096
#define QKV_N    (DMODEL + 2 * DGROUP)   // 5120
#define KOFF     DMODEL
#define VOFF     (DMODEL + DGROUP)
#define WSCALE   64.0f
#define INVW     0.015625f               // 1/64

// ============================ scratch (device globals) ======================
__device__ __half g_xhi[SEQ * DMODEL];
__device__ __half g_xlo[SEQ * DMODEL];
__device__ __half g_QKVhi[SEQ * QKV_N];
__device__ __half g_QKVlo[SEQ * QKV_N];
__device__ __half g_Of[SEQ * DMODEL];          // attention out, single fp16
__device__ __half g_wqkvT_hi[QKV_N * KDIM];
__device__ __half g_wqkvT_lo[QKV_N * KDIM];
__device__ __half g_woT_hi[DMODEL * KDIM];
__device__ __half g_woT_lo[DMODEL * KDIM];
__device__ float  g_bqkv[QKV_N];

// ============================ PTX helpers ===================================
__device__ __forceinline__ uint32_t smem_u32(const void* p) {
    uint32_t a;
    asm("{ .reg .u64 t; cvta.to.shared.u64 t, %1; cvt.u32.u64 %0, t; }" : "=r"(a) : "l"(p));
    return a;
}
#define CP_ASYNC16(dst, src) \
    asm volatile("cp.async.cg.shared.global [%0], [%1], 16;" :: "r"(dst), "l"(src) : "memory")
#define CP_COMMIT() asm volatile("cp.async.commit_group;" ::: "memory")
#define CP_WAIT0()  asm volatile("cp.async.wait_group 0;" ::: "memory")
#define CP_WAIT1()  asm volatile("cp.async.wait_group 1;" ::: "memory")

__device__ __forceinline__ void ldsm_x4(uint32_t* r, uint32_t addr) {
    asm volatile("ldmatrix.sync.aligned.m8n8.x4.shared.b16 {%0,%1,%2,%3}, [%4];"
                 : "=r"(r[0]), "=r"(r[1]), "=r"(r[2]), "=r"(r[3]) : "r"(addr));
}
__device__ __forceinline__ void ldsm_x4_t(uint32_t* r, uint32_t addr) {
    asm volatile("ldmatrix.sync.aligned.m8n8.x4.trans.shared.b16 {%0,%1,%2,%3}, [%4];"
                 : "=r"(r[0]), "=r"(r[1]), "=r"(r[2]), "=r"(r[3]) : "r"(addr));
}
__device__ __forceinline__ void mma16816(float* d, const uint32_t* a, const uint32_t* b) {
    asm volatile(
        "mma.sync.aligned.m16n8k16.row.col.f32.f16.f16.f32 "
        "{%0,%1,%2,%3}, {%4,%5,%6,%7}, {%8,%9}, {%0,%1,%2,%3};"
        : "+f"(d[0]), "+f"(d[1]), "+f"(d[2]), "+f"(d[3])
        : "r"(a[0]), "r"(a[1]), "r"(a[2]), "r"(a[3]), "r"(b[0]), "r"(b[1]));
}
// pack (lo -> low half, hi -> high half)
__device__ __forceinline__ uint32_t packh2(float lo, float hi) {
    uint32_t r;
    asm("cvt.rn.f16x2.f32 %0, %1, %2;" : "=r"(r) : "f"(hi), "f"(lo));
    return r;
}
__device__ __forceinline__ void unpackh2(uint32_t v, float& lo, float& hi) {
    __half2 h = *reinterpret_cast<__half2*>(&v);
    lo = __half2float(h.x); hi = __half2float(h.y);
}

// ============================ GEMM common ===================================
#define BM 128
#define BN 128
#define BK 32
#define NIT (KDIM / BK)          // 128
#define RS 40
#define MAT_BYTES (128 * RS * 2) // 10240

// -------- gemm3: 3-product split (A hi/lo, B hi/lo), split fp16 out --------
#define STAGE3 (4 * MAT_BYTES)
#define GEMM3_SMEM (2 * STAGE3)          // 81920
#define OFF_AHI 0
#define OFF_ALO (1 * MAT_BYTES)
#define OFF_BHI (2 * MAT_BYTES)
#define OFF_BLO (3 * MAT_BYTES)

__device__ __forceinline__ void g3_load(
    uint32_t st, int tid,
    const __half* __restrict__ Ahi, const __half* __restrict__ Alo,
    const __half* __restrict__ Bhi, const __half* __restrict__ Blo,
    int mBase, int nBase, int kt)
{
    const size_t k0 = (size_t)kt * BK;
    #pragma unroll
    for (int i = 0; i < 2; i++) {
        int e = tid + i * 256, r = e >> 2, c = e & 3;
        CP_ASYNC16(st + OFF_AHI + r * 80 + c * 16, Ahi + (size_t)(mBase + r) * KDIM + k0 + c * 8);
    }
    #pragma unroll
    for (int i = 0; i < 2; i++) {
        int e = tid + i * 256, r = e >> 2, c = e & 3;
        CP_ASYNC16(st + OFF_ALO + r * 80 + c * 16, Alo + (size_t)(mBase + r) * KDIM + k0 + c * 8);
    }
    #pragma unroll
    for (int i = 0; i < 2; i++) {
        int e = tid + i * 256, r = e >> 2, c = e & 3;
        CP_ASYNC16(st + OFF_BHI + r * 80 + c * 16, Bhi + (size_t)(nBase + r) * KDIM + k0 + c * 8);
    }
    #pragma unroll
    for (int i = 0; i < 2; i++) {
        int e = tid + i * 256, r = e >> 2, c = e & 3;
        CP_ASYNC16(st + OFF_BLO + r * 80 + c * 16, Blo + (size_t)(nBase + r) * KDIM + k0 + c * 8);
    }
    CP_COMMIT();
}

__global__ __launch_bounds__(256, 2)
void gemm3(const __half* __restrict__ Ahi, const __half* __restrict__ Alo,
           const __half* __restrict__ Bhi, const __half* __restrict__ Blo,
           const float* __restrict__ bias,
           __half* __restrict__ Chi, __half* __restrict__ Clo, int Nglob)
{
    extern __shared__ char smc[];
    const uint32_t sbase = smem_u32(smc);
    const int tid  = threadIdx.x;
    const int wid  = tid >> 5, lane = tid & 31;
    const int wm   = wid & 3, wn = wid >> 2;
    const int mBase = blockIdx.y * BM, nBase = blockIdx.x * BN;

    const uint32_t a_lane =
        (uint32_t)(((wm * 32 + (lane & 15)) * RS + ((lane >> 4) << 3)) * 2);
    const uint32_t b_lane =
        (uint32_t)(((wn * 64 + ((lane >> 4) << 3) + (lane & 7)) * RS + (((lane >> 3) & 1) << 3)) * 2);

    float acc[2][8][4];
    #pragma unroll
    for (int i = 0; i < 2; i++)
        #pragma unroll
        for (int j = 0; j < 8; j++)
            #pragma unroll
            for (int c = 0; c < 4; c++)
                acc[i][j][c] = 0.0f;

    g3_load(sbase, tid, Ahi, Alo, Bhi, Blo, mBase, nBase, 0);
    g3_load(sbase + STAGE3, tid, Ahi, Alo, Bhi, Blo, mBase, nBase, 1);

    for (int it = 0; it < NIT; it++) {
        if (it + 2 < NIT) { CP_WAIT1(); } else { CP_WAIT0(); }
        __syncthreads();
        const uint32_t st = sbase + (it & 1) * STAGE3;

        #pragma unroll
        for (int kk = 0; kk < 2; kk++) {
            const uint32_t koff = kk * 32;
            uint32_t bh[4][4], bl[4][4];
            #pragma unroll
            for (int j = 0; j < 4; j++) {
                ldsm_x4(bh[j], st + OFF_BHI + b_lane + j * (16 * RS * 2) + koff);
                ldsm_x4(bl[j], st + OFF_BLO + b_lane + j * (16 * RS * 2) + koff);
            }
            #pragma unroll
            for (int i = 0; i < 2; i++) {
                uint32_t ah[4], al[4];
                ldsm_x4(ah, st + OFF_AHI + a_lane + i * (16 * RS * 2) + koff);
                ldsm_x4(al, st + OFF_ALO + a_lane + i * (16 * RS * 2) + koff);
                #pragma unroll
                for (int jj = 0; jj < 8; jj++) {
                    const uint32_t* bhp = &bh[jj >> 1][(jj & 1) * 2];
                    const uint32_t* blp = &bl[jj >> 1][(jj & 1) * 2];
                    mma16816(acc[i][jj], ah, bhp);
                    mma16816(acc[i][jj], ah, blp);
                    mma16816(acc[i][jj], al, bhp);
                }
            }
        }
        __syncthreads();
        if (it + 2 < NIT)
            g3_load(sbase + (it & 1) * STAGE3, tid, Ahi, Alo, Bhi, Blo, mBase, nBase, it + 2);
    }

    const int r0 = mBase + wm * 32 + (lane >> 2);
    const int c0 = nBase + wn * 64 + (lane & 3) * 2;
    #pragma unroll
    for (int i = 0; i < 2; i++) {
        #pragma unroll
        for (int jj = 0; jj < 8; jj++) {
            const int col = c0 + jj * 8;
            const float b0 = __ldg(&bias[col]), b1 = __ldg(&bias[col + 1]);
            const int row = r0 + i * 16;
            float u0 = acc[i][jj][0] * INVW + b0, u1 = acc[i][jj][1] * INVW + b1;
            float u2 = acc[i][jj][2] * INVW + b0, u3 = acc[i][jj][3] * INVW + b1;
            uint32_t h0 = packh2(u0, u1), h1 = packh2(u2, u3);
            float f0, f1, f2, f3;
            unpackh2(h0, f0, f1); unpackh2(h1, f2, f3);
            *(uint32_t*)&Chi[(size_t)row * Nglob + col]       = h0;
            *(uint32_t*)&Chi[(size_t)(row + 8) * Nglob + col] = h1;
            *(uint32_t*)&Clo[(size_t)row * Nglob + col]       = packh2(u0 - f0, u1 - f1);
            *(uint32_t*)&Clo[(size_t)(row + 8) * Nglob + col] = packh2(u2 - f2, u3 - f3);
        }
    }
}

// -------- gemm2: 2-product (A single fp16, B hi/lo), fp32 out + bias -------
#define STAGE2 (3 * MAT_BYTES)           // 30720
#define GEMM2_SMEM (2 * STAGE2)          // 61440
#define OFF2_AF  0
#define OFF2_BHI (1 * MAT_BYTES)
#define OFF2_BLO (2 * MAT_BYTES)

__device__ __forceinline__ void g2_load(
    uint32_t st, int tid,
    const __half* __restrict__ Af,
    const __half* __restrict__ Bhi, const __half* __restrict__ Blo,
    int mBase, int nBase, int kt)
{
    const size_t k0 = (size_t)kt * BK;
    #pragma unroll
    for (int i = 0; i < 2; i++) {
        int e = tid + i * 256, r = e >> 2, c = e & 3;
        CP_ASYNC16(st + OFF2_AF + r * 80 + c * 16, Af + (size_t)(mBase + r) * KDIM + k0 + c * 8);
    }
    #pragma unroll
    for (int i = 0; i < 2; i++) {
        int e = tid + i * 256, r = e >> 2, c = e & 3;
        CP_ASYNC16(st + OFF2_BHI + r * 80 + c * 16, Bhi + (size_t)(nBase + r) * KDIM + k0 + c * 8);
    }
    #pragma unroll
    for (int i = 0; i < 2; i++) {
        int e = tid + i * 256, r = e >> 2, c = e & 3;
        CP_ASYNC16(st + OFF2_BLO + r * 80 + c * 16, Blo + (size_t)(nBase + r) * KDIM + k0 + c * 8);
    }
    CP_COMMIT();
}

__global__ __launch_bounds__(256, 2)
void gemm2(const __half* __restrict__ Af,
           const __half* __restrict__ Bhi, const __half* __restrict__ Blo,
           const float* __restrict__ bias, float* __restrict__ Cf, int Nglob)
{
    extern __shared__ char smc[];
    const uint32_t sbase = smem_u32(smc);
    const int tid  = threadIdx.x;
    const int wid  = tid >> 5, lane = tid & 31;
    const int wm   = wid & 3, wn = wid >> 2;
    const int mBase = blockIdx.y * BM, nBase = blockIdx.x * BN;

    const uint32_t a_lane =
        (uint32_t)(((wm * 32 + (lane & 15)) * RS + ((lane >> 4) << 3)) * 2);
    const uint32_t b_lane =
        (uint32_t)(((wn * 64 + ((lane >> 4) << 3) + (lane & 7)) * RS + (((lane >> 3) & 1) << 3)) * 2);

    float acc[2][8][4];
    #pragma unroll
    for (int i = 0; i < 2; i++)
        #pragma unroll
        for (int j = 0; j < 8; j++)
            #pragma unroll
            for (int c = 0; c < 4; c++)
                acc[i][j][c] = 0.0f;

    g2_load(sbase, tid, Af, Bhi, Blo, mBase, nBase, 0);
    g2_load(sbase + STAGE2, tid, Af, Bhi, Blo, mBase, nBase, 1);

    for (int it = 0; it < NIT; it++) {
        if (it + 2 < NIT) { CP_WAIT1(); } else { CP_WAIT0(); }
        __syncthreads();
        const uint32_t st = sbase + (it & 1) * STAGE2;

        #pragma unroll
        for (int kk = 0; kk < 2; kk++) {
            const uint32_t koff = kk * 32;
            uint32_t bh[4][4], bl[4][4];
            #pragma unroll
            for (int j = 0; j < 4; j++) {
                ldsm_x4(bh[j], st + OFF2_BHI + b_lane + j * (16 * RS * 2) + koff);
                ldsm_x4(bl[j], st + OFF2_BLO + b_lane + j * (16 * RS * 2) + koff);
            }
            #pragma unroll
            for (int i = 0; i < 2; i++) {
                uint32_t af[4];
                ldsm_x4(af, st + OFF2_AF + a_lane + i * (16 * RS * 2) + koff);
                #pragma unroll
                for (int jj = 0; jj < 8; jj++) {
                    mma16816(acc[i][jj], af, &bh[jj >> 1][(jj & 1) * 2]);
                    mma16816(acc[i][jj], af, &bl[jj >> 1][(jj & 1) * 2]);
                }
            }
        }
        __syncthreads();
        if (it + 2 < NIT)
            g2_load(sbase + (it & 1) * STAGE2, tid, Af, Bhi, Blo, mBase, nBase, it + 2);
    }

    const int r0 = mBase + wm * 32 + (lane >> 2);
    const int c0 = nBase + wn * 64 + (lane & 3) * 2;
    #pragma unroll
    for (int i = 0; i < 2; i++) {
        #pragma unroll
        for (int jj = 0; jj < 8; jj++) {
            const int col = c0 + jj * 8;
            const float b0 = __ldg(&bias[col]), b1 = __ldg(&bias[col + 1]);
            const int row = r0 + i * 16;
            *(float2*)&Cf[(size_t)row * Nglob + col] =
                make_float2(acc[i][jj][0] * INVW + b0, acc[i][jj][1] * INVW + b1);
            *(float2*)&Cf[(size_t)(row + 8) * Nglob + col] =
                make_float2(acc[i][jj][2] * INVW + b0, acc[i][jj][3] * INVW + b1);
        }
    }
}

// ============================ conversion kernels ============================
__global__ void split_kernel(const float* __restrict__ in,
                             __half* __restrict__ hi, __half* __restrict__ lo, int n)
{
    int idx = (blockIdx.x * blockDim.x + threadIdx.x) * 4;
    if (idx >= n) return;
    float4 v = *(const float4*)(in + idx);
    __half h0 = __float2half_rn(v.x), h1 = __float2half_rn(v.y);
    __half h2 = __float2half_rn(v.z), h3 = __float2half_rn(v.w);
    __half l0 = __float2half_rn(v.x - __half2float(h0));
    __half l1 = __float2half_rn(v.y - __half2float(h1));
    __half l2 = __float2half_rn(v.z - __half2float(h2));
    __half l3 = __float2half_rn(v.w - __half2float(h3));
    __half2* H = (__half2*)(hi + idx);
    __half2* L = (__half2*)(lo + idx);
    H[0] = {h0, h1}; H[1] = {h2, h3};
    L[0] = {l0, l1}; L[1] = {l2, l3};
}

// w[K, N] -> t[N, K], scaled by 64, split into fp16 hi/lo
__global__ void transpose_split(const float* __restrict__ w,
                                __half* __restrict__ thi, __half* __restrict__ tlo,
                                int K, int N)
{
    __shared__ float tile[32][33];
    const int kb = blockIdx.y * 32, nb = blockIdx.x * 32;
    const int tx = threadIdx.x, ty = threadIdx.y;
    #pragma unroll
    for (int j = 0; j < 4; j++) {
        int r = ty + 8 * j;
        tile[r][tx] = w[(size_t)(kb + r) * N + nb + tx];
    }
    __syncthreads();
    #pragma unroll
    for (int j = 0; j < 4; j++) {
        int r = ty + 8 * j;
        float v = tile[tx][r] * WSCALE;
        __half h = __float2half_rn(v);
        __half l = __float2half_rn(v - __half2float(h));
        size_t o = (size_t)(nb + r) * K + kb + tx;
        thi[o] = h; tlo[o] = l;
    }
}

// ============================ flash attention ===============================
// QK: 3-product split fp16. PV: 2-product (P single fp16, V hi/lo).
#define FRS 72
#define FQ_BYTES  (128 * FRS * 2)
#define FKV_BYTES (64 * FRS * 2)
#define FSTG_BYTES (4 * FKV_BYTES)
#define FQLO_OFF  FQ_BYTES
#define FSTG_OFF  (2 * FQ_BYTES)
#define FLASH_SMEM (FSTG_OFF + 2 * FSTG_BYTES)
#define FNIT (SEQ / 64)

__device__ __forceinline__ void flash_load_kv(
    uint32_t st, int tid,
    const __half* __restrict__ QKVhi, const __half* __restrict__ QKVlo,
    int krow0, int kcol0, int vcol0)
{
    #pragma unroll
    for (int i = 0; i < 2; i++) {
        int e = tid + i * 256, r = e >> 3, c = e & 7;
        CP_ASYNC16(st + r * (FRS * 2) + c * 16, QKVhi + (size_t)(krow0 + r) * QKV_N + kcol0 + c * 8);
    }
    #pragma unroll
    for (int i = 0; i < 2; i++) {
        int e = tid + i * 256, r = e >> 3, c = e & 7;
        CP_ASYNC16(st + FKV_BYTES + r * (FRS * 2) + c * 16, QKVlo + (size_t)(krow0 + r) * QKV_N + kcol0 + c * 8);
    }
    #pragma unroll
    for (int i = 0; i < 2; i++) {
        int e = tid + i * 256, r = e >> 3, c = e & 7;
        CP_ASYNC16(st + 2 * FKV_BYTES + r * (FRS * 2) + c * 16, QKVhi + (size_t)(krow0 + r) * QKV_N + vcol0 + c * 8);
    }
    #pragma unroll
    for (int i = 0; i < 2; i++) {
        int e = tid + i * 256, r = e >> 3, c = e & 7;
        CP_ASYNC16(st + 3 * FKV_BYTES + r * (FRS * 2) + c * 16, QKVlo + (size_t)(krow0 + r) * QKV_N + vcol0 + c * 8);
    }
    CP_COMMIT();
}

__global__ __launch_bounds__(256, 1)
void flash_mma(const __half* __restrict__ QKVhi, const __half* __restrict__ QKVlo,
               __half* __restrict__ Of)
{
    extern __shared__ char smc[];
    const uint32_t sbase = smem_u32(smc);
    const int tid  = threadIdx.x;
    const int wid  = tid >> 5, lane = tid & 31;
    const int head = blockIdx.y, g = head >> 3;
    const int qrow0 = blockIdx.x * 128;
    const int qcol0 = head * DH;
    const int kcol0 = KOFF + g * DH;
    const int vcol0 = VOFF + g * DH;

    #pragma unroll
    for (int i = 0; i < 4; i++) {
        int e = tid + i * 256, r = e >> 3, c = e & 7;
        CP_ASYNC16(sbase + r * (FRS * 2) + c * 16, QKVhi + (size_t)(qrow0 + r) * QKV_N + qcol0 + c * 8);
    }
    #pragma unroll
    for (int i = 0; i < 4; i++) {
        int e = tid + i * 256, r = e >> 3, c = e & 7;
        CP_ASYNC16(sbase + FQLO_OFF + r * (FRS * 2) + c * 16, QKVlo + (size_t)(qrow0 + r) * QKV_N + qcol0 + c * 8);
    }
    flash_load_kv(sbase + FSTG_OFF, tid, QKVhi, QKVlo, 0, kcol0, vcol0);
    flash_load_kv(sbase + FSTG_OFF + FSTG_BYTES, tid, QKVhi, QKVlo, 64, kcol0, vcol0);

    const uint32_t a_lane =
        (uint32_t)(((wid * 16 + (lane & 15)) * FRS + ((lane >> 4) << 3)) * 2);
    const uint32_t b_lane =
        (uint32_t)(((((lane >> 4) << 3) + (lane & 7)) * FRS + (((lane >> 3) & 1) << 3)) * 2);
    const uint32_t v_lane =
        (uint32_t)(((((lane >> 3) & 1) * 8 + (lane & 7)) * FRS + ((lane >> 4) << 3)) * 2);

    float oacc[8][4];
    #pragma unroll
    for (int t = 0; t < 8; t++)
        #pragma unroll
        for (int c = 0; c < 4; c++) oacc[t][c] = 0.0f;
    float m0 = -INFINITY, m1 = -INFINITY, l0 = 0.0f, l1 = 0.0f;

    for (int it = 0; it < FNIT; it++) {
        if (it < FNIT - 1) { CP_WAIT1(); } else { CP_WAIT0(); }
        __syncthreads();
        const uint32_t st = sbase + FSTG_OFF + (it & 1) * FSTG_BYTES;

        float sacc[8][4];
        #pragma unroll
        for (int t = 0; t < 8; t++)
            #pragma unroll
            for (int c = 0; c < 4; c++) sacc[t][c] = 0.0f;

        #pragma unroll
        for (int kk = 0; kk < 4; kk++) {
            const uint32_t koff = kk * 32;
            uint32_t ah[4], al[4];
            ldsm_x4(ah, sbase + a_lane + koff);
            ldsm_x4(al, sbase + FQLO_OFF + a_lane + koff);
            uint32_t bh[4][4], bl[4][4];
            #pragma unroll
            for (int j = 0; j < 4; j++) {
                ldsm_x4(bh[j], st + b_lane + j * (16 * FRS * 2) + koff);
                ldsm_x4(bl[j], st + FKV_BYTES + b_lane + j * (16 * FRS * 2) + koff);
            }
            #pragma unroll
            for (int t = 0; t < 8; t++) {
                const uint32_t* bhp = &bh[t >> 1][(t & 1) * 2];
                const uint32_t* blp = &bl[t >> 1][(t & 1) * 2];
                mma16816(sacc[t], ah, bhp);
                mma16816(sacc[t], ah, blp);
                mma16816(sacc[t], al, bhp);
            }
        }

        const float scale = 0.125f;
        float mx0 = -INFINITY, mx1 = -INFINITY;
        #pragma unroll
        for (int t = 0; t < 8; t++) {
            #pragma unroll
            for (int c = 0; c < 4; c++) sacc[t][c] *= scale;
            mx0 = fmaxf(mx0, fmaxf(sacc[t][0], sacc[t][1]));
            mx1 = fmaxf(mx1, fmaxf(sacc[t][2], sacc[t][3]));
        }
        mx0 = fmaxf(mx0, __shfl_xor_sync(0xffffffffu, mx0, 1));
        mx0 = fmaxf(mx0, __shfl_xor_sync(0xffffffffu, mx0, 2));
        mx1 = fmaxf(mx1, __shfl_xor_sync(0xffffffffu, mx1, 1));
        mx1 = fmaxf(mx1, __shfl_xor_sync(0xffffffffu, mx1, 2));
        const float mn0 = fmaxf(m0, mx0), mn1 = fmaxf(m1, mx1);
        const float corr0 = __expf(m0 - mn0), corr1 = __expf(m1 - mn1);
        m0 = mn0; m1 = mn1;

        float sum0 = 0.0f, sum1 = 0.0f;
        uint32_t pf[8][2];
        #pragma unroll
        for (int t = 0; t < 8; t++) {
            float p0 = __expf(sacc[t][0] - mn0), p1 = __expf(sacc[t][1] - mn0);
            float p2 = __expf(sacc[t][2] - mn1), p3 = __expf(sacc[t][3] - mn1);
            sum0 += p0 + p1; sum1 += p2 + p3;
            pf[t][0] = packh2(p0, p1);
            pf[t][1] = packh2(p2, p3);
        }
        sum0 += __shfl_xor_sync(0xffffffffu, sum0, 1);
        sum0 += __shfl_xor_sync(0xffffffffu, sum0, 2);
        sum1 += __shfl_xor_sync(0xffffffffu, sum1, 1);
        sum1 += __shfl_xor_sync(0xffffffffu, sum1, 2);
        l0 = l0 * corr0 + sum0;
        l1 = l1 * corr1 + sum1;
        #pragma unroll
        for (int t = 0; t < 8; t++) {
            oacc[t][0] *= corr0; oacc[t][1] *= corr0;
            oacc[t][2] *= corr1; oacc[t][3] *= corr1;
        }

        // O += P V : P single fp16, V hi/lo (2 products)
        #pragma unroll
        for (int j = 0; j < 4; j++) {
            uint32_t ap[4] = { pf[2 * j][0], pf[2 * j][1], pf[2 * j + 1][0], pf[2 * j + 1][1] };
            #pragma unroll
            for (int nb = 0; nb < 4; nb++) {
                uint32_t vaddr = st + 2 * FKV_BYTES + v_lane + j * (16 * FRS * 2) + nb * 32;
                uint32_t vh[4], vl[4];
                ldsm_x4_t(vh, vaddr);
                ldsm_x4_t(vl, vaddr + FKV_BYTES);
                mma16816(oacc[2 * nb],     ap, &vh[0]);
                mma16816(oacc[2 * nb],     ap, &vl[0]);
                mma16816(oacc[2 * nb + 1], ap, &vh[2]);
                mma16816(oacc[2 * nb + 1], ap, &vl[2]);
            }
        }

        __syncthreads();
        if (it + 2 < FNIT)
            flash_load_kv(st, tid, QKVhi, QKVlo, (it + 2) * 64, kcol0, vcol0);
    }

    const float inv0 = 1.0f / l0, inv1 = 1.0f / l1;
    const int row0 = qrow0 + wid * 16 + (lane >> 2);
    const int row1 = row0 + 8;
    #pragma unroll
    for (int t = 0; t < 8; t++) {
        const int col = qcol0 + t * 8 + (lane & 3) * 2;
        *(uint32_t*)&Of[(size_t)row0 * DMODEL + col] =
            packh2(oacc[t][0] * inv0, oacc[t][1] * inv0);
        *(uint32_t*)&Of[(size_t)row1 * DMODEL + col] =
            packh2(oacc[t][2] * inv1, oacc[t][3] * inv1);
    }
}

// ============================ kernel_launch =================================
extern "C" void kernel_launch(void* const* d_in, const int* in_sizes, int n_in,
                              void* d_out, int out_size)
{
    const float* x  = (const float*)d_in[0];
    const float* wq = (const float*)d_in[1];
    const float* bq = (const float*)d_in[2];
    const float* wk = (const float*)d_in[3];
    const float* bk = (const float*)d_in[4];
    const float* wv = (const float*)d_in[5];
    const float* bv = (const float*)d_in[6];
    const float* wo = (const float*)d_in[7];
    const float* bo = (const float*)d_in[8];
    float* out = (float*)d_out;

    __half *xhi, *xlo, *QKVhi, *QKVlo, *Of;
    __half *wqkvh, *wqkvl, *woh, *wol;
    float* bqkv;
    cudaGetSymbolAddress((void**)&xhi, g_xhi);
    cudaGetSymbolAddress((void**)&xlo, g_xlo);
    cudaGetSymbolAddress((void**)&QKVhi, g_QKVhi);
    cudaGetSymbolAddress((void**)&QKVlo, g_QKVlo);
    cudaGetSymbolAddress((void**)&Of, g_Of);
    cudaGetSymbolAddress((void**)&wqkvh, g_wqkvT_hi);
    cudaGetSymbolAddress((void**)&wqkvl, g_wqkvT_lo);
    cudaGetSymbolAddress((void**)&woh, g_woT_hi);
    cudaGetSymbolAddress((void**)&wol, g_woT_lo);
    cudaGetSymbolAddress((void**)&bqkv, g_bqkv);

    cudaFuncSetAttribute(gemm3, cudaFuncAttributeMaxDynamicSharedMemorySize, GEMM3_SMEM);
    cudaFuncSetAttribute(gemm2, cudaFuncAttributeMaxDynamicSharedMemorySize, GEMM2_SMEM);
    cudaFuncSetAttribute(flash_mma, cudaFuncAttributeMaxDynamicSharedMemorySize, FLASH_SMEM);

    const int nX = SEQ * DMODEL;

    cudaMemcpyAsync(bqkv,        bq, DMODEL * sizeof(float), cudaMemcpyDeviceToDevice);
    cudaMemcpyAsync(bqkv + KOFF, bk, DGROUP * sizeof(float), cudaMemcpyDeviceToDevice);
    cudaMemcpyAsync(bqkv + VOFF, bv, DGROUP * sizeof(float), cudaMemcpyDeviceToDevice);

    split_kernel<<<nX / (256 * 4), 256>>>(x, xhi, xlo, nX);
    transpose_split<<<dim3(DMODEL / 32, KDIM / 32), dim3(32, 8)>>>(wq, wqkvh, wqkvl, KDIM, DMODEL);
    transpose_split<<<dim3(DGROUP / 32, KDIM / 32), dim3(32, 8)>>>(
        wk, wqkvh + (size_t)KOFF * KDIM, wqkvl + (size_t)KOFF * KDIM, KDIM, DGROUP);
    transpose_split<<<dim3(DGROUP / 32, KDIM / 32), dim3(32, 8)>>>(
        wv, wqkvh + (size_t)VOFF * KDIM, wqkvl + (size_t)VOFF * KDIM, KDIM, DGROUP);
    transpose_split<<<dim3(DMODEL / 32, KDIM / 32), dim3(32, 8)>>>(wo, woh, wol, KDIM, DMODEL);

    // fused QKV projection (3-product): [2048,4096] @ [4096,5120]
    gemm3<<<dim3(QKV_N / BN, SEQ / BM), 256, GEMM3_SMEM>>>(
        xhi, xlo, wqkvh, wqkvl, bqkv, QKVhi, QKVlo, QKV_N);

    flash_mma<<<dim3(SEQ / 128, NHEADS), 256, FLASH_SMEM>>>(QKVhi, QKVlo, Of);

    // O projection (2-product): [2048,4096] @ [4096,4096] -> fp32 out
    gemm2<<<dim3(DMODEL / BN, SEQ / BM), 256, GEMM2_SMEM>>>(
        Of, woh, wol, bo, out, DMODEL);
}

// round 11
// speedup vs baseline: 4.1145x; 1.1220x over previous
#include <cuda_runtime.h>
#include <cuda_fp16.h>
#include <math.h>
#include <stdint.h>

// ============================ problem constants =============================
#define SEQ      2048
#define DMODEL   4096
#define DGROUP   512
#define DH       64
#define NHEADS   64
#define KDIM     4096
#define QKV_N    (DMODEL + 2 * DGROUP)   // 5120
#define KOFF     DMODEL
#define VOFF     (DMODEL + DGROUP)
#define WSCALE   64.0f
#define INVW     0.015625f               // 1/64

// ============================ scratch (device globals) ======================
__device__ __half g_xhi[SEQ * DMODEL];
__device__ __half g_xlo[SEQ * DMODEL];
__device__ __half g_QKVhi[SEQ * QKV_N];
__device__ __half g_QKVlo[SEQ * QKV_N];
__device__ __half g_Of[SEQ * DMODEL];
__device__ __half g_wqkvT_hi[QKV_N * KDIM];
__device__ __half g_wqkvT_lo[QKV_N * KDIM];
__device__ __half g_woT[DMODEL * KDIM];        // single fp16, unscaled
__device__ float  g_bqkv[QKV_N];

// ============================ PTX helpers ===================================
__device__ __forceinline__ uint32_t smem_u32(const void* p) {
    uint32_t a;
    asm("{ .reg .u64 t; cvta.to.shared.u64 t, %1; cvt.u32.u64 %0, t; }" : "=r"(a) : "l"(p));
    return a;
}
#define CP_ASYNC16(dst, src) \
    asm volatile("cp.async.cg.shared.global [%0], [%1], 16;" :: "r"(dst), "l"(src) : "memory")
#define CP_COMMIT() asm volatile("cp.async.commit_group;" ::: "memory")
#define CP_WAIT0()  asm volatile("cp.async.wait_group 0;" ::: "memory")
#define CP_WAIT1()  asm volatile("cp.async.wait_group 1;" ::: "memory")

__device__ __forceinline__ void ldsm_x4(uint32_t* r, uint32_t addr) {
    asm volatile("ldmatrix.sync.aligned.m8n8.x4.shared.b16 {%0,%1,%2,%3}, [%4];"
                 : "=r"(r[0]), "=r"(r[1]), "=r"(r[2]), "=r"(r[3]) : "r"(addr));
}
__device__ __forceinline__ void ldsm_x4_t(uint32_t* r, uint32_t addr) {
    asm volatile("ldmatrix.sync.aligned.m8n8.x4.trans.shared.b16 {%0,%1,%2,%3}, [%4];"
                 : "=r"(r[0]), "=r"(r[1]), "=r"(r[2]), "=r"(r[3]) : "r"(addr));
}
__device__ __forceinline__ void mma16816(float* d, const uint32_t* a, const uint32_t* b) {
    asm volatile(
        "mma.sync.aligned.m16n8k16.row.col.f32.f16.f16.f32 "
        "{%0,%1,%2,%3}, {%4,%5,%6,%7}, {%8,%9}, {%0,%1,%2,%3};"
        : "+f"(d[0]), "+f"(d[1]), "+f"(d[2]), "+f"(d[3])
        : "r"(a[0]), "r"(a[1]), "r"(a[2]), "r"(a[3]), "r"(b[0]), "r"(b[1]));
}
__device__ __forceinline__ uint32_t packh2(float lo, float hi) {
    uint32_t r;
    asm("cvt.rn.f16x2.f32 %0, %1, %2;" : "=r"(r) : "f"(hi), "f"(lo));
    return r;
}
__device__ __forceinline__ void unpackh2(uint32_t v, float& lo, float& hi) {
    __half2 h = *reinterpret_cast<__half2*>(&v);
    lo = __half2float(h.x); hi = __half2float(h.y);
}

// ============================ GEMM common ===================================
#define BM 128
#define BN 128
#define BK 32
#define NIT (KDIM / BK)          // 128
#define RS 40
#define MAT_BYTES (128 * RS * 2) // 10240

// -------- gemm3: 3-product split (A hi/lo, B hi/lo), split fp16 out --------
#define STAGE3 (4 * MAT_BYTES)
#define GEMM3_SMEM (2 * STAGE3)          // 81920
#define OFF_AHI 0
#define OFF_ALO (1 * MAT_BYTES)
#define OFF_BHI (2 * MAT_BYTES)
#define OFF_BLO (3 * MAT_BYTES)

__device__ __forceinline__ void g3_load(
    uint32_t st, int tid,
    const __half* __restrict__ Ahi, const __half* __restrict__ Alo,
    const __half* __restrict__ Bhi, const __half* __restrict__ Blo,
    int mBase, int nBase, int kt)
{
    const size_t k0 = (size_t)kt * BK;
    #pragma unroll
    for (int i = 0; i < 2; i++) {
        int e = tid + i * 256, r = e >> 2, c = e & 3;
        CP_ASYNC16(st + OFF_AHI + r * 80 + c * 16, Ahi + (size_t)(mBase + r) * KDIM + k0 + c * 8);
    }
    #pragma unroll
    for (int i = 0; i < 2; i++) {
        int e = tid + i * 256, r = e >> 2, c = e & 3;
        CP_ASYNC16(st + OFF_ALO + r * 80 + c * 16, Alo + (size_t)(mBase + r) * KDIM + k0 + c * 8);
    }
    #pragma unroll
    for (int i = 0; i < 2; i++) {
        int e = tid + i * 256, r = e >> 2, c = e & 3;
        CP_ASYNC16(st + OFF_BHI + r * 80 + c * 16, Bhi + (size_t)(nBase + r) * KDIM + k0 + c * 8);
    }
    #pragma unroll
    for (int i = 0; i < 2; i++) {
        int e = tid + i * 256, r = e >> 2, c = e & 3;
        CP_ASYNC16(st + OFF_BLO + r * 80 + c * 16, Blo + (size_t)(nBase + r) * KDIM + k0 + c * 8);
    }
    CP_COMMIT();
}

__global__ __launch_bounds__(256, 2)
void gemm3(const __half* __restrict__ Ahi, const __half* __restrict__ Alo,
           const __half* __restrict__ Bhi, const __half* __restrict__ Blo,
           const float* __restrict__ bias,
           __half* __restrict__ Chi, __half* __restrict__ Clo, int Nglob)
{
    extern __shared__ char smc[];
    const uint32_t sbase = smem_u32(smc);
    const int tid  = threadIdx.x;
    const int wid  = tid >> 5, lane = tid & 31;
    const int wm   = wid & 3, wn = wid >> 2;
    const int mBase = blockIdx.y * BM, nBase = blockIdx.x * BN;

    const uint32_t a_lane =
        (uint32_t)(((wm * 32 + (lane & 15)) * RS + ((lane >> 4) << 3)) * 2);
    const uint32_t b_lane =
        (uint32_t)(((wn * 64 + ((lane >> 4) << 3) + (lane & 7)) * RS + (((lane >> 3) & 1) << 3)) * 2);

    float acc[2][8][4];
    #pragma unroll
    for (int i = 0; i < 2; i++)
        #pragma unroll
        for (int j = 0; j < 8; j++)
            #pragma unroll
            for (int c = 0; c < 4; c++)
                acc[i][j][c] = 0.0f;

    g3_load(sbase, tid, Ahi, Alo, Bhi, Blo, mBase, nBase, 0);
    g3_load(sbase + STAGE3, tid, Ahi, Alo, Bhi, Blo, mBase, nBase, 1);

    for (int it = 0; it < NIT; it++) {
        if (it + 2 < NIT) { CP_WAIT1(); } else { CP_WAIT0(); }
        __syncthreads();
        const uint32_t st = sbase + (it & 1) * STAGE3;

        #pragma unroll
        for (int kk = 0; kk < 2; kk++) {
            const uint32_t koff = kk * 32;
            uint32_t bh[4][4], bl[4][4];
            #pragma unroll
            for (int j = 0; j < 4; j++) {
                ldsm_x4(bh[j], st + OFF_BHI + b_lane + j * (16 * RS * 2) + koff);
                ldsm_x4(bl[j], st + OFF_BLO + b_lane + j * (16 * RS * 2) + koff);
            }
            #pragma unroll
            for (int i = 0; i < 2; i++) {
                uint32_t ah[4], al[4];
                ldsm_x4(ah, st + OFF_AHI + a_lane + i * (16 * RS * 2) + koff);
                ldsm_x4(al, st + OFF_ALO + a_lane + i * (16 * RS * 2) + koff);
                #pragma unroll
                for (int jj = 0; jj < 8; jj++) {
                    const uint32_t* bhp = &bh[jj >> 1][(jj & 1) * 2];
                    const uint32_t* blp = &bl[jj >> 1][(jj & 1) * 2];
                    mma16816(acc[i][jj], ah, bhp);
                    mma16816(acc[i][jj], ah, blp);
                    mma16816(acc[i][jj], al, bhp);
                }
            }
        }
        __syncthreads();
        if (it + 2 < NIT)
            g3_load(sbase + (it & 1) * STAGE3, tid, Ahi, Alo, Bhi, Blo, mBase, nBase, it + 2);
    }

    const int r0 = mBase + wm * 32 + (lane >> 2);
    const int c0 = nBase + wn * 64 + (lane & 3) * 2;
    #pragma unroll
    for (int i = 0; i < 2; i++) {
        #pragma unroll
        for (int jj = 0; jj < 8; jj++) {
            const int col = c0 + jj * 8;
            const float b0 = __ldg(&bias[col]), b1 = __ldg(&bias[col + 1]);
            const int row = r0 + i * 16;
            float u0 = acc[i][jj][0] * INVW + b0, u1 = acc[i][jj][1] * INVW + b1;
            float u2 = acc[i][jj][2] * INVW + b0, u3 = acc[i][jj][3] * INVW + b1;
            uint32_t h0 = packh2(u0, u1), h1 = packh2(u2, u3);
            float f0, f1, f2, f3;
            unpackh2(h0, f0, f1); unpackh2(h1, f2, f3);
            *(uint32_t*)&Chi[(size_t)row * Nglob + col]       = h0;
            *(uint32_t*)&Chi[(size_t)(row + 8) * Nglob + col] = h1;
            *(uint32_t*)&Clo[(size_t)row * Nglob + col]       = packh2(u0 - f0, u1 - f1);
            *(uint32_t*)&Clo[(size_t)(row + 8) * Nglob + col] = packh2(u2 - f2, u3 - f3);
        }
    }
}

// -------- gemm1: plain fp16 GEMM (A single, B single), fp32 out + bias -----
#define STAGE1 (2 * MAT_BYTES)           // 20480
#define GEMM1_SMEM (2 * STAGE1)          // 40960
#define OFF1_AF 0
#define OFF1_BF (1 * MAT_BYTES)

__device__ __forceinline__ void g1_load(
    uint32_t st, int tid,
    const __half* __restrict__ Af, const __half* __restrict__ Bf,
    int mBase, int nBase, int kt)
{
    const size_t k0 = (size_t)kt * BK;
    #pragma unroll
    for (int i = 0; i < 2; i++) {
        int e = tid + i * 256, r = e >> 2, c = e & 3;
        CP_ASYNC16(st + OFF1_AF + r * 80 + c * 16, Af + (size_t)(mBase + r) * KDIM + k0 + c * 8);
    }
    #pragma unroll
    for (int i = 0; i < 2; i++) {
        int e = tid + i * 256, r = e >> 2, c = e & 3;
        CP_ASYNC16(st + OFF1_BF + r * 80 + c * 16, Bf + (size_t)(nBase + r) * KDIM + k0 + c * 8);
    }
    CP_COMMIT();
}

__global__ __launch_bounds__(256, 2)
void gemm1(const __half* __restrict__ Af, const __half* __restrict__ Bf,
           const float* __restrict__ bias, float* __restrict__ Cf, int Nglob)
{
    extern __shared__ char smc[];
    const uint32_t sbase = smem_u32(smc);
    const int tid  = threadIdx.x;
    const int wid  = tid >> 5, lane = tid & 31;
    const int wm   = wid & 3, wn = wid >> 2;
    const int mBase = blockIdx.y * BM, nBase = blockIdx.x * BN;

    const uint32_t a_lane =
        (uint32_t)(((wm * 32 + (lane & 15)) * RS + ((lane >> 4) << 3)) * 2);
    const uint32_t b_lane =
        (uint32_t)(((wn * 64 + ((lane >> 4) << 3) + (lane & 7)) * RS + (((lane >> 3) & 1) << 3)) * 2);

    float acc[2][8][4];
    #pragma unroll
    for (int i = 0; i < 2; i++)
        #pragma unroll
        for (int j = 0; j < 8; j++)
            #pragma unroll
            for (int c = 0; c < 4; c++)
                acc[i][j][c] = 0.0f;

    g1_load(sbase, tid, Af, Bf, mBase, nBase, 0);
    g1_load(sbase + STAGE1, tid, Af, Bf, mBase, nBase, 1);

    for (int it = 0; it < NIT; it++) {
        if (it + 2 < NIT) { CP_WAIT1(); } else { CP_WAIT0(); }
        __syncthreads();
        const uint32_t st = sbase + (it & 1) * STAGE1;

        #pragma unroll
        for (int kk = 0; kk < 2; kk++) {
            const uint32_t koff = kk * 32;
            uint32_t bf[4][4];
            #pragma unroll
            for (int j = 0; j < 4; j++)
                ldsm_x4(bf[j], st + OFF1_BF + b_lane + j * (16 * RS * 2) + koff);
            #pragma unroll
            for (int i = 0; i < 2; i++) {
                uint32_t af[4];
                ldsm_x4(af, st + OFF1_AF + a_lane + i * (16 * RS * 2) + koff);
                #pragma unroll
                for (int jj = 0; jj < 8; jj++)
                    mma16816(acc[i][jj], af, &bf[jj >> 1][(jj & 1) * 2]);
            }
        }
        __syncthreads();
        if (it + 2 < NIT)
            g1_load(sbase + (it & 1) * STAGE1, tid, Af, Bf, mBase, nBase, it + 2);
    }

    const int r0 = mBase + wm * 32 + (lane >> 2);
    const int c0 = nBase + wn * 64 + (lane & 3) * 2;
    #pragma unroll
    for (int i = 0; i < 2; i++) {
        #pragma unroll
        for (int jj = 0; jj < 8; jj++) {
            const int col = c0 + jj * 8;
            const float b0 = __ldg(&bias[col]), b1 = __ldg(&bias[col + 1]);
            const int row = r0 + i * 16;
            *(float2*)&Cf[(size_t)row * Nglob + col] =
                make_float2(acc[i][jj][0] + b0, acc[i][jj][1] + b1);
            *(float2*)&Cf[(size_t)(row + 8) * Nglob + col] =
                make_float2(acc[i][jj][2] + b0, acc[i][jj][3] + b1);
        }
    }
}

// ============================ conversion kernels ============================
__global__ void split_kernel(const float* __restrict__ in,
                             __half* __restrict__ hi, __half* __restrict__ lo, int n)
{
    int idx = (blockIdx.x * blockDim.x + threadIdx.x) * 4;
    if (idx >= n) return;
    float4 v = *(const float4*)(in + idx);
    __half h0 = __float2half_rn(v.x), h1 = __float2half_rn(v.y);
    __half h2 = __float2half_rn(v.z), h3 = __float2half_rn(v.w);
    __half l0 = __float2half_rn(v.x - __half2float(h0));
    __half l1 = __float2half_rn(v.y - __half2float(h1));
    __half l2 = __float2half_rn(v.z - __half2float(h2));
    __half l3 = __float2half_rn(v.w - __half2float(h3));
    __half2* H = (__half2*)(hi + idx);
    __half2* L = (__half2*)(lo + idx);
    H[0] = {h0, h1}; H[1] = {h2, h3};
    L[0] = {l0, l1}; L[1] = {l2, l3};
}

// w[K, N] -> t[N, K], scaled by 64, split into fp16 hi/lo
__global__ void transpose_split(const float* __restrict__ w,
                                __half* __restrict__ thi, __half* __restrict__ tlo,
                                int K, int N)
{
    __shared__ float tile[32][33];
    const int kb = blockIdx.y * 32, nb = blockIdx.x * 32;
    const int tx = threadIdx.x, ty = threadIdx.y;
    #pragma unroll
    for (int j = 0; j < 4; j++) {
        int r = ty + 8 * j;
        tile[r][tx] = w[(size_t)(kb + r) * N + nb + tx];
    }
    __syncthreads();
    #pragma unroll
    for (int j = 0; j < 4; j++) {
        int r = ty + 8 * j;
        float v = tile[tx][r] * WSCALE;
        __half h = __float2half_rn(v);
        __half l = __float2half_rn(v - __half2float(h));
        size_t o = (size_t)(nb + r) * K + kb + tx;
        thi[o] = h; tlo[o] = l;
    }
}

// w[K, N] -> t[N, K], single fp16 (unscaled)
__global__ void transpose_half(const float* __restrict__ w,
                               __half* __restrict__ t, int K, int N)
{
    __shared__ float tile[32][33];
    const int kb = blockIdx.y * 32, nb = blockIdx.x * 32;
    const int tx = threadIdx.x, ty = threadIdx.y;
    #pragma unroll
    for (int j = 0; j < 4; j++) {
        int r = ty + 8 * j;
        tile[r][tx] = w[(size_t)(kb + r) * N + nb + tx];
    }
    __syncthreads();
    #pragma unroll
    for (int j = 0; j < 4; j++) {
        int r = ty + 8 * j;
        t[(size_t)(nb + r) * K + kb + tx] = __float2half_rn(tile[tx][r]);
    }
}

// ============================ flash attention ===============================
// QK: 3-product split fp16. PV: 2-product (P fp16, V hi/lo) — R7-proven form.
#define FRS 72
#define FQ_BYTES  (128 * FRS * 2)
#define FKV_BYTES (64 * FRS * 2)
#define FSTG_BYTES (4 * FKV_BYTES)       // Khi, Klo, Vhi, Vlo
#define FQLO_OFF  FQ_BYTES
#define FSTG_OFF  (2 * FQ_BYTES)
#define FLASH_SMEM (FSTG_OFF + 2 * FSTG_BYTES)   // 110592
#define FNIT (SEQ / 64)

__device__ __forceinline__ void flash_load_kv(
    uint32_t st, int tid,
    const __half* __restrict__ QKVhi, const __half* __restrict__ QKVlo,
    int krow0, int kcol0, int vcol0)
{
    #pragma unroll
    for (int i = 0; i < 2; i++) {
        int e = tid + i * 256, r = e >> 3, c = e & 7;
        CP_ASYNC16(st + r * (FRS * 2) + c * 16, QKVhi + (size_t)(krow0 + r) * QKV_N + kcol0 + c * 8);
    }
    #pragma unroll
    for (int i = 0; i < 2; i++) {
        int e = tid + i * 256, r = e >> 3, c = e & 7;
        CP_ASYNC16(st + FKV_BYTES + r * (FRS * 2) + c * 16, QKVlo + (size_t)(krow0 + r) * QKV_N + kcol0 + c * 8);
    }
    #pragma unroll
    for (int i = 0; i < 2; i++) {
        int e = tid + i * 256, r = e >> 3, c = e & 7;
        CP_ASYNC16(st + 2 * FKV_BYTES + r * (FRS * 2) + c * 16, QKVhi + (size_t)(krow0 + r) * QKV_N + vcol0 + c * 8);
    }
    #pragma unroll
    for (int i = 0; i < 2; i++) {
        int e = tid + i * 256, r = e >> 3, c = e & 7;
        CP_ASYNC16(st + 3 * FKV_BYTES + r * (FRS * 2) + c * 16, QKVlo + (size_t)(krow0 + r) * QKV_N + vcol0 + c * 8);
    }
    CP_COMMIT();
}

__global__ __launch_bounds__(256, 1)
void flash_mma(const __half* __restrict__ QKVhi, const __half* __restrict__ QKVlo,
               __half* __restrict__ Of)
{
    extern __shared__ char smc[];
    const uint32_t sbase = smem_u32(smc);
    const int tid  = threadIdx.x;
    const int wid  = tid >> 5, lane = tid & 31;
    const int head = blockIdx.y, g = head >> 3;
    const int qrow0 = blockIdx.x * 128;
    const int qcol0 = head * DH;
    const int kcol0 = KOFF + g * DH;
    const int vcol0 = VOFF + g * DH;

    #pragma unroll
    for (int i = 0; i < 4; i++) {
        int e = tid + i * 256, r = e >> 3, c = e & 7;
        CP_ASYNC16(sbase + r * (FRS * 2) + c * 16, QKVhi + (size_t)(qrow0 + r) * QKV_N + qcol0 + c * 8);
    }
    #pragma unroll
    for (int i = 0; i < 4; i++) {
        int e = tid + i * 256, r = e >> 3, c = e & 7;
        CP_ASYNC16(sbase + FQLO_OFF + r * (FRS * 2) + c * 16, QKVlo + (size_t)(qrow0 + r) * QKV_N + qcol0 + c * 8);
    }
    flash_load_kv(sbase + FSTG_OFF, tid, QKVhi, QKVlo, 0, kcol0, vcol0);
    flash_load_kv(sbase + FSTG_OFF + FSTG_BYTES, tid, QKVhi, QKVlo, 64, kcol0, vcol0);

    const uint32_t a_lane =
        (uint32_t)(((wid * 16 + (lane & 15)) * FRS + ((lane >> 4) << 3)) * 2);
    const uint32_t b_lane =
        (uint32_t)(((((lane >> 4) << 3) + (lane & 7)) * FRS + (((lane >> 3) & 1) << 3)) * 2);
    const uint32_t v_lane =
        (uint32_t)(((((lane >> 3) & 1) * 8 + (lane & 7)) * FRS + ((lane >> 4) << 3)) * 2);

    float oacc[8][4];
    #pragma unroll
    for (int t = 0; t < 8; t++)
        #pragma unroll
        for (int c = 0; c < 4; c++) oacc[t][c] = 0.0f;
    float m0 = -INFINITY, m1 = -INFINITY, l0 = 0.0f, l1 = 0.0f;

    for (int it = 0; it < FNIT; it++) {
        if (it < FNIT - 1) { CP_WAIT1(); } else { CP_WAIT0(); }
        __syncthreads();
        const uint32_t st = sbase + FSTG_OFF + (it & 1) * FSTG_BYTES;

        float sacc[8][4];
        #pragma unroll
        for (int t = 0; t < 8; t++)
            #pragma unroll
            for (int c = 0; c < 4; c++) sacc[t][c] = 0.0f;

        #pragma unroll
        for (int kk = 0; kk < 4; kk++) {
            const uint32_t koff = kk * 32;
            uint32_t ah[4], al[4];
            ldsm_x4(ah, sbase + a_lane + koff);
            ldsm_x4(al, sbase + FQLO_OFF + a_lane + koff);
            uint32_t bh[4][4], bl[4][4];
            #pragma unroll
            for (int j = 0; j < 4; j++) {
                ldsm_x4(bh[j], st + b_lane + j * (16 * FRS * 2) + koff);
                ldsm_x4(bl[j], st + FKV_BYTES + b_lane + j * (16 * FRS * 2) + koff);
            }
            #pragma unroll
            for (int t = 0; t < 8; t++) {
                const uint32_t* bhp = &bh[t >> 1][(t & 1) * 2];
                const uint32_t* blp = &bl[t >> 1][(t & 1) * 2];
                mma16816(sacc[t], ah, bhp);
                mma16816(sacc[t], ah, blp);
                mma16816(sacc[t], al, bhp);
            }
        }

        const float scale = 0.125f;
        float mx0 = -INFINITY, mx1 = -INFINITY;
        #pragma unroll
        for (int t = 0; t < 8; t++) {
            #pragma unroll
            for (int c = 0; c < 4; c++) sacc[t][c] *= scale;
            mx0 = fmaxf(mx0, fmaxf(sacc[t][0], sacc[t][1]));
            mx1 = fmaxf(mx1, fmaxf(sacc[t][2], sacc[t][3]));
        }
        mx0 = fmaxf(mx0, __shfl_xor_sync(0xffffffffu, mx0, 1));
        mx0 = fmaxf(mx0, __shfl_xor_sync(0xffffffffu, mx0, 2));
        mx1 = fmaxf(mx1, __shfl_xor_sync(0xffffffffu, mx1, 1));
        mx1 = fmaxf(mx1, __shfl_xor_sync(0xffffffffu, mx1, 2));
        const float mn0 = fmaxf(m0, mx0), mn1 = fmaxf(m1, mx1);
        const float corr0 = __expf(m0 - mn0), corr1 = __expf(m1 - mn1);
        m0 = mn0; m1 = mn1;

        float sum0 = 0.0f, sum1 = 0.0f;
        uint32_t pf[8][2];
        #pragma unroll
        for (int t = 0; t < 8; t++) {
            float p0 = __expf(sacc[t][0] - mn0), p1 = __expf(sacc[t][1] - mn0);
            float p2 = __expf(sacc[t][2] - mn1), p3 = __expf(sacc[t][3] - mn1);
            sum0 += p0 + p1; sum1 += p2 + p3;
            pf[t][0] = packh2(p0, p1);
            pf[t][1] = packh2(p2, p3);
        }
        sum0 += __shfl_xor_sync(0xffffffffu, sum0, 1);
        sum0 += __shfl_xor_sync(0xffffffffu, sum0, 2);
        sum1 += __shfl_xor_sync(0xffffffffu, sum1, 1);
        sum1 += __shfl_xor_sync(0xffffffffu, sum1, 2);
        l0 = l0 * corr0 + sum0;
        l1 = l1 * corr1 + sum1;
        #pragma unroll
        for (int t = 0; t < 8; t++) {
            oacc[t][0] *= corr0; oacc[t][1] *= corr0;
            oacc[t][2] *= corr1; oacc[t][3] *= corr1;
        }

        // O += P V : P single fp16, V hi/lo (2 products)
        #pragma unroll
        for (int j = 0; j < 4; j++) {
            uint32_t ap[4] = { pf[2 * j][0], pf[2 * j][1], pf[2 * j + 1][0], pf[2 * j + 1][1] };
            #pragma unroll
            for (int nb = 0; nb < 4; nb++) {
                uint32_t vaddr = st + 2 * FKV_BYTES + v_lane + j * (16 * FRS * 2) + nb * 32;
                uint32_t vh[4], vl[4];
                ldsm_x4_t(vh, vaddr);
                ldsm_x4_t(vl, vaddr + FKV_BYTES);
                mma16816(oacc[2 * nb],     ap, &vh[0]);
                mma16816(oacc[2 * nb],     ap, &vl[0]);
                mma16816(oacc[2 * nb + 1], ap, &vh[2]);
                mma16816(oacc[2 * nb + 1], ap, &vl[2]);
            }
        }

        __syncthreads();
        if (it + 2 < FNIT)
            flash_load_kv(st, tid, QKVhi, QKVlo, (it + 2) * 64, kcol0, vcol0);
    }

    const float inv0 = 1.0f / l0, inv1 = 1.0f / l1;
    const int row0 = qrow0 + wid * 16 + (lane >> 2);
    const int row1 = row0 + 8;
    #pragma unroll
    for (int t = 0; t < 8; t++) {
        const int col = qcol0 + t * 8 + (lane & 3) * 2;
        *(uint32_t*)&Of[(size_t)row0 * DMODEL + col] =
            packh2(oacc[t][0] * inv0, oacc[t][1] * inv0);
        *(uint32_t*)&Of[(size_t)row1 * DMODEL + col] =
            packh2(oacc[t][2] * inv1, oacc[t][3] * inv1);
    }
}

// ============================ kernel_launch =================================
extern "C" void kernel_launch(void* const* d_in, const int* in_sizes, int n_in,
                              void* d_out, int out_size)
{
    const float* x  = (const float*)d_in[0];
    const float* wq = (const float*)d_in[1];
    const float* bq = (const float*)d_in[2];
    const float* wk = (const float*)d_in[3];
    const float* bk = (const float*)d_in[4];
    const float* wv = (const float*)d_in[5];
    const float* bv = (const float*)d_in[6];
    const float* wo = (const float*)d_in[7];
    const float* bo = (const float*)d_in[8];
    float* out = (float*)d_out;

    __half *xhi, *xlo, *QKVhi, *QKVlo, *Of;
    __half *wqkvh, *wqkvl, *woT;
    float* bqkv;
    cudaGetSymbolAddress((void**)&xhi, g_xhi);
    cudaGetSymbolAddress((void**)&xlo, g_xlo);
    cudaGetSymbolAddress((void**)&QKVhi, g_QKVhi);
    cudaGetSymbolAddress((void**)&QKVlo, g_QKVlo);
    cudaGetSymbolAddress((void**)&Of, g_Of);
    cudaGetSymbolAddress((void**)&wqkvh, g_wqkvT_hi);
    cudaGetSymbolAddress((void**)&wqkvl, g_wqkvT_lo);
    cudaGetSymbolAddress((void**)&woT, g_woT);
    cudaGetSymbolAddress((void**)&bqkv, g_bqkv);

    cudaFuncSetAttribute(gemm3, cudaFuncAttributeMaxDynamicSharedMemorySize, GEMM3_SMEM);
    cudaFuncSetAttribute(gemm1, cudaFuncAttributeMaxDynamicSharedMemorySize, GEMM1_SMEM);
    cudaFuncSetAttribute(flash_mma, cudaFuncAttributeMaxDynamicSharedMemorySize, FLASH_SMEM);

    const int nX = SEQ * DMODEL;

    cudaMemcpyAsync(bqkv,        bq, DMODEL * sizeof(float), cudaMemcpyDeviceToDevice);
    cudaMemcpyAsync(bqkv + KOFF, bk, DGROUP * sizeof(float), cudaMemcpyDeviceToDevice);
    cudaMemcpyAsync(bqkv + VOFF, bv, DGROUP * sizeof(float), cudaMemcpyDeviceToDevice);

    split_kernel<<<nX / (256 * 4), 256>>>(x, xhi, xlo, nX);
    transpose_split<<<dim3(DMODEL / 32, KDIM / 32), dim3(32, 8)>>>(wq, wqkvh, wqkvl, KDIM, DMODEL);
    transpose_split<<<dim3(DGROUP / 32, KDIM / 32), dim3(32, 8)>>>(
        wk, wqkvh + (size_t)KOFF * KDIM, wqkvl + (size_t)KOFF * KDIM, KDIM, DGROUP);
    transpose_split<<<dim3(DGROUP / 32, KDIM / 32), dim3(32, 8)>>>(
        wv, wqkvh + (size_t)VOFF * KDIM, wqkvl + (size_t)VOFF * KDIM, KDIM, DGROUP);
    transpose_half<<<dim3(DMODEL / 32, KDIM / 32), dim3(32, 8)>>>(wo, woT, KDIM, DMODEL);

    // fused QKV projection (3-product): [2048,4096] @ [4096,5120]
    gemm3<<<dim3(QKV_N / BN, SEQ / BM), 256, GEMM3_SMEM>>>(
        xhi, xlo, wqkvh, wqkvl, bqkv, QKVhi, QKVlo, QKV_N);

    flash_mma<<<dim3(SEQ / 128, NHEADS), 256, FLASH_SMEM>>>(QKVhi, QKVlo, Of);

    // O projection (1-product): [2048,4096] @ [4096,4096] -> fp32 out
    gemm1<<<dim3(DMODEL / BN, SEQ / BM), 256, GEMM1_SMEM>>>(Of, woT, bo, out, DMODEL);
}

// round 12
// speedup vs baseline: 4.3099x; 1.0475x over previous
#include <cuda_runtime.h>
#include <cuda_fp16.h>
#include <math.h>
#include <stdint.h>

// ============================ problem constants =============================
#define SEQ      2048
#define DMODEL   4096
#define DGROUP   512
#define DH       64
#define NHEADS   64
#define KDIM     4096
#define QKV_N    (DMODEL + 2 * DGROUP)   // 5120
#define KOFF     DMODEL
#define VOFF     (DMODEL + DGROUP)
#define WSCALE   64.0f
#define INVW     0.015625f               // 1/64

// ============================ scratch (device globals) ======================
__device__ __half g_xhi[SEQ * DMODEL];
__device__ __half g_xlo[SEQ * DMODEL];
__device__ __half g_QKVhi[SEQ * QKV_N];
__device__ __half g_QKVlo[SEQ * QKV_N];
__device__ __half g_Of[SEQ * DMODEL];
__device__ __half g_wqkvT_hi[QKV_N * KDIM];
__device__ __half g_wqkvT_lo[QKV_N * KDIM];
__device__ __half g_woT[DMODEL * KDIM];        // single fp16, unscaled
__device__ float  g_bqkv[QKV_N];

// ============================ PTX helpers ===================================
__device__ __forceinline__ uint32_t smem_u32(const void* p) {
    uint32_t a;
    asm("{ .reg .u64 t; cvta.to.shared.u64 t, %1; cvt.u32.u64 %0, t; }" : "=r"(a) : "l"(p));
    return a;
}
#define CP_ASYNC16(dst, src) \
    asm volatile("cp.async.cg.shared.global [%0], [%1], 16;" :: "r"(dst), "l"(src) : "memory")
#define CP_COMMIT() asm volatile("cp.async.commit_group;" ::: "memory")
#define CP_WAIT0()  asm volatile("cp.async.wait_group 0;" ::: "memory")
#define CP_WAIT1()  asm volatile("cp.async.wait_group 1;" ::: "memory")

__device__ __forceinline__ void ldsm_x4(uint32_t* r, uint32_t addr) {
    asm volatile("ldmatrix.sync.aligned.m8n8.x4.shared.b16 {%0,%1,%2,%3}, [%4];"
                 : "=r"(r[0]), "=r"(r[1]), "=r"(r[2]), "=r"(r[3]) : "r"(addr));
}
__device__ __forceinline__ void ldsm_x4_t(uint32_t* r, uint32_t addr) {
    asm volatile("ldmatrix.sync.aligned.m8n8.x4.trans.shared.b16 {%0,%1,%2,%3}, [%4];"
                 : "=r"(r[0]), "=r"(r[1]), "=r"(r[2]), "=r"(r[3]) : "r"(addr));
}
__device__ __forceinline__ void mma16816(float* d, const uint32_t* a, const uint32_t* b) {
    asm volatile(
        "mma.sync.aligned.m16n8k16.row.col.f32.f16.f16.f32 "
        "{%0,%1,%2,%3}, {%4,%5,%6,%7}, {%8,%9}, {%0,%1,%2,%3};"
        : "+f"(d[0]), "+f"(d[1]), "+f"(d[2]), "+f"(d[3])
        : "r"(a[0]), "r"(a[1]), "r"(a[2]), "r"(a[3]), "r"(b[0]), "r"(b[1]));
}
__device__ __forceinline__ uint32_t packh2(float lo, float hi) {
    uint32_t r;
    asm("cvt.rn.f16x2.f32 %0, %1, %2;" : "=r"(r) : "f"(hi), "f"(lo));
    return r;
}
__device__ __forceinline__ void unpackh2(uint32_t v, float& lo, float& hi) {
    __half2 h = *reinterpret_cast<__half2*>(&v);
    lo = __half2float(h.x); hi = __half2float(h.y);
}

// ============================ GEMM common ===================================
#define BM 128
#define BN 128
#define BK 32
#define NIT (KDIM / BK)          // 128
#define RS 40
#define MAT_BYTES (128 * RS * 2) // 10240

// -------- gemm3: 3-product split (A hi/lo, B hi/lo), split fp16 out --------
#define STAGE3 (4 * MAT_BYTES)
#define GEMM3_SMEM (2 * STAGE3)          // 81920
#define OFF_AHI 0
#define OFF_ALO (1 * MAT_BYTES)
#define OFF_BHI (2 * MAT_BYTES)
#define OFF_BLO (3 * MAT_BYTES)

__device__ __forceinline__ void g3_load(
    uint32_t st, int tid,
    const __half* __restrict__ Ahi, const __half* __restrict__ Alo,
    const __half* __restrict__ Bhi, const __half* __restrict__ Blo,
    int mBase, int nBase, int kt)
{
    const size_t k0 = (size_t)kt * BK;
    #pragma unroll
    for (int i = 0; i < 2; i++) {
        int e = tid + i * 256, r = e >> 2, c = e & 3;
        CP_ASYNC16(st + OFF_AHI + r * 80 + c * 16, Ahi + (size_t)(mBase + r) * KDIM + k0 + c * 8);
    }
    #pragma unroll
    for (int i = 0; i < 2; i++) {
        int e = tid + i * 256, r = e >> 2, c = e & 3;
        CP_ASYNC16(st + OFF_ALO + r * 80 + c * 16, Alo + (size_t)(mBase + r) * KDIM + k0 + c * 8);
    }
    #pragma unroll
    for (int i = 0; i < 2; i++) {
        int e = tid + i * 256, r = e >> 2, c = e & 3;
        CP_ASYNC16(st + OFF_BHI + r * 80 + c * 16, Bhi + (size_t)(nBase + r) * KDIM + k0 + c * 8);
    }
    #pragma unroll
    for (int i = 0; i < 2; i++) {
        int e = tid + i * 256, r = e >> 2, c = e & 3;
        CP_ASYNC16(st + OFF_BLO + r * 80 + c * 16, Blo + (size_t)(nBase + r) * KDIM + k0 + c * 8);
    }
    CP_COMMIT();
}

__global__ __launch_bounds__(256, 2)
void gemm3(const __half* __restrict__ Ahi, const __half* __restrict__ Alo,
           const __half* __restrict__ Bhi, const __half* __restrict__ Blo,
           const float* __restrict__ bias,
           __half* __restrict__ Chi, __half* __restrict__ Clo, int Nglob)
{
    extern __shared__ char smc[];
    const uint32_t sbase = smem_u32(smc);
    const int tid  = threadIdx.x;
    const int wid  = tid >> 5, lane = tid & 31;
    const int wm   = wid & 3, wn = wid >> 2;
    const int mBase = blockIdx.y * BM, nBase = blockIdx.x * BN;

    const uint32_t a_lane =
        (uint32_t)(((wm * 32 + (lane & 15)) * RS + ((lane >> 4) << 3)) * 2);
    const uint32_t b_lane =
        (uint32_t)(((wn * 64 + ((lane >> 4) << 3) + (lane & 7)) * RS + (((lane >> 3) & 1) << 3)) * 2);

    float acc[2][8][4];
    #pragma unroll
    for (int i = 0; i < 2; i++)
        #pragma unroll
        for (int j = 0; j < 8; j++)
            #pragma unroll
            for (int c = 0; c < 4; c++)
                acc[i][j][c] = 0.0f;

    g3_load(sbase, tid, Ahi, Alo, Bhi, Blo, mBase, nBase, 0);
    g3_load(sbase + STAGE3, tid, Ahi, Alo, Bhi, Blo, mBase, nBase, 1);

    for (int it = 0; it < NIT; it++) {
        if (it + 2 < NIT) { CP_WAIT1(); } else { CP_WAIT0(); }
        __syncthreads();
        const uint32_t st = sbase + (it & 1) * STAGE3;

        #pragma unroll
        for (int kk = 0; kk < 2; kk++) {
            const uint32_t koff = kk * 32;
            uint32_t bh[4][4], bl[4][4];
            #pragma unroll
            for (int j = 0; j < 4; j++) {
                ldsm_x4(bh[j], st + OFF_BHI + b_lane + j * (16 * RS * 2) + koff);
                ldsm_x4(bl[j], st + OFF_BLO + b_lane + j * (16 * RS * 2) + koff);
            }
            #pragma unroll
            for (int i = 0; i < 2; i++) {
                uint32_t ah[4], al[4];
                ldsm_x4(ah, st + OFF_AHI + a_lane + i * (16 * RS * 2) + koff);
                ldsm_x4(al, st + OFF_ALO + a_lane + i * (16 * RS * 2) + koff);
                #pragma unroll
                for (int jj = 0; jj < 8; jj++) {
                    const uint32_t* bhp = &bh[jj >> 1][(jj & 1) * 2];
                    const uint32_t* blp = &bl[jj >> 1][(jj & 1) * 2];
                    mma16816(acc[i][jj], ah, bhp);
                    mma16816(acc[i][jj], ah, blp);
                    mma16816(acc[i][jj], al, bhp);
                }
            }
        }
        __syncthreads();
        if (it + 2 < NIT)
            g3_load(sbase + (it & 1) * STAGE3, tid, Ahi, Alo, Bhi, Blo, mBase, nBase, it + 2);
    }

    const int r0 = mBase + wm * 32 + (lane >> 2);
    const int c0 = nBase + wn * 64 + (lane & 3) * 2;
    #pragma unroll
    for (int i = 0; i < 2; i++) {
        #pragma unroll
        for (int jj = 0; jj < 8; jj++) {
            const int col = c0 + jj * 8;
            const float b0 = __ldg(&bias[col]), b1 = __ldg(&bias[col + 1]);
            const int row = r0 + i * 16;
            float u0 = acc[i][jj][0] * INVW + b0, u1 = acc[i][jj][1] * INVW + b1;
            float u2 = acc[i][jj][2] * INVW + b0, u3 = acc[i][jj][3] * INVW + b1;
            uint32_t h0 = packh2(u0, u1), h1 = packh2(u2, u3);
            float f0, f1, f2, f3;
            unpackh2(h0, f0, f1); unpackh2(h1, f2, f3);
            *(uint32_t*)&Chi[(size_t)row * Nglob + col]       = h0;
            *(uint32_t*)&Chi[(size_t)(row + 8) * Nglob + col] = h1;
            *(uint32_t*)&Clo[(size_t)row * Nglob + col]       = packh2(u0 - f0, u1 - f1);
            *(uint32_t*)&Clo[(size_t)(row + 8) * Nglob + col] = packh2(u2 - f2, u3 - f3);
        }
    }
}

// -------- gemm1: plain fp16 GEMM (A single, B single), fp32 out + bias -----
#define STAGE1 (2 * MAT_BYTES)           // 20480
#define GEMM1_SMEM (2 * STAGE1)          // 40960
#define OFF1_AF 0
#define OFF1_BF (1 * MAT_BYTES)

__device__ __forceinline__ void g1_load(
    uint32_t st, int tid,
    const __half* __restrict__ Af, const __half* __restrict__ Bf,
    int mBase, int nBase, int kt)
{
    const size_t k0 = (size_t)kt * BK;
    #pragma unroll
    for (int i = 0; i < 2; i++) {
        int e = tid + i * 256, r = e >> 2, c = e & 3;
        CP_ASYNC16(st + OFF1_AF + r * 80 + c * 16, Af + (size_t)(mBase + r) * KDIM + k0 + c * 8);
    }
    #pragma unroll
    for (int i = 0; i < 2; i++) {
        int e = tid + i * 256, r = e >> 2, c = e & 3;
        CP_ASYNC16(st + OFF1_BF + r * 80 + c * 16, Bf + (size_t)(nBase + r) * KDIM + k0 + c * 8);
    }
    CP_COMMIT();
}

__global__ __launch_bounds__(256, 2)
void gemm1(const __half* __restrict__ Af, const __half* __restrict__ Bf,
           const float* __restrict__ bias, float* __restrict__ Cf, int Nglob)
{
    extern __shared__ char smc[];
    const uint32_t sbase = smem_u32(smc);
    const int tid  = threadIdx.x;
    const int wid  = tid >> 5, lane = tid & 31;
    const int wm   = wid & 3, wn = wid >> 2;
    const int mBase = blockIdx.y * BM, nBase = blockIdx.x * BN;

    const uint32_t a_lane =
        (uint32_t)(((wm * 32 + (lane & 15)) * RS + ((lane >> 4) << 3)) * 2);
    const uint32_t b_lane =
        (uint32_t)(((wn * 64 + ((lane >> 4) << 3) + (lane & 7)) * RS + (((lane >> 3) & 1) << 3)) * 2);

    float acc[2][8][4];
    #pragma unroll
    for (int i = 0; i < 2; i++)
        #pragma unroll
        for (int j = 0; j < 8; j++)
            #pragma unroll
            for (int c = 0; c < 4; c++)
                acc[i][j][c] = 0.0f;

    g1_load(sbase, tid, Af, Bf, mBase, nBase, 0);
    g1_load(sbase + STAGE1, tid, Af, Bf, mBase, nBase, 1);

    for (int it = 0; it < NIT; it++) {
        if (it + 2 < NIT) { CP_WAIT1(); } else { CP_WAIT0(); }
        __syncthreads();
        const uint32_t st = sbase + (it & 1) * STAGE1;

        #pragma unroll
        for (int kk = 0; kk < 2; kk++) {
            const uint32_t koff = kk * 32;
            uint32_t bf[4][4];
            #pragma unroll
            for (int j = 0; j < 4; j++)
                ldsm_x4(bf[j], st + OFF1_BF + b_lane + j * (16 * RS * 2) + koff);
            #pragma unroll
            for (int i = 0; i < 2; i++) {
                uint32_t af[4];
                ldsm_x4(af, st + OFF1_AF + a_lane + i * (16 * RS * 2) + koff);
                #pragma unroll
                for (int jj = 0; jj < 8; jj++)
                    mma16816(acc[i][jj], af, &bf[jj >> 1][(jj & 1) * 2]);
            }
        }
        __syncthreads();
        if (it + 2 < NIT)
            g1_load(sbase + (it & 1) * STAGE1, tid, Af, Bf, mBase, nBase, it + 2);
    }

    const int r0 = mBase + wm * 32 + (lane >> 2);
    const int c0 = nBase + wn * 64 + (lane & 3) * 2;
    #pragma unroll
    for (int i = 0; i < 2; i++) {
        #pragma unroll
        for (int jj = 0; jj < 8; jj++) {
            const int col = c0 + jj * 8;
            const float b0 = __ldg(&bias[col]), b1 = __ldg(&bias[col + 1]);
            const int row = r0 + i * 16;
            *(float2*)&Cf[(size_t)row * Nglob + col] =
                make_float2(acc[i][jj][0] + b0, acc[i][jj][1] + b1);
            *(float2*)&Cf[(size_t)(row + 8) * Nglob + col] =
                make_float2(acc[i][jj][2] + b0, acc[i][jj][3] + b1);
        }
    }
}

// ============================ conversion kernels ============================
__global__ void split_kernel(const float* __restrict__ in,
                             __half* __restrict__ hi, __half* __restrict__ lo, int n)
{
    int idx = (blockIdx.x * blockDim.x + threadIdx.x) * 4;
    if (idx >= n) return;
    float4 v = *(const float4*)(in + idx);
    __half h0 = __float2half_rn(v.x), h1 = __float2half_rn(v.y);
    __half h2 = __float2half_rn(v.z), h3 = __float2half_rn(v.w);
    __half l0 = __float2half_rn(v.x - __half2float(h0));
    __half l1 = __float2half_rn(v.y - __half2float(h1));
    __half l2 = __float2half_rn(v.z - __half2float(h2));
    __half l3 = __float2half_rn(v.w - __half2float(h3));
    __half2* H = (__half2*)(hi + idx);
    __half2* L = (__half2*)(lo + idx);
    H[0] = {h0, h1}; H[1] = {h2, h3};
    L[0] = {l0, l1}; L[1] = {l2, l3};
}

// w[K, N] -> t[N, K], scaled by 64, split into fp16 hi/lo
__global__ void transpose_split(const float* __restrict__ w,
                                __half* __restrict__ thi, __half* __restrict__ tlo,
                                int K, int N)
{
    __shared__ float tile[32][33];
    const int kb = blockIdx.y * 32, nb = blockIdx.x * 32;
    const int tx = threadIdx.x, ty = threadIdx.y;
    #pragma unroll
    for (int j = 0; j < 4; j++) {
        int r = ty + 8 * j;
        tile[r][tx] = w[(size_t)(kb + r) * N + nb + tx];
    }
    __syncthreads();
    #pragma unroll
    for (int j = 0; j < 4; j++) {
        int r = ty + 8 * j;
        float v = tile[tx][r] * WSCALE;
        __half h = __float2half_rn(v);
        __half l = __float2half_rn(v - __half2float(h));
        size_t o = (size_t)(nb + r) * K + kb + tx;
        thi[o] = h; tlo[o] = l;
    }
}

// w[K, N] -> t[N, K], single fp16 (unscaled)
__global__ void transpose_half(const float* __restrict__ w,
                               __half* __restrict__ t, int K, int N)
{
    __shared__ float tile[32][33];
    const int kb = blockIdx.y * 32, nb = blockIdx.x * 32;
    const int tx = threadIdx.x, ty = threadIdx.y;
    #pragma unroll
    for (int j = 0; j < 4; j++) {
        int r = ty + 8 * j;
        tile[r][tx] = w[(size_t)(kb + r) * N + nb + tx];
    }
    __syncthreads();
    #pragma unroll
    for (int j = 0; j < 4; j++) {
        int r = ty + 8 * j;
        t[(size_t)(nb + r) * K + kb + tx] = __float2half_rn(tile[tx][r]);
    }
}

// ============================ flash attention ===============================
// QK: 3-product split fp16. PV: 1-product (P fp16, V-hi only).
#define FRS 72
#define FQ_BYTES  (128 * FRS * 2)
#define FKV_BYTES (64 * FRS * 2)
#define FSTG_BYTES (3 * FKV_BYTES)       // Khi, Klo, Vhi
#define FQLO_OFF  FQ_BYTES
#define FSTG_OFF  (2 * FQ_BYTES)
#define FLASH_SMEM (FSTG_OFF + 2 * FSTG_BYTES)   // 92160
#define FNIT (SEQ / 64)

__device__ __forceinline__ void flash_load_kv(
    uint32_t st, int tid,
    const __half* __restrict__ QKVhi, const __half* __restrict__ QKVlo,
    int krow0, int kcol0, int vcol0)
{
    #pragma unroll
    for (int i = 0; i < 2; i++) {
        int e = tid + i * 256, r = e >> 3, c = e & 7;
        CP_ASYNC16(st + r * (FRS * 2) + c * 16, QKVhi + (size_t)(krow0 + r) * QKV_N + kcol0 + c * 8);
    }
    #pragma unroll
    for (int i = 0; i < 2; i++) {
        int e = tid + i * 256, r = e >> 3, c = e & 7;
        CP_ASYNC16(st + FKV_BYTES + r * (FRS * 2) + c * 16, QKVlo + (size_t)(krow0 + r) * QKV_N + kcol0 + c * 8);
    }
    #pragma unroll
    for (int i = 0; i < 2; i++) {
        int e = tid + i * 256, r = e >> 3, c = e & 7;
        CP_ASYNC16(st + 2 * FKV_BYTES + r * (FRS * 2) + c * 16, QKVhi + (size_t)(krow0 + r) * QKV_N + vcol0 + c * 8);
    }
    CP_COMMIT();
}

__global__ __launch_bounds__(256, 1)
void flash_mma(const __half* __restrict__ QKVhi, const __half* __restrict__ QKVlo,
               __half* __restrict__ Of)
{
    extern __shared__ char smc[];
    const uint32_t sbase = smem_u32(smc);
    const int tid  = threadIdx.x;
    const int wid  = tid >> 5, lane = tid & 31;
    const int head = blockIdx.y, g = head >> 3;
    const int qrow0 = blockIdx.x * 128;
    const int qcol0 = head * DH;
    const int kcol0 = KOFF + g * DH;
    const int vcol0 = VOFF + g * DH;

    #pragma unroll
    for (int i = 0; i < 4; i++) {
        int e = tid + i * 256, r = e >> 3, c = e & 7;
        CP_ASYNC16(sbase + r * (FRS * 2) + c * 16, QKVhi + (size_t)(qrow0 + r) * QKV_N + qcol0 + c * 8);
    }
    #pragma unroll
    for (int i = 0; i < 4; i++) {
        int e = tid + i * 256, r = e >> 3, c = e & 7;
        CP_ASYNC16(sbase + FQLO_OFF + r * (FRS * 2) + c * 16, QKVlo + (size_t)(qrow0 + r) * QKV_N + qcol0 + c * 8);
    }
    flash_load_kv(sbase + FSTG_OFF, tid, QKVhi, QKVlo, 0, kcol0, vcol0);
    flash_load_kv(sbase + FSTG_OFF + FSTG_BYTES, tid, QKVhi, QKVlo, 64, kcol0, vcol0);

    const uint32_t a_lane =
        (uint32_t)(((wid * 16 + (lane & 15)) * FRS + ((lane >> 4) << 3)) * 2);
    const uint32_t b_lane =
        (uint32_t)(((((lane >> 4) << 3) + (lane & 7)) * FRS + (((lane >> 3) & 1) << 3)) * 2);
    const uint32_t v_lane =
        (uint32_t)(((((lane >> 3) & 1) * 8 + (lane & 7)) * FRS + ((lane >> 4) << 3)) * 2);

    float oacc[8][4];
    #pragma unroll
    for (int t = 0; t < 8; t++)
        #pragma unroll
        for (int c = 0; c < 4; c++) oacc[t][c] = 0.0f;
    float m0 = -INFINITY, m1 = -INFINITY, l0 = 0.0f, l1 = 0.0f;

    for (int it = 0; it < FNIT; it++) {
        if (it < FNIT - 1) { CP_WAIT1(); } else { CP_WAIT0(); }
        __syncthreads();
        const uint32_t st = sbase + FSTG_OFF + (it & 1) * FSTG_BYTES;

        float sacc[8][4];
        #pragma unroll
        for (int t = 0; t < 8; t++)
            #pragma unroll
            for (int c = 0; c < 4; c++) sacc[t][c] = 0.0f;

        #pragma unroll
        for (int kk = 0; kk < 4; kk++) {
            const uint32_t koff = kk * 32;
            uint32_t ah[4], al[4];
            ldsm_x4(ah, sbase + a_lane + koff);
            ldsm_x4(al, sbase + FQLO_OFF + a_lane + koff);
            uint32_t bh[4][4], bl[4][4];
            #pragma unroll
            for (int j = 0; j < 4; j++) {
                ldsm_x4(bh[j], st + b_lane + j * (16 * FRS * 2) + koff);
                ldsm_x4(bl[j], st + FKV_BYTES + b_lane + j * (16 * FRS * 2) + koff);
            }
            #pragma unroll
            for (int t = 0; t < 8; t++) {
                const uint32_t* bhp = &bh[t >> 1][(t & 1) * 2];
                const uint32_t* blp = &bl[t >> 1][(t & 1) * 2];
                mma16816(sacc[t], ah, bhp);
                mma16816(sacc[t], ah, blp);
                mma16816(sacc[t], al, bhp);
            }
        }

        const float scale = 0.125f;
        float mx0 = -INFINITY, mx1 = -INFINITY;
        #pragma unroll
        for (int t = 0; t < 8; t++) {
            #pragma unroll
            for (int c = 0; c < 4; c++) sacc[t][c] *= scale;
            mx0 = fmaxf(mx0, fmaxf(sacc[t][0], sacc[t][1]));
            mx1 = fmaxf(mx1, fmaxf(sacc[t][2], sacc[t][3]));
        }
        mx0 = fmaxf(mx0, __shfl_xor_sync(0xffffffffu, mx0, 1));
        mx0 = fmaxf(mx0, __shfl_xor_sync(0xffffffffu, mx0, 2));
        mx1 = fmaxf(mx1, __shfl_xor_sync(0xffffffffu, mx1, 1));
        mx1 = fmaxf(mx1, __shfl_xor_sync(0xffffffffu, mx1, 2));
        const float mn0 = fmaxf(m0, mx0), mn1 = fmaxf(m1, mx1);
        const float corr0 = __expf(m0 - mn0), corr1 = __expf(m1 - mn1);
        m0 = mn0; m1 = mn1;

        float sum0 = 0.0f, sum1 = 0.0f;
        uint32_t pf[8][2];
        #pragma unroll
        for (int t = 0; t < 8; t++) {
            float p0 = __expf(sacc[t][0] - mn0), p1 = __expf(sacc[t][1] - mn0);
            float p2 = __expf(sacc[t][2] - mn1), p3 = __expf(sacc[t][3] - mn1);
            sum0 += p0 + p1; sum1 += p2 + p3;
            pf[t][0] = packh2(p0, p1);
            pf[t][1] = packh2(p2, p3);
        }
        sum0 += __shfl_xor_sync(0xffffffffu, sum0, 1);
        sum0 += __shfl_xor_sync(0xffffffffu, sum0, 2);
        sum1 += __shfl_xor_sync(0xffffffffu, sum1, 1);
        sum1 += __shfl_xor_sync(0xffffffffu, sum1, 2);
        l0 = l0 * corr0 + sum0;
        l1 = l1 * corr1 + sum1;
        #pragma unroll
        for (int t = 0; t < 8; t++) {
            oacc[t][0] *= corr0; oacc[t][1] *= corr0;
            oacc[t][2] *= corr1; oacc[t][3] *= corr1;
        }

        // O += P V : both single fp16 (1 product)
        #pragma unroll
        for (int j = 0; j < 4; j++) {
            uint32_t ap[4] = { pf[2 * j][0], pf[2 * j][1], pf[2 * j + 1][0], pf[2 * j + 1][1] };
            #pragma unroll
            for (int nb = 0; nb < 4; nb++) {
                uint32_t vaddr = st + 2 * FKV_BYTES + v_lane + j * (16 * FRS * 2) + nb * 32;
                uint32_t vh[4];
                ldsm_x4_t(vh, vaddr);
                mma16816(oacc[2 * nb],     ap, &vh[0]);
                mma16816(oacc[2 * nb + 1], ap, &vh[2]);
            }
        }

        __syncthreads();
        if (it + 2 < FNIT)
            flash_load_kv(st, tid, QKVhi, QKVlo, (it + 2) * 64, kcol0, vcol0);
    }

    const float inv0 = 1.0f / l0, inv1 = 1.0f / l1;
    const int row0 = qrow0 + wid * 16 + (lane >> 2);
    const int row1 = row0 + 8;
    #pragma unroll
    for (int t = 0; t < 8; t++) {
        const int col = qcol0 + t * 8 + (lane & 3) * 2;
        *(uint32_t*)&Of[(size_t)row0 * DMODEL + col] =
            packh2(oacc[t][0] * inv0, oacc[t][1] * inv0);
        *(uint32_t*)&Of[(size_t)row1 * DMODEL + col] =
            packh2(oacc[t][2] * inv1, oacc[t][3] * inv1);
    }
}

// ============================ kernel_launch =================================
extern "C" void kernel_launch(void* const* d_in, const int* in_sizes, int n_in,
                              void* d_out, int out_size)
{
    const float* x  = (const float*)d_in[0];
    const float* wq = (const float*)d_in[1];
    const float* bq = (const float*)d_in[2];
    const float* wk = (const float*)d_in[3];
    const float* bk = (const float*)d_in[4];
    const float* wv = (const float*)d_in[5];
    const float* bv = (const float*)d_in[6];
    const float* wo = (const float*)d_in[7];
    const float* bo = (const float*)d_in[8];
    float* out = (float*)d_out;

    __half *xhi, *xlo, *QKVhi, *QKVlo, *Of;
    __half *wqkvh, *wqkvl, *woT;
    float* bqkv;
    cudaGetSymbolAddress((void**)&xhi, g_xhi);
    cudaGetSymbolAddress((void**)&xlo, g_xlo);
    cudaGetSymbolAddress((void**)&QKVhi, g_QKVhi);
    cudaGetSymbolAddress((void**)&QKVlo, g_QKVlo);
    cudaGetSymbolAddress((void**)&Of, g_Of);
    cudaGetSymbolAddress((void**)&wqkvh, g_wqkvT_hi);
    cudaGetSymbolAddress((void**)&wqkvl, g_wqkvT_lo);
    cudaGetSymbolAddress((void**)&woT, g_woT);
    cudaGetSymbolAddress((void**)&bqkv, g_bqkv);

    cudaFuncSetAttribute(gemm3, cudaFuncAttributeMaxDynamicSharedMemorySize, GEMM3_SMEM);
    cudaFuncSetAttribute(gemm1, cudaFuncAttributeMaxDynamicSharedMemorySize, GEMM1_SMEM);
    cudaFuncSetAttribute(flash_mma, cudaFuncAttributeMaxDynamicSharedMemorySize, FLASH_SMEM);

    const int nX = SEQ * DMODEL;

    cudaMemcpyAsync(bqkv,        bq, DMODEL * sizeof(float), cudaMemcpyDeviceToDevice);
    cudaMemcpyAsync(bqkv + KOFF, bk, DGROUP * sizeof(float), cudaMemcpyDeviceToDevice);
    cudaMemcpyAsync(bqkv + VOFF, bv, DGROUP * sizeof(float), cudaMemcpyDeviceToDevice);

    split_kernel<<<nX / (256 * 4), 256>>>(x, xhi, xlo, nX);
    transpose_split<<<dim3(DMODEL / 32, KDIM / 32), dim3(32, 8)>>>(wq, wqkvh, wqkvl, KDIM, DMODEL);
    transpose_split<<<dim3(DGROUP / 32, KDIM / 32), dim3(32, 8)>>>(
        wk, wqkvh + (size_t)KOFF * KDIM, wqkvl + (size_t)KOFF * KDIM, KDIM, DGROUP);
    transpose_split<<<dim3(DGROUP / 32, KDIM / 32), dim3(32, 8)>>>(
        wv, wqkvh + (size_t)VOFF * KDIM, wqkvl + (size_t)VOFF * KDIM, KDIM, DGROUP);
    transpose_half<<<dim3(DMODEL / 32, KDIM / 32), dim3(32, 8)>>>(wo, woT, KDIM, DMODEL);

    // fused QKV projection (3-product): [2048,4096] @ [4096,5120]
    gemm3<<<dim3(QKV_N / BN, SEQ / BM), 256, GEMM3_SMEM>>>(
        xhi, xlo, wqkvh, wqkvl, bqkv, QKVhi, QKVlo, QKV_N);

    flash_mma<<<dim3(SEQ / 128, NHEADS), 256, FLASH_SMEM>>>(QKVhi, QKVlo, Of);

    // O projection (1-product): [2048,4096] @ [4096,4096] -> fp32 out
    gemm1<<<dim3(DMODEL / BN, SEQ / BM), 256, GEMM1_SMEM>>>(Of, woT, bo, out, DMODEL);
}

// round 13
// speedup vs baseline: 4.6688x; 1.0833x over previous
#include <cuda_runtime.h>
#include <cuda_fp16.h>
#include <math.h>
#include <stdint.h>

// ============================ problem constants =============================
#define SEQ      2048
#define DMODEL   4096
#define DGROUP   512
#define DH       64
#define NHEADS   64
#define KDIM     4096
#define QKV_N    (DMODEL + 2 * DGROUP)   // 5120
#define KOFF     DMODEL
#define VOFF     (DMODEL + DGROUP)
#define WSCALE   64.0f
#define INVW     0.015625f               // 1/64

// ============================ scratch (device globals) ======================
__device__ __half g_xhi[SEQ * DMODEL];
__device__ __half g_xlo[SEQ * DMODEL];
__device__ __half g_QKVhi[SEQ * QKV_N];
__device__ __half g_QKVlo[SEQ * QKV_N];
__device__ __half g_Of[SEQ * DMODEL];
__device__ __half g_wqkvT_hi[QKV_N * KDIM];
__device__ __half g_wqkvT_lo[QKV_N * KDIM];
__device__ __half g_woT[DMODEL * KDIM];        // single fp16, unscaled
__device__ float  g_bqkv[QKV_N];

// ============================ PTX helpers ===================================
__device__ __forceinline__ uint32_t smem_u32(const void* p) {
    uint32_t a;
    asm("{ .reg .u64 t; cvta.to.shared.u64 t, %1; cvt.u32.u64 %0, t; }" : "=r"(a) : "l"(p));
    return a;
}
#define CP_ASYNC16(dst, src) \
    asm volatile("cp.async.cg.shared.global [%0], [%1], 16;" :: "r"(dst), "l"(src) : "memory")
#define CP_COMMIT() asm volatile("cp.async.commit_group;" ::: "memory")
#define CP_WAIT0()  asm volatile("cp.async.wait_group 0;" ::: "memory")
#define CP_WAIT1()  asm volatile("cp.async.wait_group 1;" ::: "memory")

__device__ __forceinline__ void ldsm_x4(uint32_t* r, uint32_t addr) {
    asm volatile("ldmatrix.sync.aligned.m8n8.x4.shared.b16 {%0,%1,%2,%3}, [%4];"
                 : "=r"(r[0]), "=r"(r[1]), "=r"(r[2]), "=r"(r[3]) : "r"(addr));
}
__device__ __forceinline__ void ldsm_x4_t(uint32_t* r, uint32_t addr) {
    asm volatile("ldmatrix.sync.aligned.m8n8.x4.trans.shared.b16 {%0,%1,%2,%3}, [%4];"
                 : "=r"(r[0]), "=r"(r[1]), "=r"(r[2]), "=r"(r[3]) : "r"(addr));
}
__device__ __forceinline__ void mma16816(float* d, const uint32_t* a, const uint32_t* b) {
    asm volatile(
        "mma.sync.aligned.m16n8k16.row.col.f32.f16.f16.f32 "
        "{%0,%1,%2,%3}, {%4,%5,%6,%7}, {%8,%9}, {%0,%1,%2,%3};"
        : "+f"(d[0]), "+f"(d[1]), "+f"(d[2]), "+f"(d[3])
        : "r"(a[0]), "r"(a[1]), "r"(a[2]), "r"(a[3]), "r"(b[0]), "r"(b[1]));
}
__device__ __forceinline__ uint32_t packh2(float lo, float hi) {
    uint32_t r;
    asm("cvt.rn.f16x2.f32 %0, %1, %2;" : "=r"(r) : "f"(hi), "f"(lo));
    return r;
}
__device__ __forceinline__ void unpackh2(uint32_t v, float& lo, float& hi) {
    __half2 h = *reinterpret_cast<__half2*>(&v);
    lo = __half2float(h.x); hi = __half2float(h.y);
}

// ============================ GEMM common ===================================
#define BM 128
#define BN 128
#define BK 32
#define NIT (KDIM / BK)          // 128
#define RS 40
#define MAT_BYTES (128 * RS * 2) // 10240

// -------- gemm3: 3-product split (A hi/lo, B hi/lo), split fp16 out --------
#define STAGE3 (4 * MAT_BYTES)
#define GEMM3_SMEM (2 * STAGE3)          // 81920
#define OFF_AHI 0
#define OFF_ALO (1 * MAT_BYTES)
#define OFF_BHI (2 * MAT_BYTES)
#define OFF_BLO (3 * MAT_BYTES)

__device__ __forceinline__ void g3_load(
    uint32_t st, int tid,
    const __half* __restrict__ Ahi, const __half* __restrict__ Alo,
    const __half* __restrict__ Bhi, const __half* __restrict__ Blo,
    int mBase, int nBase, int kt)
{
    const size_t k0 = (size_t)kt * BK;
    #pragma unroll
    for (int i = 0; i < 2; i++) {
        int e = tid + i * 256, r = e >> 2, c = e & 3;
        CP_ASYNC16(st + OFF_AHI + r * 80 + c * 16, Ahi + (size_t)(mBase + r) * KDIM + k0 + c * 8);
    }
    #pragma unroll
    for (int i = 0; i < 2; i++) {
        int e = tid + i * 256, r = e >> 2, c = e & 3;
        CP_ASYNC16(st + OFF_ALO + r * 80 + c * 16, Alo + (size_t)(mBase + r) * KDIM + k0 + c * 8);
    }
    #pragma unroll
    for (int i = 0; i < 2; i++) {
        int e = tid + i * 256, r = e >> 2, c = e & 3;
        CP_ASYNC16(st + OFF_BHI + r * 80 + c * 16, Bhi + (size_t)(nBase + r) * KDIM + k0 + c * 8);
    }
    #pragma unroll
    for (int i = 0; i < 2; i++) {
        int e = tid + i * 256, r = e >> 2, c = e & 3;
        CP_ASYNC16(st + OFF_BLO + r * 80 + c * 16, Blo + (size_t)(nBase + r) * KDIM + k0 + c * 8);
    }
    CP_COMMIT();
}

__global__ __launch_bounds__(256, 2)
void gemm3(const __half* __restrict__ Ahi, const __half* __restrict__ Alo,
           const __half* __restrict__ Bhi, const __half* __restrict__ Blo,
           const float* __restrict__ bias,
           __half* __restrict__ Chi, __half* __restrict__ Clo, int Nglob)
{
    extern __shared__ char smc[];
    const uint32_t sbase = smem_u32(smc);
    const int tid  = threadIdx.x;
    const int wid  = tid >> 5, lane = tid & 31;
    const int wm   = wid & 3, wn = wid >> 2;
    const int mBase = blockIdx.y * BM, nBase = blockIdx.x * BN;

    const uint32_t a_lane =
        (uint32_t)(((wm * 32 + (lane & 15)) * RS + ((lane >> 4) << 3)) * 2);
    const uint32_t b_lane =
        (uint32_t)(((wn * 64 + ((lane >> 4) << 3) + (lane & 7)) * RS + (((lane >> 3) & 1) << 3)) * 2);

    float acc[2][8][4];
    #pragma unroll
    for (int i = 0; i < 2; i++)
        #pragma unroll
        for (int j = 0; j < 8; j++)
            #pragma unroll
            for (int c = 0; c < 4; c++)
                acc[i][j][c] = 0.0f;

    g3_load(sbase, tid, Ahi, Alo, Bhi, Blo, mBase, nBase, 0);
    g3_load(sbase + STAGE3, tid, Ahi, Alo, Bhi, Blo, mBase, nBase, 1);

    for (int it = 0; it < NIT; it++) {
        if (it + 2 < NIT) { CP_WAIT1(); } else { CP_WAIT0(); }
        __syncthreads();
        const uint32_t st = sbase + (it & 1) * STAGE3;

        #pragma unroll
        for (int kk = 0; kk < 2; kk++) {
            const uint32_t koff = kk * 32;
            uint32_t bh[4][4], bl[4][4];
            #pragma unroll
            for (int j = 0; j < 4; j++) {
                ldsm_x4(bh[j], st + OFF_BHI + b_lane + j * (16 * RS * 2) + koff);
                ldsm_x4(bl[j], st + OFF_BLO + b_lane + j * (16 * RS * 2) + koff);
            }
            #pragma unroll
            for (int i = 0; i < 2; i++) {
                uint32_t ah[4], al[4];
                ldsm_x4(ah, st + OFF_AHI + a_lane + i * (16 * RS * 2) + koff);
                ldsm_x4(al, st + OFF_ALO + a_lane + i * (16 * RS * 2) + koff);
                #pragma unroll
                for (int jj = 0; jj < 8; jj++) {
                    const uint32_t* bhp = &bh[jj >> 1][(jj & 1) * 2];
                    const uint32_t* blp = &bl[jj >> 1][(jj & 1) * 2];
                    mma16816(acc[i][jj], ah, bhp);
                    mma16816(acc[i][jj], ah, blp);
                    mma16816(acc[i][jj], al, bhp);
                }
            }
        }
        __syncthreads();
        if (it + 2 < NIT)
            g3_load(sbase + (it & 1) * STAGE3, tid, Ahi, Alo, Bhi, Blo, mBase, nBase, it + 2);
    }

    const int r0 = mBase + wm * 32 + (lane >> 2);
    const int c0 = nBase + wn * 64 + (lane & 3) * 2;
    #pragma unroll
    for (int i = 0; i < 2; i++) {
        #pragma unroll
        for (int jj = 0; jj < 8; jj++) {
            const int col = c0 + jj * 8;
            const float b0 = __ldg(&bias[col]), b1 = __ldg(&bias[col + 1]);
            const int row = r0 + i * 16;
            float u0 = acc[i][jj][0] * INVW + b0, u1 = acc[i][jj][1] * INVW + b1;
            float u2 = acc[i][jj][2] * INVW + b0, u3 = acc[i][jj][3] * INVW + b1;
            uint32_t h0 = packh2(u0, u1), h1 = packh2(u2, u3);
            float f0, f1, f2, f3;
            unpackh2(h0, f0, f1); unpackh2(h1, f2, f3);
            *(uint32_t*)&Chi[(size_t)row * Nglob + col]       = h0;
            *(uint32_t*)&Chi[(size_t)(row + 8) * Nglob + col] = h1;
            *(uint32_t*)&Clo[(size_t)row * Nglob + col]       = packh2(u0 - f0, u1 - f1);
            *(uint32_t*)&Clo[(size_t)(row + 8) * Nglob + col] = packh2(u2 - f2, u3 - f3);
        }
    }
}

// -------- gemm1: plain fp16 GEMM (A single, B single), fp32 out + bias -----
#define STAGE1 (2 * MAT_BYTES)           // 20480
#define GEMM1_SMEM (2 * STAGE1)          // 40960
#define OFF1_AF 0
#define OFF1_BF (1 * MAT_BYTES)

__device__ __forceinline__ void g1_load(
    uint32_t st, int tid,
    const __half* __restrict__ Af, const __half* __restrict__ Bf,
    int mBase, int nBase, int kt)
{
    const size_t k0 = (size_t)kt * BK;
    #pragma unroll
    for (int i = 0; i < 2; i++) {
        int e = tid + i * 256, r = e >> 2, c = e & 3;
        CP_ASYNC16(st + OFF1_AF + r * 80 + c * 16, Af + (size_t)(mBase + r) * KDIM + k0 + c * 8);
    }
    #pragma unroll
    for (int i = 0; i < 2; i++) {
        int e = tid + i * 256, r = e >> 2, c = e & 3;
        CP_ASYNC16(st + OFF1_BF + r * 80 + c * 16, Bf + (size_t)(nBase + r) * KDIM + k0 + c * 8);
    }
    CP_COMMIT();
}

__global__ __launch_bounds__(256, 2)
void gemm1(const __half* __restrict__ Af, const __half* __restrict__ Bf,
           const float* __restrict__ bias, float* __restrict__ Cf, int Nglob)
{
    extern __shared__ char smc[];
    const uint32_t sbase = smem_u32(smc);
    const int tid  = threadIdx.x;
    const int wid  = tid >> 5, lane = tid & 31;
    const int wm   = wid & 3, wn = wid >> 2;
    const int mBase = blockIdx.y * BM, nBase = blockIdx.x * BN;

    const uint32_t a_lane =
        (uint32_t)(((wm * 32 + (lane & 15)) * RS + ((lane >> 4) << 3)) * 2);
    const uint32_t b_lane =
        (uint32_t)(((wn * 64 + ((lane >> 4) << 3) + (lane & 7)) * RS + (((lane >> 3) & 1) << 3)) * 2);

    float acc[2][8][4];
    #pragma unroll
    for (int i = 0; i < 2; i++)
        #pragma unroll
        for (int j = 0; j < 8; j++)
            #pragma unroll
            for (int c = 0; c < 4; c++)
                acc[i][j][c] = 0.0f;

    g1_load(sbase, tid, Af, Bf, mBase, nBase, 0);
    g1_load(sbase + STAGE1, tid, Af, Bf, mBase, nBase, 1);

    for (int it = 0; it < NIT; it++) {
        if (it + 2 < NIT) { CP_WAIT1(); } else { CP_WAIT0(); }
        __syncthreads();
        const uint32_t st = sbase + (it & 1) * STAGE1;

        #pragma unroll
        for (int kk = 0; kk < 2; kk++) {
            const uint32_t koff = kk * 32;
            uint32_t bf[4][4];
            #pragma unroll
            for (int j = 0; j < 4; j++)
                ldsm_x4(bf[j], st + OFF1_BF + b_lane + j * (16 * RS * 2) + koff);
            #pragma unroll
            for (int i = 0; i < 2; i++) {
                uint32_t af[4];
                ldsm_x4(af, st + OFF1_AF + a_lane + i * (16 * RS * 2) + koff);
                #pragma unroll
                for (int jj = 0; jj < 8; jj++)
                    mma16816(acc[i][jj], af, &bf[jj >> 1][(jj & 1) * 2]);
            }
        }
        __syncthreads();
        if (it + 2 < NIT)
            g1_load(sbase + (it & 1) * STAGE1, tid, Af, Bf, mBase, nBase, it + 2);
    }

    const int r0 = mBase + wm * 32 + (lane >> 2);
    const int c0 = nBase + wn * 64 + (lane & 3) * 2;
    #pragma unroll
    for (int i = 0; i < 2; i++) {
        #pragma unroll
        for (int jj = 0; jj < 8; jj++) {
            const int col = c0 + jj * 8;
            const float b0 = __ldg(&bias[col]), b1 = __ldg(&bias[col + 1]);
            const int row = r0 + i * 16;
            *(float2*)&Cf[(size_t)row * Nglob + col] =
                make_float2(acc[i][jj][0] + b0, acc[i][jj][1] + b1);
            *(float2*)&Cf[(size_t)(row + 8) * Nglob + col] =
                make_float2(acc[i][jj][2] + b0, acc[i][jj][3] + b1);
        }
    }
}

// ============================ conversion kernels ============================
__global__ void split_kernel(const float* __restrict__ in,
                             __half* __restrict__ hi, __half* __restrict__ lo, int n)
{
    int idx = (blockIdx.x * blockDim.x + threadIdx.x) * 4;
    if (idx >= n) return;
    float4 v = *(const float4*)(in + idx);
    __half h0 = __float2half_rn(v.x), h1 = __float2half_rn(v.y);
    __half h2 = __float2half_rn(v.z), h3 = __float2half_rn(v.w);
    __half l0 = __float2half_rn(v.x - __half2float(h0));
    __half l1 = __float2half_rn(v.y - __half2float(h1));
    __half l2 = __float2half_rn(v.z - __half2float(h2));
    __half l3 = __float2half_rn(v.w - __half2float(h3));
    __half2* H = (__half2*)(hi + idx);
    __half2* L = (__half2*)(lo + idx);
    H[0] = {h0, h1}; H[1] = {h2, h3};
    L[0] = {l0, l1}; L[1] = {l2, l3};
}

// w[K, N] -> t[N, K], scaled by 64, split into fp16 hi/lo
__global__ void transpose_split(const float* __restrict__ w,
                                __half* __restrict__ thi, __half* __restrict__ tlo,
                                int K, int N)
{
    __shared__ float tile[32][33];
    const int kb = blockIdx.y * 32, nb = blockIdx.x * 32;
    const int tx = threadIdx.x, ty = threadIdx.y;
    #pragma unroll
    for (int j = 0; j < 4; j++) {
        int r = ty + 8 * j;
        tile[r][tx] = w[(size_t)(kb + r) * N + nb + tx];
    }
    __syncthreads();
    #pragma unroll
    for (int j = 0; j < 4; j++) {
        int r = ty + 8 * j;
        float v = tile[tx][r] * WSCALE;
        __half h = __float2half_rn(v);
        __half l = __float2half_rn(v - __half2float(h));
        size_t o = (size_t)(nb + r) * K + kb + tx;
        thi[o] = h; tlo[o] = l;
    }
}

// w[K, N] -> t[N, K], single fp16 (unscaled)
__global__ void transpose_half(const float* __restrict__ w,
                               __half* __restrict__ t, int K, int N)
{
    __shared__ float tile[32][33];
    const int kb = blockIdx.y * 32, nb = blockIdx.x * 32;
    const int tx = threadIdx.x, ty = threadIdx.y;
    #pragma unroll
    for (int j = 0; j < 4; j++) {
        int r = ty + 8 * j;
        tile[r][tx] = w[(size_t)(kb + r) * N + nb + tx];
    }
    __syncthreads();
    #pragma unroll
    for (int j = 0; j < 4; j++) {
        int r = ty + 8 * j;
        t[(size_t)(nb + r) * K + kb + tx] = __float2half_rn(tile[tx][r]);
    }
}

// ============================ flash attention ===============================
// QK: 2-product (QhKh + QlKh; K-lo dropped). PV: 1-product (P fp16, V-hi).
#define FRS 72
#define FQ_BYTES  (128 * FRS * 2)
#define FKV_BYTES (64 * FRS * 2)
#define FSTG_BYTES (2 * FKV_BYTES)       // Khi, Vhi
#define FQLO_OFF  FQ_BYTES
#define FSTG_OFF  (2 * FQ_BYTES)
#define FLASH_SMEM (FSTG_OFF + 2 * FSTG_BYTES)   // 73728
#define FNIT (SEQ / 64)

__device__ __forceinline__ void flash_load_kv(
    uint32_t st, int tid,
    const __half* __restrict__ QKVhi,
    int krow0, int kcol0, int vcol0)
{
    #pragma unroll
    for (int i = 0; i < 2; i++) {
        int e = tid + i * 256, r = e >> 3, c = e & 7;
        CP_ASYNC16(st + r * (FRS * 2) + c * 16, QKVhi + (size_t)(krow0 + r) * QKV_N + kcol0 + c * 8);
    }
    #pragma unroll
    for (int i = 0; i < 2; i++) {
        int e = tid + i * 256, r = e >> 3, c = e & 7;
        CP_ASYNC16(st + FKV_BYTES + r * (FRS * 2) + c * 16, QKVhi + (size_t)(krow0 + r) * QKV_N + vcol0 + c * 8);
    }
    CP_COMMIT();
}

__global__ __launch_bounds__(256, 1)
void flash_mma(const __half* __restrict__ QKVhi, const __half* __restrict__ QKVlo,
               __half* __restrict__ Of)
{
    extern __shared__ char smc[];
    const uint32_t sbase = smem_u32(smc);
    const int tid  = threadIdx.x;
    const int wid  = tid >> 5, lane = tid & 31;
    const int head = blockIdx.y, g = head >> 3;
    const int qrow0 = blockIdx.x * 128;
    const int qcol0 = head * DH;
    const int kcol0 = KOFF + g * DH;
    const int vcol0 = VOFF + g * DH;

    #pragma unroll
    for (int i = 0; i < 4; i++) {
        int e = tid + i * 256, r = e >> 3, c = e & 7;
        CP_ASYNC16(sbase + r * (FRS * 2) + c * 16, QKVhi + (size_t)(qrow0 + r) * QKV_N + qcol0 + c * 8);
    }
    #pragma unroll
    for (int i = 0; i < 4; i++) {
        int e = tid + i * 256, r = e >> 3, c = e & 7;
        CP_ASYNC16(sbase + FQLO_OFF + r * (FRS * 2) + c * 16, QKVlo + (size_t)(qrow0 + r) * QKV_N + qcol0 + c * 8);
    }
    flash_load_kv(sbase + FSTG_OFF, tid, QKVhi, 0, kcol0, vcol0);
    flash_load_kv(sbase + FSTG_OFF + FSTG_BYTES, tid, QKVhi, 64, kcol0, vcol0);

    const uint32_t a_lane =
        (uint32_t)(((wid * 16 + (lane & 15)) * FRS + ((lane >> 4) << 3)) * 2);
    const uint32_t b_lane =
        (uint32_t)(((((lane >> 4) << 3) + (lane & 7)) * FRS + (((lane >> 3) & 1) << 3)) * 2);
    const uint32_t v_lane =
        (uint32_t)(((((lane >> 3) & 1) * 8 + (lane & 7)) * FRS + ((lane >> 4) << 3)) * 2);

    float oacc[8][4];
    #pragma unroll
    for (int t = 0; t < 8; t++)
        #pragma unroll
        for (int c = 0; c < 4; c++) oacc[t][c] = 0.0f;
    float m0 = -INFINITY, m1 = -INFINITY, l0 = 0.0f, l1 = 0.0f;

    for (int it = 0; it < FNIT; it++) {
        if (it < FNIT - 1) { CP_WAIT1(); } else { CP_WAIT0(); }
        __syncthreads();
        const uint32_t st = sbase + FSTG_OFF + (it & 1) * FSTG_BYTES;

        float sacc[8][4];
        #pragma unroll
        for (int t = 0; t < 8; t++)
            #pragma unroll
            for (int c = 0; c < 4; c++) sacc[t][c] = 0.0f;

        // S = (Qhi + Qlo) * Khi : 2 products
        #pragma unroll
        for (int kk = 0; kk < 4; kk++) {
            const uint32_t koff = kk * 32;
            uint32_t ah[4], al[4];
            ldsm_x4(ah, sbase + a_lane + koff);
            ldsm_x4(al, sbase + FQLO_OFF + a_lane + koff);
            uint32_t bh[4][4];
            #pragma unroll
            for (int j = 0; j < 4; j++)
                ldsm_x4(bh[j], st + b_lane + j * (16 * FRS * 2) + koff);
            #pragma unroll
            for (int t = 0; t < 8; t++) {
                const uint32_t* bhp = &bh[t >> 1][(t & 1) * 2];
                mma16816(sacc[t], ah, bhp);
                mma16816(sacc[t], al, bhp);
            }
        }

        const float scale = 0.125f;
        float mx0 = -INFINITY, mx1 = -INFINITY;
        #pragma unroll
        for (int t = 0; t < 8; t++) {
            #pragma unroll
            for (int c = 0; c < 4; c++) sacc[t][c] *= scale;
            mx0 = fmaxf(mx0, fmaxf(sacc[t][0], sacc[t][1]));
            mx1 = fmaxf(mx1, fmaxf(sacc[t][2], sacc[t][3]));
        }
        mx0 = fmaxf(mx0, __shfl_xor_sync(0xffffffffu, mx0, 1));
        mx0 = fmaxf(mx0, __shfl_xor_sync(0xffffffffu, mx0, 2));
        mx1 = fmaxf(mx1, __shfl_xor_sync(0xffffffffu, mx1, 1));
        mx1 = fmaxf(mx1, __shfl_xor_sync(0xffffffffu, mx1, 2));
        const float mn0 = fmaxf(m0, mx0), mn1 = fmaxf(m1, mx1);
        const float corr0 = __expf(m0 - mn0), corr1 = __expf(m1 - mn1);
        m0 = mn0; m1 = mn1;

        float sum0 = 0.0f, sum1 = 0.0f;
        uint32_t pf[8][2];
        #pragma unroll
        for (int t = 0; t < 8; t++) {
            float p0 = __expf(sacc[t][0] - mn0), p1 = __expf(sacc[t][1] - mn0);
            float p2 = __expf(sacc[t][2] - mn1), p3 = __expf(sacc[t][3] - mn1);
            sum0 += p0 + p1; sum1 += p2 + p3;
            pf[t][0] = packh2(p0, p1);
            pf[t][1] = packh2(p2, p3);
        }
        sum0 += __shfl_xor_sync(0xffffffffu, sum0, 1);
        sum0 += __shfl_xor_sync(0xffffffffu, sum0, 2);
        sum1 += __shfl_xor_sync(0xffffffffu, sum1, 1);
        sum1 += __shfl_xor_sync(0xffffffffu, sum1, 2);
        l0 = l0 * corr0 + sum0;
        l1 = l1 * corr1 + sum1;
        #pragma unroll
        for (int t = 0; t < 8; t++) {
            oacc[t][0] *= corr0; oacc[t][1] *= corr0;
            oacc[t][2] *= corr1; oacc[t][3] *= corr1;
        }

        // O += P V : both single fp16 (1 product)
        #pragma unroll
        for (int j = 0; j < 4; j++) {
            uint32_t ap[4] = { pf[2 * j][0], pf[2 * j][1], pf[2 * j + 1][0], pf[2 * j + 1][1] };
            #pragma unroll
            for (int nb = 0; nb < 4; nb++) {
                uint32_t vaddr = st + FKV_BYTES + v_lane + j * (16 * FRS * 2) + nb * 32;
                uint32_t vh[4];
                ldsm_x4_t(vh, vaddr);
                mma16816(oacc[2 * nb],     ap, &vh[0]);
                mma16816(oacc[2 * nb + 1], ap, &vh[2]);
            }
        }

        __syncthreads();
        if (it + 2 < FNIT)
            flash_load_kv(st, tid, QKVhi, (it + 2) * 64, kcol0, vcol0);
    }

    const float inv0 = 1.0f / l0, inv1 = 1.0f / l1;
    const int row0 = qrow0 + wid * 16 + (lane >> 2);
    const int row1 = row0 + 8;
    #pragma unroll
    for (int t = 0; t < 8; t++) {
        const int col = qcol0 + t * 8 + (lane & 3) * 2;
        *(uint32_t*)&Of[(size_t)row0 * DMODEL + col] =
            packh2(oacc[t][0] * inv0, oacc[t][1] * inv0);
        *(uint32_t*)&Of[(size_t)row1 * DMODEL + col] =
            packh2(oacc[t][2] * inv1, oacc[t][3] * inv1);
    }
}

// ============================ kernel_launch =================================
extern "C" void kernel_launch(void* const* d_in, const int* in_sizes, int n_in,
                              void* d_out, int out_size)
{
    const float* x  = (const float*)d_in[0];
    const float* wq = (const float*)d_in[1];
    const float* bq = (const float*)d_in[2];
    const float* wk = (const float*)d_in[3];
    const float* bk = (const float*)d_in[4];
    const float* wv = (const float*)d_in[5];
    const float* bv = (const float*)d_in[6];
    const float* wo = (const float*)d_in[7];
    const float* bo = (const float*)d_in[8];
    float* out = (float*)d_out;

    __half *xhi, *xlo, *QKVhi, *QKVlo, *Of;
    __half *wqkvh, *wqkvl, *woT;
    float* bqkv;
    cudaGetSymbolAddress((void**)&xhi, g_xhi);
    cudaGetSymbolAddress((void**)&xlo, g_xlo);
    cudaGetSymbolAddress((void**)&QKVhi, g_QKVhi);
    cudaGetSymbolAddress((void**)&QKVlo, g_QKVlo);
    cudaGetSymbolAddress((void**)&Of, g_Of);
    cudaGetSymbolAddress((void**)&wqkvh, g_wqkvT_hi);
    cudaGetSymbolAddress((void**)&wqkvl, g_wqkvT_lo);
    cudaGetSymbolAddress((void**)&woT, g_woT);
    cudaGetSymbolAddress((void**)&bqkv, g_bqkv);

    cudaFuncSetAttribute(gemm3, cudaFuncAttributeMaxDynamicSharedMemorySize, GEMM3_SMEM);
    cudaFuncSetAttribute(gemm1, cudaFuncAttributeMaxDynamicSharedMemorySize, GEMM1_SMEM);
    cudaFuncSetAttribute(flash_mma, cudaFuncAttributeMaxDynamicSharedMemorySize, FLASH_SMEM);

    const int nX = SEQ * DMODEL;

    cudaMemcpyAsync(bqkv,        bq, DMODEL * sizeof(float), cudaMemcpyDeviceToDevice);
    cudaMemcpyAsync(bqkv + KOFF, bk, DGROUP * sizeof(float), cudaMemcpyDeviceToDevice);
    cudaMemcpyAsync(bqkv + VOFF, bv, DGROUP * sizeof(float), cudaMemcpyDeviceToDevice);

    split_kernel<<<nX / (256 * 4), 256>>>(x, xhi, xlo, nX);
    transpose_split<<<dim3(DMODEL / 32, KDIM / 32), dim3(32, 8)>>>(wq, wqkvh, wqkvl, KDIM, DMODEL);
    transpose_split<<<dim3(DGROUP / 32, KDIM / 32), dim3(32, 8)>>>(
        wk, wqkvh + (size_t)KOFF * KDIM, wqkvl + (size_t)KOFF * KDIM, KDIM, DGROUP);
    transpose_split<<<dim3(DGROUP / 32, KDIM / 32), dim3(32, 8)>>>(
        wv, wqkvh + (size_t)VOFF * KDIM, wqkvl + (size_t)VOFF * KDIM, KDIM, DGROUP);
    transpose_half<<<dim3(DMODEL / 32, KDIM / 32), dim3(32, 8)>>>(wo, woT, KDIM, DMODEL);

    // fused QKV projection (3-product): [2048,4096] @ [4096,5120]
    gemm3<<<dim3(QKV_N / BN, SEQ / BM), 256, GEMM3_SMEM>>>(
        xhi, xlo, wqkvh, wqkvl, bqkv, QKVhi, QKVlo, QKV_N);

    flash_mma<<<dim3(SEQ / 128, NHEADS), 256, FLASH_SMEM>>>(QKVhi, QKVlo, Of);

    // O projection (1-product): [2048,4096] @ [4096,4096] -> fp32 out
    gemm1<<<dim3(DMODEL / BN, SEQ / BM), 256, GEMM1_SMEM>>>(Of, woT, bo, out, DMODEL);
}

// round 14
// speedup vs baseline: 4.8794x; 1.0451x over previous
#include <cuda_runtime.h>
#include <cuda_fp16.h>
#include <math.h>
#include <stdint.h>

// ============================ problem constants =============================
#define SEQ      2048
#define DMODEL   4096
#define DGROUP   512
#define DH       64
#define NHEADS   64
#define KDIM     4096
#define QKV_N    (DMODEL + 2 * DGROUP)   // 5120
#define KOFF     DMODEL
#define VOFF     (DMODEL + DGROUP)
#define WSCALE   64.0f
#define INVW     0.015625f               // 1/64

// ============================ scratch (device globals) ======================
__device__ __half g_xhi[SEQ * DMODEL];
__device__ __half g_xlo[SEQ * DMODEL];
__device__ __half g_QKV[SEQ * QKV_N];          // single fp16 QKV
__device__ __half g_Of[SEQ * DMODEL];
__device__ __half g_wqkvT_hi[QKV_N * KDIM];
__device__ __half g_wqkvT_lo[QKV_N * KDIM];
__device__ __half g_woT[DMODEL * KDIM];        // single fp16, unscaled
__device__ float  g_bqkv[QKV_N];

// ============================ PTX helpers ===================================
__device__ __forceinline__ uint32_t smem_u32(const void* p) {
    uint32_t a;
    asm("{ .reg .u64 t; cvta.to.shared.u64 t, %1; cvt.u32.u64 %0, t; }" : "=r"(a) : "l"(p));
    return a;
}
#define CP_ASYNC16(dst, src) \
    asm volatile("cp.async.cg.shared.global [%0], [%1], 16;" :: "r"(dst), "l"(src) : "memory")
#define CP_COMMIT() asm volatile("cp.async.commit_group;" ::: "memory")
#define CP_WAIT0()  asm volatile("cp.async.wait_group 0;" ::: "memory")
#define CP_WAIT1()  asm volatile("cp.async.wait_group 1;" ::: "memory")

__device__ __forceinline__ void ldsm_x4(uint32_t* r, uint32_t addr) {
    asm volatile("ldmatrix.sync.aligned.m8n8.x4.shared.b16 {%0,%1,%2,%3}, [%4];"
                 : "=r"(r[0]), "=r"(r[1]), "=r"(r[2]), "=r"(r[3]) : "r"(addr));
}
__device__ __forceinline__ void ldsm_x4_t(uint32_t* r, uint32_t addr) {
    asm volatile("ldmatrix.sync.aligned.m8n8.x4.trans.shared.b16 {%0,%1,%2,%3}, [%4];"
                 : "=r"(r[0]), "=r"(r[1]), "=r"(r[2]), "=r"(r[3]) : "r"(addr));
}
__device__ __forceinline__ void mma16816(float* d, const uint32_t* a, const uint32_t* b) {
    asm volatile(
        "mma.sync.aligned.m16n8k16.row.col.f32.f16.f16.f32 "
        "{%0,%1,%2,%3}, {%4,%5,%6,%7}, {%8,%9}, {%0,%1,%2,%3};"
        : "+f"(d[0]), "+f"(d[1]), "+f"(d[2]), "+f"(d[3])
        : "r"(a[0]), "r"(a[1]), "r"(a[2]), "r"(a[3]), "r"(b[0]), "r"(b[1]));
}
__device__ __forceinline__ uint32_t packh2(float lo, float hi) {
    uint32_t r;
    asm("cvt.rn.f16x2.f32 %0, %1, %2;" : "=r"(r) : "f"(hi), "f"(lo));
    return r;
}

// ============================ GEMM common ===================================
#define BM 128
#define BN 128
#define BK 32
#define NIT (KDIM / BK)          // 128
#define RS 40
#define MAT_BYTES (128 * RS * 2) // 10240

// -------- gemm3: 3-product split (A hi/lo, B hi/lo), single fp16 out -------
#define STAGE3 (4 * MAT_BYTES)
#define GEMM3_SMEM (2 * STAGE3)          // 81920
#define OFF_AHI 0
#define OFF_ALO (1 * MAT_BYTES)
#define OFF_BHI (2 * MAT_BYTES)
#define OFF_BLO (3 * MAT_BYTES)

__device__ __forceinline__ void g3_load(
    uint32_t st, int tid,
    const __half* __restrict__ Ahi, const __half* __restrict__ Alo,
    const __half* __restrict__ Bhi, const __half* __restrict__ Blo,
    int mBase, int nBase, int kt)
{
    const size_t k0 = (size_t)kt * BK;
    #pragma unroll
    for (int i = 0; i < 2; i++) {
        int e = tid + i * 256, r = e >> 2, c = e & 3;
        CP_ASYNC16(st + OFF_AHI + r * 80 + c * 16, Ahi + (size_t)(mBase + r) * KDIM + k0 + c * 8);
    }
    #pragma unroll
    for (int i = 0; i < 2; i++) {
        int e = tid + i * 256, r = e >> 2, c = e & 3;
        CP_ASYNC16(st + OFF_ALO + r * 80 + c * 16, Alo + (size_t)(mBase + r) * KDIM + k0 + c * 8);
    }
    #pragma unroll
    for (int i = 0; i < 2; i++) {
        int e = tid + i * 256, r = e >> 2, c = e & 3;
        CP_ASYNC16(st + OFF_BHI + r * 80 + c * 16, Bhi + (size_t)(nBase + r) * KDIM + k0 + c * 8);
    }
    #pragma unroll
    for (int i = 0; i < 2; i++) {
        int e = tid + i * 256, r = e >> 2, c = e & 3;
        CP_ASYNC16(st + OFF_BLO + r * 80 + c * 16, Blo + (size_t)(nBase + r) * KDIM + k0 + c * 8);
    }
    CP_COMMIT();
}

__global__ __launch_bounds__(256, 2)
void gemm3(const __half* __restrict__ Ahi, const __half* __restrict__ Alo,
           const __half* __restrict__ Bhi, const __half* __restrict__ Blo,
           const float* __restrict__ bias,
           __half* __restrict__ C, int Nglob)
{
    extern __shared__ char smc[];
    const uint32_t sbase = smem_u32(smc);
    const int tid  = threadIdx.x;
    const int wid  = tid >> 5, lane = tid & 31;
    const int wm   = wid & 3, wn = wid >> 2;
    const int mBase = blockIdx.y * BM, nBase = blockIdx.x * BN;

    const uint32_t a_lane =
        (uint32_t)(((wm * 32 + (lane & 15)) * RS + ((lane >> 4) << 3)) * 2);
    const uint32_t b_lane =
        (uint32_t)(((wn * 64 + ((lane >> 4) << 3) + (lane & 7)) * RS + (((lane >> 3) & 1) << 3)) * 2);

    float acc[2][8][4];
    #pragma unroll
    for (int i = 0; i < 2; i++)
        #pragma unroll
        for (int j = 0; j < 8; j++)
            #pragma unroll
            for (int c = 0; c < 4; c++)
                acc[i][j][c] = 0.0f;

    g3_load(sbase, tid, Ahi, Alo, Bhi, Blo, mBase, nBase, 0);
    g3_load(sbase + STAGE3, tid, Ahi, Alo, Bhi, Blo, mBase, nBase, 1);

    for (int it = 0; it < NIT; it++) {
        if (it + 2 < NIT) { CP_WAIT1(); } else { CP_WAIT0(); }
        __syncthreads();
        const uint32_t st = sbase + (it & 1) * STAGE3;

        #pragma unroll
        for (int kk = 0; kk < 2; kk++) {
            const uint32_t koff = kk * 32;
            uint32_t bh[4][4], bl[4][4];
            #pragma unroll
            for (int j = 0; j < 4; j++) {
                ldsm_x4(bh[j], st + OFF_BHI + b_lane + j * (16 * RS * 2) + koff);
                ldsm_x4(bl[j], st + OFF_BLO + b_lane + j * (16 * RS * 2) + koff);
            }
            #pragma unroll
            for (int i = 0; i < 2; i++) {
                uint32_t ah[4], al[4];
                ldsm_x4(ah, st + OFF_AHI + a_lane + i * (16 * RS * 2) + koff);
                ldsm_x4(al, st + OFF_ALO + a_lane + i * (16 * RS * 2) + koff);
                #pragma unroll
                for (int jj = 0; jj < 8; jj++) {
                    const uint32_t* bhp = &bh[jj >> 1][(jj & 1) * 2];
                    const uint32_t* blp = &bl[jj >> 1][(jj & 1) * 2];
                    mma16816(acc[i][jj], ah, bhp);
                    mma16816(acc[i][jj], ah, blp);
                    mma16816(acc[i][jj], al, bhp);
                }
            }
        }
        __syncthreads();
        if (it + 2 < NIT)
            g3_load(sbase + (it & 1) * STAGE3, tid, Ahi, Alo, Bhi, Blo, mBase, nBase, it + 2);
    }

    const int r0 = mBase + wm * 32 + (lane >> 2);
    const int c0 = nBase + wn * 64 + (lane & 3) * 2;
    #pragma unroll
    for (int i = 0; i < 2; i++) {
        #pragma unroll
        for (int jj = 0; jj < 8; jj++) {
            const int col = c0 + jj * 8;
            const float b0 = __ldg(&bias[col]), b1 = __ldg(&bias[col + 1]);
            const int row = r0 + i * 16;
            float u0 = acc[i][jj][0] * INVW + b0, u1 = acc[i][jj][1] * INVW + b1;
            float u2 = acc[i][jj][2] * INVW + b0, u3 = acc[i][jj][3] * INVW + b1;
            *(uint32_t*)&C[(size_t)row * Nglob + col]       = packh2(u0, u1);
            *(uint32_t*)&C[(size_t)(row + 8) * Nglob + col] = packh2(u2, u3);
        }
    }
}

// -------- gemm1: plain fp16 GEMM (A single, B single), fp32 out + bias -----
#define STAGE1 (2 * MAT_BYTES)           // 20480
#define GEMM1_SMEM (2 * STAGE1)          // 40960
#define OFF1_AF 0
#define OFF1_BF (1 * MAT_BYTES)

__device__ __forceinline__ void g1_load(
    uint32_t st, int tid,
    const __half* __restrict__ Af, const __half* __restrict__ Bf,
    int mBase, int nBase, int kt)
{
    const size_t k0 = (size_t)kt * BK;
    #pragma unroll
    for (int i = 0; i < 2; i++) {
        int e = tid + i * 256, r = e >> 2, c = e & 3;
        CP_ASYNC16(st + OFF1_AF + r * 80 + c * 16, Af + (size_t)(mBase + r) * KDIM + k0 + c * 8);
    }
    #pragma unroll
    for (int i = 0; i < 2; i++) {
        int e = tid + i * 256, r = e >> 2, c = e & 3;
        CP_ASYNC16(st + OFF1_BF + r * 80 + c * 16, Bf + (size_t)(nBase + r) * KDIM + k0 + c * 8);
    }
    CP_COMMIT();
}

__global__ __launch_bounds__(256, 2)
void gemm1(const __half* __restrict__ Af, const __half* __restrict__ Bf,
           const float* __restrict__ bias, float* __restrict__ Cf, int Nglob)
{
    extern __shared__ char smc[];
    const uint32_t sbase = smem_u32(smc);
    const int tid  = threadIdx.x;
    const int wid  = tid >> 5, lane = tid & 31;
    const int wm   = wid & 3, wn = wid >> 2;
    const int mBase = blockIdx.y * BM, nBase = blockIdx.x * BN;

    const uint32_t a_lane =
        (uint32_t)(((wm * 32 + (lane & 15)) * RS + ((lane >> 4) << 3)) * 2);
    const uint32_t b_lane =
        (uint32_t)(((wn * 64 + ((lane >> 4) << 3) + (lane & 7)) * RS + (((lane >> 3) & 1) << 3)) * 2);

    float acc[2][8][4];
    #pragma unroll
    for (int i = 0; i < 2; i++)
        #pragma unroll
        for (int j = 0; j < 8; j++)
            #pragma unroll
            for (int c = 0; c < 4; c++)
                acc[i][j][c] = 0.0f;

    g1_load(sbase, tid, Af, Bf, mBase, nBase, 0);
    g1_load(sbase + STAGE1, tid, Af, Bf, mBase, nBase, 1);

    for (int it = 0; it < NIT; it++) {
        if (it + 2 < NIT) { CP_WAIT1(); } else { CP_WAIT0(); }
        __syncthreads();
        const uint32_t st = sbase + (it & 1) * STAGE1;

        #pragma unroll
        for (int kk = 0; kk < 2; kk++) {
            const uint32_t koff = kk * 32;
            uint32_t bf[4][4];
            #pragma unroll
            for (int j = 0; j < 4; j++)
                ldsm_x4(bf[j], st + OFF1_BF + b_lane + j * (16 * RS * 2) + koff);
            #pragma unroll
            for (int i = 0; i < 2; i++) {
                uint32_t af[4];
                ldsm_x4(af, st + OFF1_AF + a_lane + i * (16 * RS * 2) + koff);
                #pragma unroll
                for (int jj = 0; jj < 8; jj++)
                    mma16816(acc[i][jj], af, &bf[jj >> 1][(jj & 1) * 2]);
            }
        }
        __syncthreads();
        if (it + 2 < NIT)
            g1_load(sbase + (it & 1) * STAGE1, tid, Af, Bf, mBase, nBase, it + 2);
    }

    const int r0 = mBase + wm * 32 + (lane >> 2);
    const int c0 = nBase + wn * 64 + (lane & 3) * 2;
    #pragma unroll
    for (int i = 0; i < 2; i++) {
        #pragma unroll
        for (int jj = 0; jj < 8; jj++) {
            const int col = c0 + jj * 8;
            const float b0 = __ldg(&bias[col]), b1 = __ldg(&bias[col + 1]);
            const int row = r0 + i * 16;
            *(float2*)&Cf[(size_t)row * Nglob + col] =
                make_float2(acc[i][jj][0] + b0, acc[i][jj][1] + b1);
            *(float2*)&Cf[(size_t)(row + 8) * Nglob + col] =
                make_float2(acc[i][jj][2] + b0, acc[i][jj][3] + b1);
        }
    }
}

// ============================ conversion kernels ============================
__global__ void split_kernel(const float* __restrict__ in,
                             __half* __restrict__ hi, __half* __restrict__ lo, int n)
{
    int idx = (blockIdx.x * blockDim.x + threadIdx.x) * 4;
    if (idx >= n) return;
    float4 v = *(const float4*)(in + idx);
    __half h0 = __float2half_rn(v.x), h1 = __float2half_rn(v.y);
    __half h2 = __float2half_rn(v.z), h3 = __float2half_rn(v.w);
    __half l0 = __float2half_rn(v.x - __half2float(h0));
    __half l1 = __float2half_rn(v.y - __half2float(h1));
    __half l2 = __float2half_rn(v.z - __half2float(h2));
    __half l3 = __float2half_rn(v.w - __half2float(h3));
    __half2* H = (__half2*)(hi + idx);
    __half2* L = (__half2*)(lo + idx);
    H[0] = {h0, h1}; H[1] = {h2, h3};
    L[0] = {l0, l1}; L[1] = {l2, l3};
}

// w[K, N] -> t[N, K], scaled by 64, split into fp16 hi/lo
__global__ void transpose_split(const float* __restrict__ w,
                                __half* __restrict__ thi, __half* __restrict__ tlo,
                                int K, int N)
{
    __shared__ float tile[32][33];
    const int kb = blockIdx.y * 32, nb = blockIdx.x * 32;
    const int tx = threadIdx.x, ty = threadIdx.y;
    #pragma unroll
    for (int j = 0; j < 4; j++) {
        int r = ty + 8 * j;
        tile[r][tx] = w[(size_t)(kb + r) * N + nb + tx];
    }
    __syncthreads();
    #pragma unroll
    for (int j = 0; j < 4; j++) {
        int r = ty + 8 * j;
        float v = tile[tx][r] * WSCALE;
        __half h = __float2half_rn(v);
        __half l = __float2half_rn(v - __half2float(h));
        size_t o = (size_t)(nb + r) * K + kb + tx;
        thi[o] = h; tlo[o] = l;
    }
}

// w[K, N] -> t[N, K], single fp16 (unscaled)
__global__ void transpose_half(const float* __restrict__ w,
                               __half* __restrict__ t, int K, int N)
{
    __shared__ float tile[32][33];
    const int kb = blockIdx.y * 32, nb = blockIdx.x * 32;
    const int tx = threadIdx.x, ty = threadIdx.y;
    #pragma unroll
    for (int j = 0; j < 4; j++) {
        int r = ty + 8 * j;
        tile[r][tx] = w[(size_t)(kb + r) * N + nb + tx];
    }
    __syncthreads();
    #pragma unroll
    for (int j = 0; j < 4; j++) {
        int r = ty + 8 * j;
        t[(size_t)(nb + r) * K + kb + tx] = __float2half_rn(tile[tx][r]);
    }
}

// ============================ flash attention ===============================
// Pure fp16: QK 1-product (Q×K-hi), PV 1-product (P×V-hi).
#define FRS 72
#define FQ_BYTES  (128 * FRS * 2)        // 18432
#define FKV_BYTES (64 * FRS * 2)         // 9216
#define FSTG_BYTES (2 * FKV_BYTES)       // K, V
#define FSTG_OFF  FQ_BYTES
#define FLASH_SMEM (FSTG_OFF + 2 * FSTG_BYTES)   // 55296
#define FNIT (SEQ / 64)

__device__ __forceinline__ void flash_load_kv(
    uint32_t st, int tid,
    const __half* __restrict__ QKV,
    int krow0, int kcol0, int vcol0)
{
    #pragma unroll
    for (int i = 0; i < 2; i++) {
        int e = tid + i * 256, r = e >> 3, c = e & 7;
        CP_ASYNC16(st + r * (FRS * 2) + c * 16, QKV + (size_t)(krow0 + r) * QKV_N + kcol0 + c * 8);
    }
    #pragma unroll
    for (int i = 0; i < 2; i++) {
        int e = tid + i * 256, r = e >> 3, c = e & 7;
        CP_ASYNC16(st + FKV_BYTES + r * (FRS * 2) + c * 16, QKV + (size_t)(krow0 + r) * QKV_N + vcol0 + c * 8);
    }
    CP_COMMIT();
}

__global__ __launch_bounds__(256, 1)
void flash_mma(const __half* __restrict__ QKV, __half* __restrict__ Of)
{
    extern __shared__ char smc[];
    const uint32_t sbase = smem_u32(smc);
    const int tid  = threadIdx.x;
    const int wid  = tid >> 5, lane = tid & 31;
    const int head = blockIdx.y, g = head >> 3;
    const int qrow0 = blockIdx.x * 128;
    const int qcol0 = head * DH;
    const int kcol0 = KOFF + g * DH;
    const int vcol0 = VOFF + g * DH;

    #pragma unroll
    for (int i = 0; i < 4; i++) {
        int e = tid + i * 256, r = e >> 3, c = e & 7;
        CP_ASYNC16(sbase + r * (FRS * 2) + c * 16, QKV + (size_t)(qrow0 + r) * QKV_N + qcol0 + c * 8);
    }
    flash_load_kv(sbase + FSTG_OFF, tid, QKV, 0, kcol0, vcol0);
    flash_load_kv(sbase + FSTG_OFF + FSTG_BYTES, tid, QKV, 64, kcol0, vcol0);

    const uint32_t a_lane =
        (uint32_t)(((wid * 16 + (lane & 15)) * FRS + ((lane >> 4) << 3)) * 2);
    const uint32_t b_lane =
        (uint32_t)(((((lane >> 4) << 3) + (lane & 7)) * FRS + (((lane >> 3) & 1) << 3)) * 2);
    const uint32_t v_lane =
        (uint32_t)(((((lane >> 3) & 1) * 8 + (lane & 7)) * FRS + ((lane >> 4) << 3)) * 2);

    float oacc[8][4];
    #pragma unroll
    for (int t = 0; t < 8; t++)
        #pragma unroll
        for (int c = 0; c < 4; c++) oacc[t][c] = 0.0f;
    float m0 = -INFINITY, m1 = -INFINITY, l0 = 0.0f, l1 = 0.0f;

    for (int it = 0; it < FNIT; it++) {
        if (it < FNIT - 1) { CP_WAIT1(); } else { CP_WAIT0(); }
        __syncthreads();
        const uint32_t st = sbase + FSTG_OFF + (it & 1) * FSTG_BYTES;

        float sacc[8][4];
        #pragma unroll
        for (int t = 0; t < 8; t++)
            #pragma unroll
            for (int c = 0; c < 4; c++) sacc[t][c] = 0.0f;

        // S = Q * K : 1 product
        #pragma unroll
        for (int kk = 0; kk < 4; kk++) {
            const uint32_t koff = kk * 32;
            uint32_t ah[4];
            ldsm_x4(ah, sbase + a_lane + koff);
            uint32_t bh[4][4];
            #pragma unroll
            for (int j = 0; j < 4; j++)
                ldsm_x4(bh[j], st + b_lane + j * (16 * FRS * 2) + koff);
            #pragma unroll
            for (int t = 0; t < 8; t++)
                mma16816(sacc[t], ah, &bh[t >> 1][(t & 1) * 2]);
        }

        const float scale = 0.125f;
        float mx0 = -INFINITY, mx1 = -INFINITY;
        #pragma unroll
        for (int t = 0; t < 8; t++) {
            #pragma unroll
            for (int c = 0; c < 4; c++) sacc[t][c] *= scale;
            mx0 = fmaxf(mx0, fmaxf(sacc[t][0], sacc[t][1]));
            mx1 = fmaxf(mx1, fmaxf(sacc[t][2], sacc[t][3]));
        }
        mx0 = fmaxf(mx0, __shfl_xor_sync(0xffffffffu, mx0, 1));
        mx0 = fmaxf(mx0, __shfl_xor_sync(0xffffffffu, mx0, 2));
        mx1 = fmaxf(mx1, __shfl_xor_sync(0xffffffffu, mx1, 1));
        mx1 = fmaxf(mx1, __shfl_xor_sync(0xffffffffu, mx1, 2));
        const float mn0 = fmaxf(m0, mx0), mn1 = fmaxf(m1, mx1);
        const float corr0 = __expf(m0 - mn0), corr1 = __expf(m1 - mn1);
        m0 = mn0; m1 = mn1;

        float sum0 = 0.0f, sum1 = 0.0f;
        uint32_t pf[8][2];
        #pragma unroll
        for (int t = 0; t < 8; t++) {
            float p0 = __expf(sacc[t][0] - mn0), p1 = __expf(sacc[t][1] - mn0);
            float p2 = __expf(sacc[t][2] - mn1), p3 = __expf(sacc[t][3] - mn1);
            sum0 += p0 + p1; sum1 += p2 + p3;
            pf[t][0] = packh2(p0, p1);
            pf[t][1] = packh2(p2, p3);
        }
        sum0 += __shfl_xor_sync(0xffffffffu, sum0, 1);
        sum0 += __shfl_xor_sync(0xffffffffu, sum0, 2);
        sum1 += __shfl_xor_sync(0xffffffffu, sum1, 1);
        sum1 += __shfl_xor_sync(0xffffffffu, sum1, 2);
        l0 = l0 * corr0 + sum0;
        l1 = l1 * corr1 + sum1;
        #pragma unroll
        for (int t = 0; t < 8; t++) {
            oacc[t][0] *= corr0; oacc[t][1] *= corr0;
            oacc[t][2] *= corr1; oacc[t][3] *= corr1;
        }

        // O += P V : 1 product
        #pragma unroll
        for (int j = 0; j < 4; j++) {
            uint32_t ap[4] = { pf[2 * j][0], pf[2 * j][1], pf[2 * j + 1][0], pf[2 * j + 1][1] };
            #pragma unroll
            for (int nb = 0; nb < 4; nb++) {
                uint32_t vaddr = st + FKV_BYTES + v_lane + j * (16 * FRS * 2) + nb * 32;
                uint32_t vh[4];
                ldsm_x4_t(vh, vaddr);
                mma16816(oacc[2 * nb],     ap, &vh[0]);
                mma16816(oacc[2 * nb + 1], ap, &vh[2]);
            }
        }

        __syncthreads();
        if (it + 2 < FNIT)
            flash_load_kv(st, tid, QKV, (it + 2) * 64, kcol0, vcol0);
    }

    const float inv0 = 1.0f / l0, inv1 = 1.0f / l1;
    const int row0 = qrow0 + wid * 16 + (lane >> 2);
    const int row1 = row0 + 8;
    #pragma unroll
    for (int t = 0; t < 8; t++) {
        const int col = qcol0 + t * 8 + (lane & 3) * 2;
        *(uint32_t*)&Of[(size_t)row0 * DMODEL + col] =
            packh2(oacc[t][0] * inv0, oacc[t][1] * inv0);
        *(uint32_t*)&Of[(size_t)row1 * DMODEL + col] =
            packh2(oacc[t][2] * inv1, oacc[t][3] * inv1);
    }
}

// ============================ kernel_launch =================================
extern "C" void kernel_launch(void* const* d_in, const int* in_sizes, int n_in,
                              void* d_out, int out_size)
{
    const float* x  = (const float*)d_in[0];
    const float* wq = (const float*)d_in[1];
    const float* bq = (const float*)d_in[2];
    const float* wk = (const float*)d_in[3];
    const float* bk = (const float*)d_in[4];
    const float* wv = (const float*)d_in[5];
    const float* bv = (const float*)d_in[6];
    const float* wo = (const float*)d_in[7];
    const float* bo = (const float*)d_in[8];
    float* out = (float*)d_out;

    __half *xhi, *xlo, *QKV, *Of;
    __half *wqkvh, *wqkvl, *woT;
    float* bqkv;
    cudaGetSymbolAddress((void**)&xhi, g_xhi);
    cudaGetSymbolAddress((void**)&xlo, g_xlo);
    cudaGetSymbolAddress((void**)&QKV, g_QKV);
    cudaGetSymbolAddress((void**)&Of, g_Of);
    cudaGetSymbolAddress((void**)&wqkvh, g_wqkvT_hi);
    cudaGetSymbolAddress((void**)&wqkvl, g_wqkvT_lo);
    cudaGetSymbolAddress((void**)&woT, g_woT);
    cudaGetSymbolAddress((void**)&bqkv, g_bqkv);

    cudaFuncSetAttribute(gemm3, cudaFuncAttributeMaxDynamicSharedMemorySize, GEMM3_SMEM);
    cudaFuncSetAttribute(gemm1, cudaFuncAttributeMaxDynamicSharedMemorySize, GEMM1_SMEM);
    cudaFuncSetAttribute(flash_mma, cudaFuncAttributeMaxDynamicSharedMemorySize, FLASH_SMEM);

    const int nX = SEQ * DMODEL;

    cudaMemcpyAsync(bqkv,        bq, DMODEL * sizeof(float), cudaMemcpyDeviceToDevice);
    cudaMemcpyAsync(bqkv + KOFF, bk, DGROUP * sizeof(float), cudaMemcpyDeviceToDevice);
    cudaMemcpyAsync(bqkv + VOFF, bv, DGROUP * sizeof(float), cudaMemcpyDeviceToDevice);

    split_kernel<<<nX / (256 * 4), 256>>>(x, xhi, xlo, nX);
    transpose_split<<<dim3(DMODEL / 32, KDIM / 32), dim3(32, 8)>>>(wq, wqkvh, wqkvl, KDIM, DMODEL);
    transpose_split<<<dim3(DGROUP / 32, KDIM / 32), dim3(32, 8)>>>(
        wk, wqkvh + (size_t)KOFF * KDIM, wqkvl + (size_t)KOFF * KDIM, KDIM, DGROUP);
    transpose_split<<<dim3(DGROUP / 32, KDIM / 32), dim3(32, 8)>>>(
        wv, wqkvh + (size_t)VOFF * KDIM, wqkvl + (size_t)VOFF * KDIM, KDIM, DGROUP);
    transpose_half<<<dim3(DMODEL / 32, KDIM / 32), dim3(32, 8)>>>(wo, woT, KDIM, DMODEL);

    // fused QKV projection (3-product, single fp16 out): [2048,4096] @ [4096,5120]
    gemm3<<<dim3(QKV_N / BN, SEQ / BM), 256, GEMM3_SMEM>>>(
        xhi, xlo, wqkvh, wqkvl, bqkv, QKV, QKV_N);

    flash_mma<<<dim3(SEQ / 128, NHEADS), 256, FLASH_SMEM>>>(QKV, Of);

    // O projection (1-product): [2048,4096] @ [4096,4096] -> fp32 out
    gemm1<<<dim3(DMODEL / BN, SEQ / BM), 256, GEMM1_SMEM>>>(Of, woT, bo, out, DMODEL);
}